// round 1
// baseline (speedup 1.0000x reference)
#include <cuda_runtime.h>

#define NB   2
#define SEQ  2048
#define DM   1024
#define NH   16
#define HD   64
#define ROWS (NB*SEQ)          // 4096
#define SCALE 0.125f           // 1/sqrt(64)

// Scratch (allocation-free: __device__ globals)
__device__ float g_Q[(size_t)NH*NB*SEQ*HD];
__device__ float g_K[(size_t)NH*NB*SEQ*HD];
__device__ float g_V[(size_t)NH*NB*SEQ*HD];
__device__ float g_Y[(size_t)ROWS*DM];

// ---------------------------------------------------------------------------
// NT GEMM with bias: C[r,c] = sum_m A[r,m]*B[c,m] + bias[c]
// MODE 0: C row-major [ROWS, DM]
// MODE 1: QKV layout: c=h*64+d, r=n*2048+k -> C[((h*NB+n)*SEQ+k)*HD + d]
// 64x64 tile, BK=16, 256 threads, 4x4 microtile.
// ---------------------------------------------------------------------------
template<int MODE>
__global__ void __launch_bounds__(256) gemm_nt_kernel(
    const float* __restrict__ A, const float* __restrict__ B,
    const float* __restrict__ bias, float* __restrict__ C, int Kdim)
{
    __shared__ float As[16][64];   // [k][row] (transposed at load)
    __shared__ float Bs[16][64];   // [k][col]

    const int tid = threadIdx.x;
    const int tx = tid & 15, ty = tid >> 4;
    const int row0 = blockIdx.y << 6;
    const int col0 = blockIdx.x << 6;

    const int lr = tid >> 2;            // 0..63
    const int lk = (tid & 3) << 2;      // 0,4,8,12
    const float* Aptr = A + (size_t)(row0 + lr) * Kdim + lk;
    const float* Bptr = B + (size_t)(col0 + lr) * Kdim + lk;

    float acc[4][4] = {};

    for (int k0 = 0; k0 < Kdim; k0 += 16) {
        float4 av = *(const float4*)(Aptr + k0);
        float4 bv = *(const float4*)(Bptr + k0);
        __syncthreads();
        As[lk+0][lr] = av.x; As[lk+1][lr] = av.y; As[lk+2][lr] = av.z; As[lk+3][lr] = av.w;
        Bs[lk+0][lr] = bv.x; Bs[lk+1][lr] = bv.y; Bs[lk+2][lr] = bv.z; Bs[lk+3][lr] = bv.w;
        __syncthreads();
        #pragma unroll
        for (int kk = 0; kk < 16; kk++) {
            float4 a = *(const float4*)&As[kk][ty << 2];
            float4 b = *(const float4*)&Bs[kk][tx << 2];
            acc[0][0] += a.x*b.x; acc[0][1] += a.x*b.y; acc[0][2] += a.x*b.z; acc[0][3] += a.x*b.w;
            acc[1][0] += a.y*b.x; acc[1][1] += a.y*b.y; acc[1][2] += a.y*b.z; acc[1][3] += a.y*b.w;
            acc[2][0] += a.z*b.x; acc[2][1] += a.z*b.y; acc[2][2] += a.z*b.z; acc[2][3] += a.z*b.w;
            acc[3][0] += a.w*b.x; acc[3][1] += a.w*b.y; acc[3][2] += a.w*b.z; acc[3][3] += a.w*b.w;
        }
    }

    #pragma unroll
    for (int i = 0; i < 4; i++) {
        const int r = row0 + (ty << 2) + i;
        #pragma unroll
        for (int j = 0; j < 4; j++) {
            const int c = col0 + (tx << 2) + j;
            const float v = acc[i][j] + bias[c];
            if (MODE == 0) {
                C[(size_t)r * DM + c] = v;
            } else {
                const int h = c >> 6, d = c & 63;
                const int n = r >> 11, kq = r & 2047;
                C[(((size_t)(h*NB + n)) * SEQ + kq) * HD + d] = v;
            }
        }
    }
}

// ---------------------------------------------------------------------------
// Flash-style attention: per (h,n) pair, 64-row Q tile resident, stream
// 64-row K/V tiles with online softmax. Writes Y in [N, K, H*D] layout.
// 256 threads; 4x4 microtile for both S=QK^T and O+=P*V.
// Dynamic smem: Qs[64][68] + Ks[64][68] + Ps[64][68] + Vs[64][64] = 68608 B
// ---------------------------------------------------------------------------
__global__ void __launch_bounds__(256) attn_kernel(
    const float* __restrict__ Q, const float* __restrict__ K,
    const float* __restrict__ V, float* __restrict__ Y)
{
    extern __shared__ float sm[];
    float (*Qs)[68] = (float(*)[68])(sm);                 // [d][q]
    float (*Ks)[68] = (float(*)[68])(sm + 64*68);         // [d][kv]
    float (*Ps)[68] = (float(*)[68])(sm + 2*64*68);       // [kv][q]
    float (*Vs)[64] = (float(*)[64])(sm + 3*64*68);       // [kv][d]

    const int tid = threadIdx.x;
    const int tx = tid & 15, ty = tid >> 4;
    const int hn = blockIdx.y;            // h*NB + n
    const int h = hn >> 1, n = hn & 1;
    const int q0 = blockIdx.x << 6;

    const float* Qb = Q + (size_t)hn * SEQ * HD;
    const float* Kb = K + (size_t)hn * SEQ * HD;
    const float* Vb = V + (size_t)hn * SEQ * HD;

    // tile-load pattern: each thread 4 float4s; row = tid>>2, col4 = (tid&3)+4*c
    const int lrow = tid >> 2;            // 0..63
    const int lc4  = tid & 3;             // 0..3

    // Load Q tile (transposed into Qs[d][q])
    #pragma unroll
    for (int c = 0; c < 4; c++) {
        const int col = ((lc4 + (c << 2)) << 2);          // 0..60
        float4 qv = *(const float4*)&Qb[(size_t)(q0 + lrow) * HD + col];
        Qs[col+0][lrow] = qv.x; Qs[col+1][lrow] = qv.y;
        Qs[col+2][lrow] = qv.z; Qs[col+3][lrow] = qv.w;
    }

    float m_i[4], l_i[4], o[4][4];
    #pragma unroll
    for (int i = 0; i < 4; i++) {
        m_i[i] = -1e30f; l_i[i] = 0.f;
        #pragma unroll
        for (int j = 0; j < 4; j++) o[i][j] = 0.f;
    }

    for (int t = 0; t < SEQ/64; t++) {
        const int k0 = t << 6;
        float4 kreg[4], vreg[4];
        #pragma unroll
        for (int c = 0; c < 4; c++) {
            const int col = ((lc4 + (c << 2)) << 2);
            kreg[c] = *(const float4*)&Kb[(size_t)(k0 + lrow) * HD + col];
            vreg[c] = *(const float4*)&Vb[(size_t)(k0 + lrow) * HD + col];
        }
        __syncthreads();   // previous iteration's PV reads complete
        #pragma unroll
        for (int c = 0; c < 4; c++) {
            const int col = ((lc4 + (c << 2)) << 2);
            Ks[col+0][lrow] = kreg[c].x; Ks[col+1][lrow] = kreg[c].y;
            Ks[col+2][lrow] = kreg[c].z; Ks[col+3][lrow] = kreg[c].w;
            *(float4*)&Vs[lrow][col] = vreg[c];
        }
        __syncthreads();   // K/V tiles ready

        // S = Q K^T  (raw scores; scale folded into the exponent)
        float s[4][4] = {};
        #pragma unroll 8
        for (int d = 0; d < HD; d++) {
            float4 a = *(const float4*)&Qs[d][ty << 2];
            float4 b = *(const float4*)&Ks[d][tx << 2];
            s[0][0] += a.x*b.x; s[0][1] += a.x*b.y; s[0][2] += a.x*b.z; s[0][3] += a.x*b.w;
            s[1][0] += a.y*b.x; s[1][1] += a.y*b.y; s[1][2] += a.y*b.z; s[1][3] += a.y*b.w;
            s[2][0] += a.z*b.x; s[2][1] += a.z*b.y; s[2][2] += a.z*b.z; s[2][3] += a.z*b.w;
            s[3][0] += a.w*b.x; s[3][1] += a.w*b.y; s[3][2] += a.w*b.z; s[3][3] += a.w*b.w;
        }

        // online softmax per q-row (row owned by the 16 threads sharing ty)
        #pragma unroll
        for (int i = 0; i < 4; i++) {
            float rmax = fmaxf(fmaxf(s[i][0], s[i][1]), fmaxf(s[i][2], s[i][3]));
            #pragma unroll
            for (int off = 8; off > 0; off >>= 1)
                rmax = fmaxf(rmax, __shfl_xor_sync(0xffffffffu, rmax, off));
            const float mnew = fmaxf(m_i[i], rmax);
            const float corr = __expf((m_i[i] - mnew) * SCALE);
            float rsum = 0.f;
            #pragma unroll
            for (int j = 0; j < 4; j++) {
                const float p = __expf((s[i][j] - mnew) * SCALE);
                Ps[(tx << 2) + j][(ty << 2) + i] = p;
                rsum += p;
            }
            #pragma unroll
            for (int off = 8; off > 0; off >>= 1)
                rsum += __shfl_xor_sync(0xffffffffu, rsum, off);
            l_i[i] = l_i[i] * corr + rsum;
            m_i[i] = mnew;
            #pragma unroll
            for (int j = 0; j < 4; j++) o[i][j] *= corr;
        }
        __syncthreads();   // P tile ready

        // O += P V
        #pragma unroll 8
        for (int kc = 0; kc < 64; kc++) {
            float4 a = *(const float4*)&Ps[kc][ty << 2];
            float4 b = *(const float4*)&Vs[kc][tx << 2];
            o[0][0] += a.x*b.x; o[0][1] += a.x*b.y; o[0][2] += a.x*b.z; o[0][3] += a.x*b.w;
            o[1][0] += a.y*b.x; o[1][1] += a.y*b.y; o[1][2] += a.y*b.z; o[1][3] += a.y*b.w;
            o[2][0] += a.z*b.x; o[2][1] += a.z*b.y; o[2][2] += a.z*b.z; o[2][3] += a.z*b.w;
            o[3][0] += a.w*b.x; o[3][1] += a.w*b.y; o[3][2] += a.w*b.z; o[3][3] += a.w*b.w;
        }
    }

    // write Y in concat-head layout [N, K, H*D]
    #pragma unroll
    for (int i = 0; i < 4; i++) {
        const float inv = 1.f / l_i[i];
        const int r = q0 + (ty << 2) + i;
        #pragma unroll
        for (int j = 0; j < 4; j++) {
            Y[((size_t)(n*SEQ + r)) * DM + h*HD + (tx << 2) + j] = o[i][j] * inv;
        }
    }
}

// ---------------------------------------------------------------------------
extern "C" void kernel_launch(void* const* d_in, const int* in_sizes, int n_in,
                              void* d_out, int out_size)
{
    const float* q  = (const float*)d_in[0];
    const float* k  = (const float*)d_in[1];
    const float* v  = (const float*)d_in[2];
    const float* Wq = (const float*)d_in[3];
    const float* bq = (const float*)d_in[4];
    const float* Wk = (const float*)d_in[5];
    const float* bk = (const float*)d_in[6];
    const float* Wv = (const float*)d_in[7];
    const float* bv = (const float*)d_in[8];
    const float* Wo = (const float*)d_in[9];
    const float* bo = (const float*)d_in[10];
    float* out = (float*)d_out;

    float *gQ, *gK, *gV, *gY;
    cudaGetSymbolAddress((void**)&gQ, g_Q);
    cudaGetSymbolAddress((void**)&gK, g_K);
    cudaGetSymbolAddress((void**)&gV, g_V);
    cudaGetSymbolAddress((void**)&gY, g_Y);

    const dim3 gb(DM/64, ROWS/64);   // (16, 64)
    gemm_nt_kernel<1><<<gb, 256>>>(q, Wq, bq, gQ, DM);
    gemm_nt_kernel<1><<<gb, 256>>>(k, Wk, bk, gK, DM);
    gemm_nt_kernel<1><<<gb, 256>>>(v, Wv, bv, gV, DM);

    const int smem = (3*64*68 + 64*64) * (int)sizeof(float);   // 68608 B
    cudaFuncSetAttribute((const void*)attn_kernel,
                         cudaFuncAttributeMaxDynamicSharedMemorySize, smem);
    const dim3 ga(SEQ/64, NH*NB);    // (32, 32)
    attn_kernel<<<ga, 256, smem>>>(gQ, gK, gV, gY);

    gemm_nt_kernel<0><<<gb, 256>>>(gY, Wo, bo, out, DM);
}

// round 3
// speedup vs baseline: 1.5185x; 1.5185x over previous
#include <cuda_runtime.h>
#include <cuda_bf16.h>
#include <cstdint>

#define NB   2
#define SEQ  2048
#define DM   1024
#define NH   16
#define HD   64
#define ROWS (NB*SEQ)          // 4096
#define SCALE 0.125f           // 1/sqrt(64)

// ---------------------------------------------------------------------------
// Scratch (allocation-free: __device__ globals)
// ---------------------------------------------------------------------------
__device__ __align__(256) float g_Q[(size_t)NH*NB*SEQ*HD];
__device__ __align__(256) float g_K[(size_t)NH*NB*SEQ*HD];
__device__ __align__(256) float g_V[(size_t)NH*NB*SEQ*HD];
__device__ __align__(256) float g_Y[(size_t)ROWS*DM];

__device__ __align__(256) __nv_bfloat16 g_xh[3][(size_t)ROWS*DM];
__device__ __align__(256) __nv_bfloat16 g_xl[3][(size_t)ROWS*DM];
__device__ __align__(256) __nv_bfloat16 g_wh[4][(size_t)DM*DM];
__device__ __align__(256) __nv_bfloat16 g_wl[4][(size_t)DM*DM];
__device__ __align__(256) __nv_bfloat16 g_yh[(size_t)ROWS*DM];
__device__ __align__(256) __nv_bfloat16 g_yl[(size_t)ROWS*DM];

// ---------------------------------------------------------------------------
// PTX helpers (baseline sm_80+ features only: mma.sync / ldmatrix / cp.async)
// ---------------------------------------------------------------------------
__device__ __forceinline__ uint32_t smem_u32(const void* p) {
    uint32_t a;
    asm("{ .reg .u64 t; cvta.to.shared.u64 t, %1; cvt.u32.u64 %0, t; }"
        : "=r"(a) : "l"(p));
    return a;
}

#define CP_ASYNC16(dst, src) \
    asm volatile("cp.async.cg.shared.global [%0], [%1], 16;" :: "r"(dst), "l"(src))
#define CP_COMMIT() asm volatile("cp.async.commit_group;" ::: "memory")
#define CP_WAIT1()  asm volatile("cp.async.wait_group 1;" ::: "memory")
#define CP_WAIT0()  asm volatile("cp.async.wait_group 0;" ::: "memory")

__device__ __forceinline__ void ldm_x4(uint32_t* r, uint32_t addr) {
    asm volatile("ldmatrix.sync.aligned.m8n8.x4.shared.b16 {%0,%1,%2,%3}, [%4];"
                 : "=r"(r[0]), "=r"(r[1]), "=r"(r[2]), "=r"(r[3]) : "r"(addr));
}

__device__ __forceinline__ void mma_bf16(float* d, const uint32_t* a, const uint32_t* b) {
    asm volatile(
        "mma.sync.aligned.m16n8k16.row.col.f32.bf16.bf16.f32 "
        "{%0,%1,%2,%3}, {%4,%5,%6,%7}, {%8,%9}, {%0,%1,%2,%3};"
        : "+f"(d[0]), "+f"(d[1]), "+f"(d[2]), "+f"(d[3])
        : "r"(a[0]), "r"(a[1]), "r"(a[2]), "r"(a[3]), "r"(b[0]), "r"(b[1]));
}

// ---------------------------------------------------------------------------
// fp32 -> bf16 hi/lo split (vectorized by 4)
// ---------------------------------------------------------------------------
__global__ void __launch_bounds__(256) split_kernel(
    const float4* __restrict__ x, __nv_bfloat16* __restrict__ hi,
    __nv_bfloat16* __restrict__ lo, int n4)
{
    int i = blockIdx.x * blockDim.x + threadIdx.x;
    if (i >= n4) return;
    float4 v = x[i];
    __nv_bfloat16 h0 = __float2bfloat16(v.x);
    __nv_bfloat16 h1 = __float2bfloat16(v.y);
    __nv_bfloat16 h2 = __float2bfloat16(v.z);
    __nv_bfloat16 h3 = __float2bfloat16(v.w);
    __nv_bfloat16 l0 = __float2bfloat16(v.x - __bfloat162float(h0));
    __nv_bfloat16 l1 = __float2bfloat16(v.y - __bfloat162float(h1));
    __nv_bfloat16 l2 = __float2bfloat16(v.z - __bfloat162float(h2));
    __nv_bfloat16 l3 = __float2bfloat16(v.w - __bfloat162float(h3));
    __nv_bfloat162* hp = (__nv_bfloat162*)hi;
    __nv_bfloat162* lp = (__nv_bfloat162*)lo;
    hp[2*i]   = __nv_bfloat162(h0, h1);
    hp[2*i+1] = __nv_bfloat162(h2, h3);
    lp[2*i]   = __nv_bfloat162(l0, l1);
    lp[2*i+1] = __nv_bfloat162(l2, l3);
}

// ---------------------------------------------------------------------------
// HMMA bf16x3 NT GEMM: C[r,c] = sum_m A[r,m]*B[c,m] + bias[c]
// CTA tile 128x128, BK=32, 256 threads / 8 warps (2x4), warp tile 64x32.
// Double-buffered cp.async smem, padded rows (stride 40 bf16 = 80B).
// MODE 0: C row-major [ROWS, DM]; MODE 1: QKV scatter layout.
// ---------------------------------------------------------------------------
#define GSTRIDE 40                      // bf16 elems per smem row (32 + 8 pad)
#define ARR_BYTES (128 * GSTRIDE * 2)   // 10240 B per 128x32 tile
#define STAGE_BYTES (4 * ARR_BYTES)     // Ah, Al, Bh, Bl = 40960 B
#define NSTAGE (DM / 32)                // 32 k-chunks

template<int MODE>
__global__ void __launch_bounds__(256) gemm_mma(
    const __nv_bfloat16* __restrict__ Ah, const __nv_bfloat16* __restrict__ Al,
    const __nv_bfloat16* __restrict__ Bh, const __nv_bfloat16* __restrict__ Bl,
    const float* __restrict__ bias, float* __restrict__ C)
{
    extern __shared__ __align__(128) char smraw[];
    const uint32_t smem0 = smem_u32(smraw);

    const int tid = threadIdx.x;
    const int lane = tid & 31;
    const int wid = tid >> 5;
    const int wm = wid >> 2;            // 0..1
    const int wn = wid & 3;             // 0..3

    const int m0 = blockIdx.y << 7;
    const int n0 = blockIdx.x << 7;

    // global sources for the 4 streamed tiles (row base folded in)
    const __nv_bfloat16* gsrc[4] = {
        Ah + (size_t)m0 * DM, Al + (size_t)m0 * DM,
        Bh + (size_t)n0 * DM, Bl + (size_t)n0 * DM
    };

    // per-thread load coords (2 chunks of 16B per array per stage)
    const int r0c = tid >> 2, cc0 = tid & 3;          // chunk 0: rows 0..63
    const int r1c = r0c + 64;                          // chunk 1: rows 64..127

    auto load_stage = [&](int s) {
        const int kk = s * 32;
        const uint32_t sb = smem0 + (s & 1) * STAGE_BYTES;
        #pragma unroll
        for (int a = 0; a < 4; a++) {
            const __nv_bfloat16* g = gsrc[a];
            const uint32_t ab = sb + a * ARR_BYTES;
            CP_ASYNC16(ab + r0c * (GSTRIDE*2) + cc0 * 16,
                       g + (size_t)r0c * DM + kk + cc0 * 8);
            CP_ASYNC16(ab + r1c * (GSTRIDE*2) + cc0 * 16,
                       g + (size_t)r1c * DM + kk + cc0 * 8);
        }
    };

    float acc[4][4][4];
    #pragma unroll
    for (int i = 0; i < 4; i++)
        #pragma unroll
        for (int j = 0; j < 4; j++)
            #pragma unroll
            for (int e = 0; e < 4; e++) acc[i][j][e] = 0.f;

    // ldmatrix lane addressing (byte offsets within a 128x40 bf16 array)
    // A-frag: row = mbase + lane%16, col8 = (lane>>4)*8
    const int a_r = lane & 15, a_c = (lane >> 4) << 3;
    // B-frag pair: n = nbase + (lane&7) + ((lane>>3)&2)*4, k8 = ((lane>>3)&1)*8
    const int b_r = (lane & 7) + (((lane >> 3) & 2) << 2);
    const int b_c = ((lane >> 3) & 1) << 3;

    load_stage(0);
    CP_COMMIT();

    for (int s = 0; s < NSTAGE; s++) {
        if (s + 1 < NSTAGE) { load_stage(s + 1); CP_COMMIT(); CP_WAIT1(); }
        else                { CP_WAIT0(); }
        __syncthreads();

        const uint32_t sb = smem0 + (s & 1) * STAGE_BYTES;
        const uint32_t sAh = sb;
        const uint32_t sAl = sb + ARR_BYTES;
        const uint32_t sBh = sb + 2 * ARR_BYTES;
        const uint32_t sBl = sb + 3 * ARR_BYTES;

        #pragma unroll
        for (int k16 = 0; k16 < 2; k16++) {
            const int kc = k16 * 16;
            uint32_t ah[4][4], al[4][4], bh[2][4], bl[2][4];
            #pragma unroll
            for (int mt = 0; mt < 4; mt++) {
                const uint32_t off =
                    ((wm * 64 + mt * 16 + a_r) * GSTRIDE + kc + a_c) * 2;
                ldm_x4(ah[mt], sAh + off);
                ldm_x4(al[mt], sAl + off);
            }
            #pragma unroll
            for (int np = 0; np < 2; np++) {
                const uint32_t off =
                    ((wn * 32 + np * 16 + b_r) * GSTRIDE + kc + b_c) * 2;
                ldm_x4(bh[np], sBh + off);
                ldm_x4(bl[np], sBl + off);
            }
            #pragma unroll
            for (int mt = 0; mt < 4; mt++) {
                #pragma unroll
                for (int nt = 0; nt < 4; nt++) {
                    const uint32_t* Bhp = &bh[nt >> 1][(nt & 1) * 2];
                    const uint32_t* Blp = &bl[nt >> 1][(nt & 1) * 2];
                    mma_bf16(acc[mt][nt], ah[mt], Bhp);
                    mma_bf16(acc[mt][nt], ah[mt], Blp);
                    mma_bf16(acc[mt][nt], al[mt], Bhp);
                }
            }
        }
        __syncthreads();
    }

    // epilogue: D fragment -> global (+bias)
    #pragma unroll
    for (int mt = 0; mt < 4; mt++) {
        #pragma unroll
        for (int nt = 0; nt < 4; nt++) {
            const int col = n0 + wn * 32 + nt * 8 + ((lane & 3) << 1);
            const float b0 = bias[col], b1 = bias[col + 1];
            #pragma unroll
            for (int half = 0; half < 2; half++) {
                const int row = m0 + wm * 64 + mt * 16 + (lane >> 2) + half * 8;
                float2 v;
                v.x = acc[mt][nt][half * 2 + 0] + b0;
                v.y = acc[mt][nt][half * 2 + 1] + b1;
                if (MODE == 0) {
                    *(float2*)&C[(size_t)row * DM + col] = v;
                } else {
                    const int h = col >> 6, d = col & 63;
                    const int nb = row >> 11, kq = row & 2047;
                    *(float2*)&C[(((size_t)(h * NB + nb)) * SEQ + kq) * HD + d] = v;
                }
            }
        }
    }
}

// ---------------------------------------------------------------------------
// Flash-style attention (fp32, unchanged from round 1 passing version)
// ---------------------------------------------------------------------------
__global__ void __launch_bounds__(256) attn_kernel(
    const float* __restrict__ Q, const float* __restrict__ K,
    const float* __restrict__ V, float* __restrict__ Y)
{
    extern __shared__ float sm[];
    float (*Qs)[68] = (float(*)[68])(sm);
    float (*Ks)[68] = (float(*)[68])(sm + 64*68);
    float (*Ps)[68] = (float(*)[68])(sm + 2*64*68);
    float (*Vs)[64] = (float(*)[64])(sm + 3*64*68);

    const int tid = threadIdx.x;
    const int tx = tid & 15, ty = tid >> 4;
    const int hn = blockIdx.y;
    const int h = hn >> 1, n = hn & 1;
    const int q0 = blockIdx.x << 6;

    const float* Qb = Q + (size_t)hn * SEQ * HD;
    const float* Kb = K + (size_t)hn * SEQ * HD;
    const float* Vb = V + (size_t)hn * SEQ * HD;

    const int lrow = tid >> 2;
    const int lc4  = tid & 3;

    #pragma unroll
    for (int c = 0; c < 4; c++) {
        const int col = ((lc4 + (c << 2)) << 2);
        float4 qv = *(const float4*)&Qb[(size_t)(q0 + lrow) * HD + col];
        Qs[col+0][lrow] = qv.x; Qs[col+1][lrow] = qv.y;
        Qs[col+2][lrow] = qv.z; Qs[col+3][lrow] = qv.w;
    }

    float m_i[4], l_i[4], o[4][4];
    #pragma unroll
    for (int i = 0; i < 4; i++) {
        m_i[i] = -1e30f; l_i[i] = 0.f;
        #pragma unroll
        for (int j = 0; j < 4; j++) o[i][j] = 0.f;
    }

    for (int t = 0; t < SEQ/64; t++) {
        const int k0 = t << 6;
        float4 kreg[4], vreg[4];
        #pragma unroll
        for (int c = 0; c < 4; c++) {
            const int col = ((lc4 + (c << 2)) << 2);
            kreg[c] = *(const float4*)&Kb[(size_t)(k0 + lrow) * HD + col];
            vreg[c] = *(const float4*)&Vb[(size_t)(k0 + lrow) * HD + col];
        }
        __syncthreads();
        #pragma unroll
        for (int c = 0; c < 4; c++) {
            const int col = ((lc4 + (c << 2)) << 2);
            Ks[col+0][lrow] = kreg[c].x; Ks[col+1][lrow] = kreg[c].y;
            Ks[col+2][lrow] = kreg[c].z; Ks[col+3][lrow] = kreg[c].w;
            *(float4*)&Vs[lrow][col] = vreg[c];
        }
        __syncthreads();

        float s[4][4] = {};
        #pragma unroll 8
        for (int d = 0; d < HD; d++) {
            float4 a = *(const float4*)&Qs[d][ty << 2];
            float4 b = *(const float4*)&Ks[d][tx << 2];
            s[0][0] += a.x*b.x; s[0][1] += a.x*b.y; s[0][2] += a.x*b.z; s[0][3] += a.x*b.w;
            s[1][0] += a.y*b.x; s[1][1] += a.y*b.y; s[1][2] += a.y*b.z; s[1][3] += a.y*b.w;
            s[2][0] += a.z*b.x; s[2][1] += a.z*b.y; s[2][2] += a.z*b.z; s[2][3] += a.z*b.w;
            s[3][0] += a.w*b.x; s[3][1] += a.w*b.y; s[3][2] += a.w*b.z; s[3][3] += a.w*b.w;
        }

        #pragma unroll
        for (int i = 0; i < 4; i++) {
            float rmax = fmaxf(fmaxf(s[i][0], s[i][1]), fmaxf(s[i][2], s[i][3]));
            #pragma unroll
            for (int off = 8; off > 0; off >>= 1)
                rmax = fmaxf(rmax, __shfl_xor_sync(0xffffffffu, rmax, off));
            const float mnew = fmaxf(m_i[i], rmax);
            const float corr = __expf((m_i[i] - mnew) * SCALE);
            float rsum = 0.f;
            #pragma unroll
            for (int j = 0; j < 4; j++) {
                const float p = __expf((s[i][j] - mnew) * SCALE);
                Ps[(tx << 2) + j][(ty << 2) + i] = p;
                rsum += p;
            }
            #pragma unroll
            for (int off = 8; off > 0; off >>= 1)
                rsum += __shfl_xor_sync(0xffffffffu, rsum, off);
            l_i[i] = l_i[i] * corr + rsum;
            m_i[i] = mnew;
            #pragma unroll
            for (int j = 0; j < 4; j++) o[i][j] *= corr;
        }
        __syncthreads();

        #pragma unroll 8
        for (int kc = 0; kc < 64; kc++) {
            float4 a = *(const float4*)&Ps[kc][ty << 2];
            float4 b = *(const float4*)&Vs[kc][tx << 2];
            o[0][0] += a.x*b.x; o[0][1] += a.x*b.y; o[0][2] += a.x*b.z; o[0][3] += a.x*b.w;
            o[1][0] += a.y*b.x; o[1][1] += a.y*b.y; o[1][2] += a.y*b.z; o[1][3] += a.y*b.w;
            o[2][0] += a.z*b.x; o[2][1] += a.z*b.y; o[2][2] += a.z*b.z; o[2][3] += a.z*b.w;
            o[3][0] += a.w*b.x; o[3][1] += a.w*b.y; o[3][2] += a.w*b.z; o[3][3] += a.w*b.w;
        }
    }

    #pragma unroll
    for (int i = 0; i < 4; i++) {
        const float inv = 1.f / l_i[i];
        const int r = q0 + (ty << 2) + i;
        #pragma unroll
        for (int j = 0; j < 4; j++) {
            Y[((size_t)(n*SEQ + r)) * DM + h*HD + (tx << 2) + j] = o[i][j] * inv;
        }
    }
}

// ---------------------------------------------------------------------------
extern "C" void kernel_launch(void* const* d_in, const int* in_sizes, int n_in,
                              void* d_out, int out_size)
{
    const float* q  = (const float*)d_in[0];
    const float* k  = (const float*)d_in[1];
    const float* v  = (const float*)d_in[2];
    const float* Wq = (const float*)d_in[3];
    const float* bq = (const float*)d_in[4];
    const float* Wk = (const float*)d_in[5];
    const float* bk = (const float*)d_in[6];
    const float* Wv = (const float*)d_in[7];
    const float* bv = (const float*)d_in[8];
    const float* Wo = (const float*)d_in[9];
    const float* bo = (const float*)d_in[10];
    float* out = (float*)d_out;

    float *gQ, *gK, *gV, *gY;
    cudaGetSymbolAddress((void**)&gQ, g_Q);
    cudaGetSymbolAddress((void**)&gK, g_K);
    cudaGetSymbolAddress((void**)&gV, g_V);
    cudaGetSymbolAddress((void**)&gY, g_Y);
    __nv_bfloat16 *xh, *xl, *wh, *wl, *yh, *yl;
    cudaGetSymbolAddress((void**)&xh, g_xh);
    cudaGetSymbolAddress((void**)&xl, g_xl);
    cudaGetSymbolAddress((void**)&wh, g_wh);
    cudaGetSymbolAddress((void**)&wl, g_wl);
    cudaGetSymbolAddress((void**)&yh, g_yh);
    cudaGetSymbolAddress((void**)&yl, g_yl);

    const size_t XN = (size_t)ROWS * DM;   // 4M
    const size_t WN = (size_t)DM * DM;     // 1M

    split_kernel<<<(int)(XN/4 + 255)/256, 256>>>((const float4*)q, xh,          xl,          (int)(XN/4));
    split_kernel<<<(int)(XN/4 + 255)/256, 256>>>((const float4*)k, xh + XN,     xl + XN,     (int)(XN/4));
    split_kernel<<<(int)(XN/4 + 255)/256, 256>>>((const float4*)v, xh + 2*XN,   xl + 2*XN,   (int)(XN/4));
    split_kernel<<<(int)(WN/4 + 255)/256, 256>>>((const float4*)Wq, wh,         wl,          (int)(WN/4));
    split_kernel<<<(int)(WN/4 + 255)/256, 256>>>((const float4*)Wk, wh + WN,    wl + WN,     (int)(WN/4));
    split_kernel<<<(int)(WN/4 + 255)/256, 256>>>((const float4*)Wv, wh + 2*WN,  wl + 2*WN,   (int)(WN/4));
    split_kernel<<<(int)(WN/4 + 255)/256, 256>>>((const float4*)Wo, wh + 3*WN,  wl + 3*WN,   (int)(WN/4));

    const int gsmem = 2 * STAGE_BYTES;      // 81920 B
    cudaFuncSetAttribute((const void*)gemm_mma<1>,
                         cudaFuncAttributeMaxDynamicSharedMemorySize, gsmem);
    cudaFuncSetAttribute((const void*)gemm_mma<0>,
                         cudaFuncAttributeMaxDynamicSharedMemorySize, gsmem);
    const dim3 gg(DM/128, ROWS/128);   // (8, 32)
    gemm_mma<1><<<gg, 256, gsmem>>>(xh,        xl,        wh,        wl,        bq, gQ);
    gemm_mma<1><<<gg, 256, gsmem>>>(xh + XN,   xl + XN,   wh + WN,   wl + WN,   bk, gK);
    gemm_mma<1><<<gg, 256, gsmem>>>(xh + 2*XN, xl + 2*XN, wh + 2*WN, wl + 2*WN, bv, gV);

    const int asmem = (3*64*68 + 64*64) * (int)sizeof(float);   // 68608 B
    cudaFuncSetAttribute((const void*)attn_kernel,
                         cudaFuncAttributeMaxDynamicSharedMemorySize, asmem);
    const dim3 ga(SEQ/64, NH*NB);    // (32, 32)
    attn_kernel<<<ga, 256, asmem>>>(gQ, gK, gV, gY);

    split_kernel<<<(int)(XN/4 + 255)/256, 256>>>((const float4*)gY, yh, yl, (int)(XN/4));
    gemm_mma<0><<<gg, 256, gsmem>>>(yh, yl, wh + 3*WN, wl + 3*WN, bo, out);
}

// round 4
// speedup vs baseline: 2.8218x; 1.8583x over previous
#include <cuda_runtime.h>
#include <cuda_bf16.h>
#include <cstdint>

#define NB   2
#define SEQ  2048
#define DM   1024
#define NH   16
#define HD   64
#define ROWS (NB*SEQ)          // 4096
#define SCALE 0.125f           // 1/sqrt(64)

// ---------------------------------------------------------------------------
// Scratch (allocation-free: __device__ globals)
// ---------------------------------------------------------------------------
#define PROJN ((size_t)NH*NB*SEQ*HD)     // 4M elems
__device__ __align__(256) __nv_bfloat16 g_qh[PROJN], g_ql[PROJN];
__device__ __align__(256) __nv_bfloat16 g_kh[PROJN], g_kl[PROJN];
__device__ __align__(256) __nv_bfloat16 g_vh[PROJN], g_vl[PROJN];
__device__ __align__(256) __nv_bfloat16 g_xh[3][(size_t)ROWS*DM];
__device__ __align__(256) __nv_bfloat16 g_xl[3][(size_t)ROWS*DM];
__device__ __align__(256) __nv_bfloat16 g_wh[4][(size_t)DM*DM];
__device__ __align__(256) __nv_bfloat16 g_wl[4][(size_t)DM*DM];
__device__ __align__(256) __nv_bfloat16 g_yh[(size_t)ROWS*DM];
__device__ __align__(256) __nv_bfloat16 g_yl[(size_t)ROWS*DM];

// ---------------------------------------------------------------------------
// PTX helpers (baseline sm_80+ features: mma.sync / ldmatrix / cp.async)
// ---------------------------------------------------------------------------
__device__ __forceinline__ uint32_t smem_u32(const void* p) {
    uint32_t a;
    asm("{ .reg .u64 t; cvta.to.shared.u64 t, %1; cvt.u32.u64 %0, t; }"
        : "=r"(a) : "l"(p));
    return a;
}

#define CP_ASYNC16(dst, src) \
    asm volatile("cp.async.cg.shared.global [%0], [%1], 16;" :: "r"(dst), "l"(src))
#define CP_COMMIT() asm volatile("cp.async.commit_group;" ::: "memory")
#define CP_WAIT1()  asm volatile("cp.async.wait_group 1;" ::: "memory")
#define CP_WAIT0()  asm volatile("cp.async.wait_group 0;" ::: "memory")

__device__ __forceinline__ void ldm_x4(uint32_t* r, uint32_t addr) {
    asm volatile("ldmatrix.sync.aligned.m8n8.x4.shared.b16 {%0,%1,%2,%3}, [%4];"
                 : "=r"(r[0]), "=r"(r[1]), "=r"(r[2]), "=r"(r[3]) : "r"(addr));
}
__device__ __forceinline__ void ldm_x4_t(uint32_t* r, uint32_t addr) {
    asm volatile("ldmatrix.sync.aligned.m8n8.x4.trans.shared.b16 {%0,%1,%2,%3}, [%4];"
                 : "=r"(r[0]), "=r"(r[1]), "=r"(r[2]), "=r"(r[3]) : "r"(addr));
}

__device__ __forceinline__ void mma_bf16(float* d, const uint32_t* a, const uint32_t* b) {
    asm volatile(
        "mma.sync.aligned.m16n8k16.row.col.f32.bf16.bf16.f32 "
        "{%0,%1,%2,%3}, {%4,%5,%6,%7}, {%8,%9}, {%0,%1,%2,%3};"
        : "+f"(d[0]), "+f"(d[1]), "+f"(d[2]), "+f"(d[3])
        : "r"(a[0]), "r"(a[1]), "r"(a[2]), "r"(a[3]), "r"(b[0]), "r"(b[1]));
}

// fp32 pair -> packed bf16x2 hi + bf16x2 lo  (a in low half)
__device__ __forceinline__ void split2(float a, float b, uint32_t& hi, uint32_t& lo) {
    __nv_bfloat16 ha = __float2bfloat16(a), hb = __float2bfloat16(b);
    __nv_bfloat16 la = __float2bfloat16(a - __bfloat162float(ha));
    __nv_bfloat16 lb = __float2bfloat16(b - __bfloat162float(hb));
    __nv_bfloat162 H(ha, hb), L(la, lb);
    hi = *(uint32_t*)&H; lo = *(uint32_t*)&L;
}

// ---------------------------------------------------------------------------
// fp32 -> bf16 hi/lo split (vectorized by 4)
// ---------------------------------------------------------------------------
__global__ void __launch_bounds__(256) split_kernel(
    const float4* __restrict__ x, __nv_bfloat16* __restrict__ hi,
    __nv_bfloat16* __restrict__ lo, int n4)
{
    int i = blockIdx.x * blockDim.x + threadIdx.x;
    if (i >= n4) return;
    float4 v = x[i];
    uint32_t h0, l0, h1, l1;
    split2(v.x, v.y, h0, l0);
    split2(v.z, v.w, h1, l1);
    uint32_t* hp = (uint32_t*)hi;
    uint32_t* lp = (uint32_t*)lo;
    hp[2*i] = h0; hp[2*i+1] = h1;
    lp[2*i] = l0; lp[2*i+1] = l1;
}

// ---------------------------------------------------------------------------
// HMMA bf16x3 NT GEMM core, CTA 128x128, BK=32, 8 warps (2x4), warp 64x32.
// MODE 0: fp32 C row-major [ROWS, DM]
// MODE 2: bf16 hi/lo pair output in QKV scatter layout [(h*NB+n)][seq][HD]
// ---------------------------------------------------------------------------
#define GSTRIDE 40
#define ARR_BYTES (128 * GSTRIDE * 2)
#define STAGE_BYTES (4 * ARR_BYTES)
#define NSTAGE (DM / 32)

template<int MODE>
__device__ __forceinline__ void gemm_body(
    const __nv_bfloat16* __restrict__ Ah, const __nv_bfloat16* __restrict__ Al,
    const __nv_bfloat16* __restrict__ Bh, const __nv_bfloat16* __restrict__ Bl,
    const float* __restrict__ bias, float* __restrict__ C,
    __nv_bfloat16* __restrict__ Ch, __nv_bfloat16* __restrict__ Cl)
{
    extern __shared__ __align__(128) char smraw[];
    const uint32_t smem0 = smem_u32(smraw);

    const int tid = threadIdx.x;
    const int lane = tid & 31;
    const int wid = tid >> 5;
    const int wm = wid >> 2;
    const int wn = wid & 3;

    const int m0 = blockIdx.y << 7;
    const int n0 = blockIdx.x << 7;

    const __nv_bfloat16* gsrc[4] = {
        Ah + (size_t)m0 * DM, Al + (size_t)m0 * DM,
        Bh + (size_t)n0 * DM, Bl + (size_t)n0 * DM
    };

    const int r0c = tid >> 2, cc0 = tid & 3;
    const int r1c = r0c + 64;

    auto load_stage = [&](int s) {
        const int kk = s * 32;
        const uint32_t sb = smem0 + (s & 1) * STAGE_BYTES;
        #pragma unroll
        for (int a = 0; a < 4; a++) {
            const __nv_bfloat16* g = gsrc[a];
            const uint32_t ab = sb + a * ARR_BYTES;
            CP_ASYNC16(ab + r0c * (GSTRIDE*2) + cc0 * 16,
                       g + (size_t)r0c * DM + kk + cc0 * 8);
            CP_ASYNC16(ab + r1c * (GSTRIDE*2) + cc0 * 16,
                       g + (size_t)r1c * DM + kk + cc0 * 8);
        }
    };

    float acc[4][4][4];
    #pragma unroll
    for (int i = 0; i < 4; i++)
        #pragma unroll
        for (int j = 0; j < 4; j++)
            #pragma unroll
            for (int e = 0; e < 4; e++) acc[i][j][e] = 0.f;

    const int a_r = lane & 15, a_c = (lane >> 4) << 3;
    const int b_r = (lane & 7) + (((lane >> 3) & 2) << 2);
    const int b_c = ((lane >> 3) & 1) << 3;

    load_stage(0);
    CP_COMMIT();

    for (int s = 0; s < NSTAGE; s++) {
        if (s + 1 < NSTAGE) { load_stage(s + 1); CP_COMMIT(); CP_WAIT1(); }
        else                { CP_WAIT0(); }
        __syncthreads();

        const uint32_t sb = smem0 + (s & 1) * STAGE_BYTES;
        const uint32_t sAh = sb;
        const uint32_t sAl = sb + ARR_BYTES;
        const uint32_t sBh = sb + 2 * ARR_BYTES;
        const uint32_t sBl = sb + 3 * ARR_BYTES;

        #pragma unroll
        for (int k16 = 0; k16 < 2; k16++) {
            const int kc = k16 * 16;
            uint32_t ah[4][4], al[4][4], bh[2][4], bl[2][4];
            #pragma unroll
            for (int mt = 0; mt < 4; mt++) {
                const uint32_t off =
                    ((wm * 64 + mt * 16 + a_r) * GSTRIDE + kc + a_c) * 2;
                ldm_x4(ah[mt], sAh + off);
                ldm_x4(al[mt], sAl + off);
            }
            #pragma unroll
            for (int np = 0; np < 2; np++) {
                const uint32_t off =
                    ((wn * 32 + np * 16 + b_r) * GSTRIDE + kc + b_c) * 2;
                ldm_x4(bh[np], sBh + off);
                ldm_x4(bl[np], sBl + off);
            }
            #pragma unroll
            for (int mt = 0; mt < 4; mt++) {
                #pragma unroll
                for (int nt = 0; nt < 4; nt++) {
                    const uint32_t* Bhp = &bh[nt >> 1][(nt & 1) * 2];
                    const uint32_t* Blp = &bl[nt >> 1][(nt & 1) * 2];
                    mma_bf16(acc[mt][nt], ah[mt], Bhp);
                    mma_bf16(acc[mt][nt], ah[mt], Blp);
                    mma_bf16(acc[mt][nt], al[mt], Bhp);
                }
            }
        }
        __syncthreads();
    }

    #pragma unroll
    for (int mt = 0; mt < 4; mt++) {
        #pragma unroll
        for (int nt = 0; nt < 4; nt++) {
            const int col = n0 + wn * 32 + nt * 8 + ((lane & 3) << 1);
            const float b0 = bias[col], b1 = bias[col + 1];
            #pragma unroll
            for (int half = 0; half < 2; half++) {
                const int row = m0 + wm * 64 + mt * 16 + (lane >> 2) + half * 8;
                const float vx = acc[mt][nt][half * 2 + 0] + b0;
                const float vy = acc[mt][nt][half * 2 + 1] + b1;
                if (MODE == 0) {
                    float2 v; v.x = vx; v.y = vy;
                    *(float2*)&C[(size_t)row * DM + col] = v;
                } else {
                    const int h = col >> 6, d = col & 63;
                    const int nb = row >> 11, kq = row & 2047;
                    const size_t idx = (((size_t)(h * NB + nb)) * SEQ + kq) * HD + d;
                    uint32_t hi, lo;
                    split2(vx, vy, hi, lo);
                    *(uint32_t*)&Ch[idx] = hi;
                    *(uint32_t*)&Cl[idx] = lo;
                }
            }
        }
    }
}

// merged QKV projection: gridDim.z = 3 selects q/k/v
__global__ void __launch_bounds__(256) gemm_qkv(
    const __nv_bfloat16* __restrict__ xh, const __nv_bfloat16* __restrict__ xl,
    const __nv_bfloat16* __restrict__ wh, const __nv_bfloat16* __restrict__ wl,
    const float* __restrict__ bq, const float* __restrict__ bk,
    const float* __restrict__ bv)
{
    const int z = blockIdx.z;
    const size_t XN = (size_t)ROWS * DM, WN = (size_t)DM * DM;
    const float* bias = (z == 0) ? bq : (z == 1) ? bk : bv;
    __nv_bfloat16* Ch = (z == 0) ? g_qh : (z == 1) ? g_kh : g_vh;
    __nv_bfloat16* Cl = (z == 0) ? g_ql : (z == 1) ? g_kl : g_vl;
    gemm_body<2>(xh + z * XN, xl + z * XN, wh + z * WN, wl + z * WN,
                 bias, nullptr, Ch, Cl);
}

__global__ void __launch_bounds__(256) gemm_out(
    const __nv_bfloat16* __restrict__ Ah, const __nv_bfloat16* __restrict__ Al,
    const __nv_bfloat16* __restrict__ Bh, const __nv_bfloat16* __restrict__ Bl,
    const float* __restrict__ bias, float* __restrict__ C)
{
    gemm_body<0>(Ah, Al, Bh, Bl, bias, C, nullptr, nullptr);
}

// ---------------------------------------------------------------------------
// FA2-style HMMA attention.
// CTA: 128 q-rows x (h,n). 8 warps x m16. K-tile 64, double-buffered cp.async.
// smem arrays: rows x 72 bf16 (144B stride). Stage = Kh,Kl,Vh,Vl (36864 B).
// ---------------------------------------------------------------------------
#define ASTRIDE 72
#define AARR    (64 * ASTRIDE * 2)      // 9216 B
#define ASTAGE  (4 * AARR)              // 36864 B

__global__ void __launch_bounds__(256) attn_mma(
    const __nv_bfloat16* __restrict__ Qh_, const __nv_bfloat16* __restrict__ Ql_,
    const __nv_bfloat16* __restrict__ Kh_, const __nv_bfloat16* __restrict__ Kl_,
    const __nv_bfloat16* __restrict__ Vh_, const __nv_bfloat16* __restrict__ Vl_,
    __nv_bfloat16* __restrict__ Yh, __nv_bfloat16* __restrict__ Yl)
{
    extern __shared__ __align__(128) char smraw[];
    const uint32_t s0 = smem_u32(smraw);

    const int tid = threadIdx.x;
    const int lane = tid & 31;
    const int wid = tid >> 5;
    const int hn = blockIdx.y;
    const int h = hn >> 1, n = hn & 1;
    const int q0 = blockIdx.x << 7;
    const size_t hoff = (size_t)hn * SEQ * HD;

    const int a_r = lane & 15, a_c = (lane >> 4) << 3;
    const int b_r = (lane & 7) + (((lane >> 3) & 2) << 2);
    const int b_c = ((lane >> 3) & 1) << 3;

    // ---- stage Q into smem, ldmatrix into registers ----
    {
        const __nv_bfloat16* Qhg = Qh_ + hoff + (size_t)q0 * HD;
        const __nv_bfloat16* Qlg = Ql_ + hoff + (size_t)q0 * HD;
        #pragma unroll
        for (int c = 0; c < 4; c++) {
            const int ch = tid + c * 256;            // 0..1023
            const int row = ch >> 3, c16 = ch & 7;
            CP_ASYNC16(s0 + row * 144 + c16 * 16, Qhg + row * 64 + c16 * 8);
            CP_ASYNC16(s0 + 18432 + row * 144 + c16 * 16, Qlg + row * 64 + c16 * 8);
        }
        CP_COMMIT(); CP_WAIT0();
        __syncthreads();
    }
    uint32_t qfh[4][4], qfl[4][4];
    #pragma unroll
    for (int t4 = 0; t4 < 4; t4++) {
        const uint32_t off = ((wid * 16 + a_r) * ASTRIDE + 16 * t4 + a_c) * 2;
        ldm_x4(qfh[t4], s0 + off);
        ldm_x4(qfl[t4], s0 + 18432 + off);
    }
    __syncthreads();

    const __nv_bfloat16* Khg = Kh_ + hoff;
    const __nv_bfloat16* Klg = Kl_ + hoff;
    const __nv_bfloat16* Vhg = Vh_ + hoff;
    const __nv_bfloat16* Vlg = Vl_ + hoff;

    auto load_stage = [&](int s) {
        const int kv0 = s << 6;
        const uint32_t sb = s0 + (s & 1) * ASTAGE;
        const __nv_bfloat16* gs[4] = { Khg, Klg, Vhg, Vlg };
        #pragma unroll
        for (int a = 0; a < 4; a++) {
            #pragma unroll
            for (int c = 0; c < 2; c++) {
                const int ch = tid + c * 256;        // 0..511
                const int row = ch >> 3, c16 = ch & 7;
                CP_ASYNC16(sb + a * AARR + row * 144 + c16 * 16,
                           gs[a] + (size_t)(kv0 + row) * 64 + c16 * 8);
            }
        }
    };

    float m0r = -1e30f, m1r = -1e30f, l0 = 0.f, l1 = 0.f;
    float O[8][4];
    #pragma unroll
    for (int j = 0; j < 8; j++)
        #pragma unroll
        for (int e = 0; e < 4; e++) O[j][e] = 0.f;

    load_stage(0); CP_COMMIT();

    for (int t = 0; t < SEQ / 64; t++) {
        if (t + 1 < SEQ / 64) { load_stage(t + 1); CP_COMMIT(); CP_WAIT1(); }
        else                  { CP_WAIT0(); }
        __syncthreads();

        const uint32_t sb = s0 + (t & 1) * ASTAGE;

        // ---- S = Q K^T (bf16x3) ----
        float S[8][4];
        #pragma unroll
        for (int j = 0; j < 8; j++)
            #pragma unroll
            for (int e = 0; e < 4; e++) S[j][e] = 0.f;

        #pragma unroll
        for (int t4 = 0; t4 < 4; t4++) {
            #pragma unroll
            for (int jp = 0; jp < 4; jp++) {
                uint32_t bh[4], bl[4];
                const uint32_t off = ((16 * jp + b_r) * ASTRIDE + 16 * t4 + b_c) * 2;
                ldm_x4(bh, sb + off);
                ldm_x4(bl, sb + AARR + off);
                mma_bf16(S[2*jp],   qfh[t4], &bh[0]);
                mma_bf16(S[2*jp],   qfh[t4], &bl[0]);
                mma_bf16(S[2*jp],   qfl[t4], &bh[0]);
                mma_bf16(S[2*jp+1], qfh[t4], &bh[2]);
                mma_bf16(S[2*jp+1], qfh[t4], &bl[2]);
                mma_bf16(S[2*jp+1], qfl[t4], &bh[2]);
            }
        }

        // ---- online softmax ----
        float corr0, corr1;
        {
            float tm = S[0][0];
            #pragma unroll
            for (int j = 0; j < 8; j++) tm = fmaxf(tm, fmaxf(S[j][0], S[j][1]));
            tm = fmaxf(tm, __shfl_xor_sync(0xffffffffu, tm, 1));
            tm = fmaxf(tm, __shfl_xor_sync(0xffffffffu, tm, 2));
            const float mnew = fmaxf(m0r, tm);
            corr0 = __expf((m0r - mnew) * SCALE);
            float rs = 0.f;
            #pragma unroll
            for (int j = 0; j < 8; j++) {
                S[j][0] = __expf((S[j][0] - mnew) * SCALE);
                S[j][1] = __expf((S[j][1] - mnew) * SCALE);
                rs += S[j][0] + S[j][1];
            }
            rs += __shfl_xor_sync(0xffffffffu, rs, 1);
            rs += __shfl_xor_sync(0xffffffffu, rs, 2);
            l0 = l0 * corr0 + rs;
            m0r = mnew;
        }
        {
            float tm = S[0][2];
            #pragma unroll
            for (int j = 0; j < 8; j++) tm = fmaxf(tm, fmaxf(S[j][2], S[j][3]));
            tm = fmaxf(tm, __shfl_xor_sync(0xffffffffu, tm, 1));
            tm = fmaxf(tm, __shfl_xor_sync(0xffffffffu, tm, 2));
            const float mnew = fmaxf(m1r, tm);
            corr1 = __expf((m1r - mnew) * SCALE);
            float rs = 0.f;
            #pragma unroll
            for (int j = 0; j < 8; j++) {
                S[j][2] = __expf((S[j][2] - mnew) * SCALE);
                S[j][3] = __expf((S[j][3] - mnew) * SCALE);
                rs += S[j][2] + S[j][3];
            }
            rs += __shfl_xor_sync(0xffffffffu, rs, 1);
            rs += __shfl_xor_sync(0xffffffffu, rs, 2);
            l1 = l1 * corr1 + rs;
            m1r = mnew;
        }

        // ---- pack P to bf16 hi/lo A-fragments ----
        uint32_t pah[4][4], pal[4][4];
        #pragma unroll
        for (int t4 = 0; t4 < 4; t4++) {
            split2(S[2*t4][0],   S[2*t4][1],   pah[t4][0], pal[t4][0]);
            split2(S[2*t4][2],   S[2*t4][3],   pah[t4][1], pal[t4][1]);
            split2(S[2*t4+1][0], S[2*t4+1][1], pah[t4][2], pal[t4][2]);
            split2(S[2*t4+1][2], S[2*t4+1][3], pah[t4][3], pal[t4][3]);
        }

        // ---- rescale O ----
        #pragma unroll
        for (int j = 0; j < 8; j++) {
            O[j][0] *= corr0; O[j][1] *= corr0;
            O[j][2] *= corr1; O[j][3] *= corr1;
        }

        // ---- O += P V (bf16x3, V via ldmatrix.trans) ----
        #pragma unroll
        for (int t4 = 0; t4 < 4; t4++) {
            #pragma unroll
            for (int jp = 0; jp < 4; jp++) {
                uint32_t vh[4], vl[4];
                const uint32_t off =
                    ((16 * t4 + (lane & 15)) * ASTRIDE + 16 * jp + a_c) * 2;
                ldm_x4_t(vh, sb + 2 * AARR + off);
                ldm_x4_t(vl, sb + 3 * AARR + off);
                mma_bf16(O[2*jp],   pah[t4], &vh[0]);
                mma_bf16(O[2*jp],   pah[t4], &vl[0]);
                mma_bf16(O[2*jp],   pal[t4], &vh[0]);
                mma_bf16(O[2*jp+1], pah[t4], &vh[2]);
                mma_bf16(O[2*jp+1], pah[t4], &vl[2]);
                mma_bf16(O[2*jp+1], pal[t4], &vh[2]);
            }
        }
        __syncthreads();
    }

    // ---- epilogue: scale by 1/l, write bf16 hi/lo in [N, K, H*D] layout ----
    const float inv0 = 1.f / l0, inv1 = 1.f / l1;
    #pragma unroll
    for (int j = 0; j < 8; j++) {
        const int col = h * 64 + 8 * j + ((lane & 3) << 1);
        #pragma unroll
        for (int half = 0; half < 2; half++) {
            const int row = q0 + wid * 16 + (lane >> 2) + half * 8;
            const float inv = half ? inv1 : inv0;
            const float y0 = O[j][half * 2 + 0] * inv;
            const float y1 = O[j][half * 2 + 1] * inv;
            const size_t idx = ((size_t)(n * SEQ) + row) * DM + col;
            uint32_t hi, lo;
            split2(y0, y1, hi, lo);
            *(uint32_t*)&Yh[idx] = hi;
            *(uint32_t*)&Yl[idx] = lo;
        }
    }
}

// ---------------------------------------------------------------------------
extern "C" void kernel_launch(void* const* d_in, const int* in_sizes, int n_in,
                              void* d_out, int out_size)
{
    const float* q  = (const float*)d_in[0];
    const float* k  = (const float*)d_in[1];
    const float* v  = (const float*)d_in[2];
    const float* Wq = (const float*)d_in[3];
    const float* bq = (const float*)d_in[4];
    const float* Wk = (const float*)d_in[5];
    const float* bk = (const float*)d_in[6];
    const float* Wv = (const float*)d_in[7];
    const float* bv = (const float*)d_in[8];
    const float* Wo = (const float*)d_in[9];
    const float* bo = (const float*)d_in[10];
    float* out = (float*)d_out;

    __nv_bfloat16 *xh, *xl, *wh, *wl, *yh, *yl, *qh, *ql, *kh, *kl, *vh, *vl;
    cudaGetSymbolAddress((void**)&xh, g_xh);
    cudaGetSymbolAddress((void**)&xl, g_xl);
    cudaGetSymbolAddress((void**)&wh, g_wh);
    cudaGetSymbolAddress((void**)&wl, g_wl);
    cudaGetSymbolAddress((void**)&yh, g_yh);
    cudaGetSymbolAddress((void**)&yl, g_yl);
    cudaGetSymbolAddress((void**)&qh, g_qh);
    cudaGetSymbolAddress((void**)&ql, g_ql);
    cudaGetSymbolAddress((void**)&kh, g_kh);
    cudaGetSymbolAddress((void**)&kl, g_kl);
    cudaGetSymbolAddress((void**)&vh, g_vh);
    cudaGetSymbolAddress((void**)&vl, g_vl);

    const size_t XN = (size_t)ROWS * DM;
    const size_t WN = (size_t)DM * DM;

    split_kernel<<<(int)(XN/4 + 255)/256, 256>>>((const float4*)q,  xh,         xl,         (int)(XN/4));
    split_kernel<<<(int)(XN/4 + 255)/256, 256>>>((const float4*)k,  xh + XN,    xl + XN,    (int)(XN/4));
    split_kernel<<<(int)(XN/4 + 255)/256, 256>>>((const float4*)v,  xh + 2*XN,  xl + 2*XN,  (int)(XN/4));
    split_kernel<<<(int)(WN/4 + 255)/256, 256>>>((const float4*)Wq, wh,         wl,         (int)(WN/4));
    split_kernel<<<(int)(WN/4 + 255)/256, 256>>>((const float4*)Wk, wh + WN,    wl + WN,    (int)(WN/4));
    split_kernel<<<(int)(WN/4 + 255)/256, 256>>>((const float4*)Wv, wh + 2*WN,  wl + 2*WN,  (int)(WN/4));
    split_kernel<<<(int)(WN/4 + 255)/256, 256>>>((const float4*)Wo, wh + 3*WN,  wl + 3*WN,  (int)(WN/4));

    const int gsmem = 2 * STAGE_BYTES;
    cudaFuncSetAttribute((const void*)gemm_qkv,
                         cudaFuncAttributeMaxDynamicSharedMemorySize, gsmem);
    cudaFuncSetAttribute((const void*)gemm_out,
                         cudaFuncAttributeMaxDynamicSharedMemorySize, gsmem);
    const dim3 gq(DM/128, ROWS/128, 3);
    gemm_qkv<<<gq, 256, gsmem>>>(xh, xl, wh, wl, bq, bk, bv);

    const int asmem = 2 * ASTAGE;   // 73728
    cudaFuncSetAttribute((const void*)attn_mma,
                         cudaFuncAttributeMaxDynamicSharedMemorySize, asmem);
    const dim3 ga(SEQ/128, NH*NB);  // (16, 32)
    attn_mma<<<ga, 256, asmem>>>(qh, ql, kh, kl, vh, vl, yh, yl);

    const dim3 gg(DM/128, ROWS/128);
    gemm_out<<<gg, 256, gsmem>>>(yh, yl, wh + 3*WN, wl + 3*WN, bo, out);
}

// round 5
// speedup vs baseline: 3.0450x; 1.0791x over previous
#include <cuda_runtime.h>
#include <cuda_bf16.h>
#include <cstdint>

#define NB   2
#define SEQ  2048
#define DM   1024
#define NH   16
#define HD   64
#define ROWS (NB*SEQ)          // 4096
#define SCALE 0.125f           // 1/sqrt(64)

// ---------------------------------------------------------------------------
// Scratch (allocation-free: __device__ globals)
// ---------------------------------------------------------------------------
#define PROJN ((size_t)NH*NB*SEQ*HD)     // 4M elems
__device__ __align__(256) __nv_bfloat16 g_qh[PROJN], g_ql[PROJN];
__device__ __align__(256) __nv_bfloat16 g_kh[PROJN], g_kl[PROJN];
__device__ __align__(256) __nv_bfloat16 g_vh[PROJN], g_vl[PROJN];
__device__ __align__(256) __nv_bfloat16 g_xh[3][(size_t)ROWS*DM];
__device__ __align__(256) __nv_bfloat16 g_xl[3][(size_t)ROWS*DM];
__device__ __align__(256) __nv_bfloat16 g_wh[4][(size_t)DM*DM];
__device__ __align__(256) __nv_bfloat16 g_wl[4][(size_t)DM*DM];
__device__ __align__(256) __nv_bfloat16 g_yh[(size_t)ROWS*DM];
__device__ __align__(256) __nv_bfloat16 g_yl[(size_t)ROWS*DM];

// ---------------------------------------------------------------------------
// PTX helpers (baseline sm_80+ features: mma.sync / ldmatrix / cp.async)
// ---------------------------------------------------------------------------
__device__ __forceinline__ uint32_t smem_u32(const void* p) {
    uint32_t a;
    asm("{ .reg .u64 t; cvta.to.shared.u64 t, %1; cvt.u32.u64 %0, t; }"
        : "=r"(a) : "l"(p));
    return a;
}

#define CP_ASYNC16(dst, src) \
    asm volatile("cp.async.cg.shared.global [%0], [%1], 16;" :: "r"(dst), "l"(src))
#define CP_COMMIT() asm volatile("cp.async.commit_group;" ::: "memory")
#define CP_WAIT0()  asm volatile("cp.async.wait_group 0;" ::: "memory")

__device__ __forceinline__ void ldm_x4(uint32_t* r, uint32_t addr) {
    asm volatile("ldmatrix.sync.aligned.m8n8.x4.shared.b16 {%0,%1,%2,%3}, [%4];"
                 : "=r"(r[0]), "=r"(r[1]), "=r"(r[2]), "=r"(r[3]) : "r"(addr));
}
__device__ __forceinline__ void ldm_x4_t(uint32_t* r, uint32_t addr) {
    asm volatile("ldmatrix.sync.aligned.m8n8.x4.trans.shared.b16 {%0,%1,%2,%3}, [%4];"
                 : "=r"(r[0]), "=r"(r[1]), "=r"(r[2]), "=r"(r[3]) : "r"(addr));
}

__device__ __forceinline__ void mma_bf16(float* d, const uint32_t* a, const uint32_t* b) {
    asm volatile(
        "mma.sync.aligned.m16n8k16.row.col.f32.bf16.bf16.f32 "
        "{%0,%1,%2,%3}, {%4,%5,%6,%7}, {%8,%9}, {%0,%1,%2,%3};"
        : "+f"(d[0]), "+f"(d[1]), "+f"(d[2]), "+f"(d[3])
        : "r"(a[0]), "r"(a[1]), "r"(a[2]), "r"(a[3]), "r"(b[0]), "r"(b[1]));
}

// fp32 pair -> packed bf16x2 hi + bf16x2 lo  (a in low half) — 6 instrs
__device__ __forceinline__ void split2(float a, float b, uint32_t& hi, uint32_t& lo) {
    asm("cvt.rn.bf16x2.f32 %0, %1, %2;" : "=r"(hi) : "f"(b), "f"(a));
    const float ha = __uint_as_float(hi << 16);
    const float hb = __uint_as_float(hi & 0xffff0000u);
    const float la = a - ha, lb = b - hb;
    asm("cvt.rn.bf16x2.f32 %0, %1, %2;" : "=r"(lo) : "f"(lb), "f"(la));
}

// ---------------------------------------------------------------------------
// fp32 -> bf16 hi/lo splits (merged launches; z selects tensor)
// ---------------------------------------------------------------------------
__global__ void __launch_bounds__(256) split_in(
    const float4* __restrict__ q, const float4* __restrict__ k,
    const float4* __restrict__ v)
{
    const int z = blockIdx.z;
    const size_t XN4 = (size_t)ROWS * DM / 4;
    const float4* src = (z == 0) ? q : (z == 1) ? k : v;
    uint32_t* hp = (uint32_t*)(g_xh[z]);
    uint32_t* lp = (uint32_t*)(g_xl[z]);
    const size_t i = blockIdx.x * 256 + threadIdx.x;
    if (i >= XN4) return;
    float4 vv = src[i];
    uint32_t h0, l0, h1, l1;
    split2(vv.x, vv.y, h0, l0);
    split2(vv.z, vv.w, h1, l1);
    hp[2*i] = h0; hp[2*i+1] = h1;
    lp[2*i] = l0; lp[2*i+1] = l1;
}

__global__ void __launch_bounds__(256) split_w(
    const float4* __restrict__ wq, const float4* __restrict__ wk,
    const float4* __restrict__ wv, const float4* __restrict__ wo)
{
    const int z = blockIdx.z;
    const size_t WN4 = (size_t)DM * DM / 4;
    const float4* src = (z == 0) ? wq : (z == 1) ? wk : (z == 2) ? wv : wo;
    uint32_t* hp = (uint32_t*)(g_wh[z]);
    uint32_t* lp = (uint32_t*)(g_wl[z]);
    const size_t i = blockIdx.x * 256 + threadIdx.x;
    if (i >= WN4) return;
    float4 vv = src[i];
    uint32_t h0, l0, h1, l1;
    split2(vv.x, vv.y, h0, l0);
    split2(vv.z, vv.w, h1, l1);
    hp[2*i] = h0; hp[2*i+1] = h1;
    lp[2*i] = l0; lp[2*i+1] = l1;
}

// ---------------------------------------------------------------------------
// HMMA bf16x3 NT GEMM core, CTA 128x128, BK=32, 8 warps (2x4), warp 64x32.
// Double-buffered cp.async, ONE sync per stage.
// MODE 0: fp32 C row-major [ROWS, DM]
// MODE 2: bf16 hi/lo pair output in QKV scatter layout [(h*NB+n)][seq][HD]
// ---------------------------------------------------------------------------
#define GSTRIDE 40
#define ARR_BYTES (128 * GSTRIDE * 2)
#define STAGE_BYTES (4 * ARR_BYTES)
#define NSTAGE (DM / 32)

template<int MODE>
__device__ __forceinline__ void gemm_body(
    const __nv_bfloat16* __restrict__ Ah, const __nv_bfloat16* __restrict__ Al,
    const __nv_bfloat16* __restrict__ Bh, const __nv_bfloat16* __restrict__ Bl,
    const float* __restrict__ bias, float* __restrict__ C,
    __nv_bfloat16* __restrict__ Ch, __nv_bfloat16* __restrict__ Cl)
{
    extern __shared__ __align__(128) char smraw[];
    const uint32_t smem0 = smem_u32(smraw);

    const int tid = threadIdx.x;
    const int lane = tid & 31;
    const int wid = tid >> 5;
    const int wm = wid >> 2;
    const int wn = wid & 3;

    const int m0 = blockIdx.y << 7;
    const int n0 = blockIdx.x << 7;

    const __nv_bfloat16* gsrc[4] = {
        Ah + (size_t)m0 * DM, Al + (size_t)m0 * DM,
        Bh + (size_t)n0 * DM, Bl + (size_t)n0 * DM
    };

    const int r0c = tid >> 2, cc0 = tid & 3;
    const int r1c = r0c + 64;

    auto load_stage = [&](int s) {
        const int kk = s * 32;
        const uint32_t sb = smem0 + (s & 1) * STAGE_BYTES;
        #pragma unroll
        for (int a = 0; a < 4; a++) {
            const __nv_bfloat16* g = gsrc[a];
            const uint32_t ab = sb + a * ARR_BYTES;
            CP_ASYNC16(ab + r0c * (GSTRIDE*2) + cc0 * 16,
                       g + (size_t)r0c * DM + kk + cc0 * 8);
            CP_ASYNC16(ab + r1c * (GSTRIDE*2) + cc0 * 16,
                       g + (size_t)r1c * DM + kk + cc0 * 8);
        }
    };

    float acc[4][4][4];
    #pragma unroll
    for (int i = 0; i < 4; i++)
        #pragma unroll
        for (int j = 0; j < 4; j++)
            #pragma unroll
            for (int e = 0; e < 4; e++) acc[i][j][e] = 0.f;

    const int a_r = lane & 15, a_c = (lane >> 4) << 3;
    const int b_r = (lane & 7) + (((lane >> 3) & 2) << 2);
    const int b_c = ((lane >> 3) & 1) << 3;

    load_stage(0);
    CP_COMMIT();

    for (int s = 0; s < NSTAGE; s++) {
        CP_WAIT0();
        __syncthreads();                  // data landed + prev buffer free
        if (s + 1 < NSTAGE) { load_stage(s + 1); CP_COMMIT(); }

        const uint32_t sb = smem0 + (s & 1) * STAGE_BYTES;
        const uint32_t sAh = sb;
        const uint32_t sAl = sb + ARR_BYTES;
        const uint32_t sBh = sb + 2 * ARR_BYTES;
        const uint32_t sBl = sb + 3 * ARR_BYTES;

        #pragma unroll
        for (int k16 = 0; k16 < 2; k16++) {
            const int kc = k16 * 16;
            uint32_t bh[2][4], bl[2][4];
            #pragma unroll
            for (int np = 0; np < 2; np++) {
                const uint32_t off =
                    ((wn * 32 + np * 16 + b_r) * GSTRIDE + kc + b_c) * 2;
                ldm_x4(bh[np], sBh + off);
                ldm_x4(bl[np], sBl + off);
            }
            #pragma unroll
            for (int mt = 0; mt < 4; mt++) {
                uint32_t ah[4], al[4];
                const uint32_t off =
                    ((wm * 64 + mt * 16 + a_r) * GSTRIDE + kc + a_c) * 2;
                ldm_x4(ah, sAh + off);
                ldm_x4(al, sAl + off);
                #pragma unroll
                for (int nt = 0; nt < 4; nt++)
                    mma_bf16(acc[mt][nt], ah, &bh[nt >> 1][(nt & 1) * 2]);
                #pragma unroll
                for (int nt = 0; nt < 4; nt++)
                    mma_bf16(acc[mt][nt], ah, &bl[nt >> 1][(nt & 1) * 2]);
                #pragma unroll
                for (int nt = 0; nt < 4; nt++)
                    mma_bf16(acc[mt][nt], al, &bh[nt >> 1][(nt & 1) * 2]);
            }
        }
    }

    #pragma unroll
    for (int mt = 0; mt < 4; mt++) {
        #pragma unroll
        for (int nt = 0; nt < 4; nt++) {
            const int col = n0 + wn * 32 + nt * 8 + ((lane & 3) << 1);
            const float b0 = bias[col], b1 = bias[col + 1];
            #pragma unroll
            for (int half = 0; half < 2; half++) {
                const int row = m0 + wm * 64 + mt * 16 + (lane >> 2) + half * 8;
                const float vx = acc[mt][nt][half * 2 + 0] + b0;
                const float vy = acc[mt][nt][half * 2 + 1] + b1;
                if (MODE == 0) {
                    float2 v; v.x = vx; v.y = vy;
                    *(float2*)&C[(size_t)row * DM + col] = v;
                } else {
                    const int h = col >> 6, d = col & 63;
                    const int nb = row >> 11, kq = row & 2047;
                    const size_t idx = (((size_t)(h * NB + nb)) * SEQ + kq) * HD + d;
                    uint32_t hi, lo;
                    split2(vx, vy, hi, lo);
                    *(uint32_t*)&Ch[idx] = hi;
                    *(uint32_t*)&Cl[idx] = lo;
                }
            }
        }
    }
}

// merged QKV projection: gridDim.z = 3 selects q/k/v
__global__ void __launch_bounds__(256) gemm_qkv(
    const __nv_bfloat16* __restrict__ xh, const __nv_bfloat16* __restrict__ xl,
    const __nv_bfloat16* __restrict__ wh, const __nv_bfloat16* __restrict__ wl,
    const float* __restrict__ bq, const float* __restrict__ bk,
    const float* __restrict__ bv)
{
    const int z = blockIdx.z;
    const size_t XN = (size_t)ROWS * DM, WN = (size_t)DM * DM;
    const float* bias = (z == 0) ? bq : (z == 1) ? bk : bv;
    __nv_bfloat16* Ch = (z == 0) ? g_qh : (z == 1) ? g_kh : g_vh;
    __nv_bfloat16* Cl = (z == 0) ? g_ql : (z == 1) ? g_kl : g_vl;
    gemm_body<2>(xh + z * XN, xl + z * XN, wh + z * WN, wl + z * WN,
                 bias, nullptr, Ch, Cl);
}

__global__ void __launch_bounds__(256) gemm_out(
    const __nv_bfloat16* __restrict__ Ah, const __nv_bfloat16* __restrict__ Al,
    const __nv_bfloat16* __restrict__ Bh, const __nv_bfloat16* __restrict__ Bl,
    const float* __restrict__ bias, float* __restrict__ C)
{
    gemm_body<0>(Ah, Al, Bh, Bl, bias, C, nullptr, nullptr);
}

// ---------------------------------------------------------------------------
// FA2-style HMMA attention. CTA: 128 q-rows x (h,n). 8 warps x m16.
// K-tile 64, double-buffered cp.async, ONE sync per kv-tile.
// ---------------------------------------------------------------------------
#define ASTRIDE 72
#define AARR    (64 * ASTRIDE * 2)      // 9216 B
#define ASTAGE  (4 * AARR)              // 36864 B

__global__ void __launch_bounds__(256) attn_mma(
    const __nv_bfloat16* __restrict__ Qh_, const __nv_bfloat16* __restrict__ Ql_,
    const __nv_bfloat16* __restrict__ Kh_, const __nv_bfloat16* __restrict__ Kl_,
    const __nv_bfloat16* __restrict__ Vh_, const __nv_bfloat16* __restrict__ Vl_,
    __nv_bfloat16* __restrict__ Yh, __nv_bfloat16* __restrict__ Yl)
{
    extern __shared__ __align__(128) char smraw[];
    const uint32_t s0 = smem_u32(smraw);

    const int tid = threadIdx.x;
    const int lane = tid & 31;
    const int wid = tid >> 5;
    const int hn = blockIdx.y;
    const int h = hn >> 1, n = hn & 1;
    const int q0 = blockIdx.x << 7;
    const size_t hoff = (size_t)hn * SEQ * HD;

    const int a_r = lane & 15, a_c = (lane >> 4) << 3;
    const int b_r = (lane & 7) + (((lane >> 3) & 2) << 2);
    const int b_c = ((lane >> 3) & 1) << 3;

    // ---- stage Q into smem (reusing stage-0 region), ldmatrix to regs ----
    {
        const __nv_bfloat16* Qhg = Qh_ + hoff + (size_t)q0 * HD;
        const __nv_bfloat16* Qlg = Ql_ + hoff + (size_t)q0 * HD;
        #pragma unroll
        for (int c = 0; c < 4; c++) {
            const int ch = tid + c * 256;            // 0..1023
            const int row = ch >> 3, c16 = ch & 7;
            CP_ASYNC16(s0 + row * 144 + c16 * 16, Qhg + row * 64 + c16 * 8);
            CP_ASYNC16(s0 + 18432 + row * 144 + c16 * 16, Qlg + row * 64 + c16 * 8);
        }
        CP_COMMIT(); CP_WAIT0();
        __syncthreads();
    }
    uint32_t qfh[4][4], qfl[4][4];
    #pragma unroll
    for (int t4 = 0; t4 < 4; t4++) {
        const uint32_t off = ((wid * 16 + a_r) * ASTRIDE + 16 * t4 + a_c) * 2;
        ldm_x4(qfh[t4], s0 + off);
        ldm_x4(qfl[t4], s0 + 18432 + off);
    }
    __syncthreads();   // all warps done reading Q region

    const __nv_bfloat16* Khg = Kh_ + hoff;
    const __nv_bfloat16* Klg = Kl_ + hoff;
    const __nv_bfloat16* Vhg = Vh_ + hoff;
    const __nv_bfloat16* Vlg = Vl_ + hoff;

    auto load_stage = [&](int s) {
        const int kv0 = s << 6;
        const uint32_t sb = s0 + (s & 1) * ASTAGE;
        const __nv_bfloat16* gs[4] = { Khg, Klg, Vhg, Vlg };
        #pragma unroll
        for (int a = 0; a < 4; a++) {
            #pragma unroll
            for (int c = 0; c < 2; c++) {
                const int ch = tid + c * 256;        // 0..511
                const int row = ch >> 3, c16 = ch & 7;
                CP_ASYNC16(sb + a * AARR + row * 144 + c16 * 16,
                           gs[a] + (size_t)(kv0 + row) * 64 + c16 * 8);
            }
        }
    };

    float m0r = -1e30f, m1r = -1e30f, l0 = 0.f, l1 = 0.f;
    float O[8][4];
    #pragma unroll
    for (int j = 0; j < 8; j++)
        #pragma unroll
        for (int e = 0; e < 4; e++) O[j][e] = 0.f;

    load_stage(0); CP_COMMIT();

    for (int t = 0; t < SEQ / 64; t++) {
        CP_WAIT0();
        __syncthreads();                  // data landed + prev buffer free
        if (t + 1 < SEQ / 64) { load_stage(t + 1); CP_COMMIT(); }

        const uint32_t sb = s0 + (t & 1) * ASTAGE;

        // ---- S = Q K^T (bf16x3) ----
        float S[8][4];
        #pragma unroll
        for (int j = 0; j < 8; j++)
            #pragma unroll
            for (int e = 0; e < 4; e++) S[j][e] = 0.f;

        #pragma unroll
        for (int t4 = 0; t4 < 4; t4++) {
            #pragma unroll
            for (int jp = 0; jp < 4; jp++) {
                uint32_t bh[4], bl[4];
                const uint32_t off = ((16 * jp + b_r) * ASTRIDE + 16 * t4 + b_c) * 2;
                ldm_x4(bh, sb + off);
                ldm_x4(bl, sb + AARR + off);
                mma_bf16(S[2*jp],   qfh[t4], &bh[0]);
                mma_bf16(S[2*jp+1], qfh[t4], &bh[2]);
                mma_bf16(S[2*jp],   qfh[t4], &bl[0]);
                mma_bf16(S[2*jp+1], qfh[t4], &bl[2]);
                mma_bf16(S[2*jp],   qfl[t4], &bh[0]);
                mma_bf16(S[2*jp+1], qfl[t4], &bh[2]);
            }
        }

        // ---- online softmax ----
        float corr0, corr1;
        {
            float tm = S[0][0];
            #pragma unroll
            for (int j = 0; j < 8; j++) tm = fmaxf(tm, fmaxf(S[j][0], S[j][1]));
            tm = fmaxf(tm, __shfl_xor_sync(0xffffffffu, tm, 1));
            tm = fmaxf(tm, __shfl_xor_sync(0xffffffffu, tm, 2));
            const float mnew = fmaxf(m0r, tm);
            corr0 = __expf((m0r - mnew) * SCALE);
            float rs = 0.f;
            #pragma unroll
            for (int j = 0; j < 8; j++) {
                S[j][0] = __expf((S[j][0] - mnew) * SCALE);
                S[j][1] = __expf((S[j][1] - mnew) * SCALE);
                rs += S[j][0] + S[j][1];
            }
            rs += __shfl_xor_sync(0xffffffffu, rs, 1);
            rs += __shfl_xor_sync(0xffffffffu, rs, 2);
            l0 = l0 * corr0 + rs;
            m0r = mnew;
        }
        {
            float tm = S[0][2];
            #pragma unroll
            for (int j = 0; j < 8; j++) tm = fmaxf(tm, fmaxf(S[j][2], S[j][3]));
            tm = fmaxf(tm, __shfl_xor_sync(0xffffffffu, tm, 1));
            tm = fmaxf(tm, __shfl_xor_sync(0xffffffffu, tm, 2));
            const float mnew = fmaxf(m1r, tm);
            corr1 = __expf((m1r - mnew) * SCALE);
            float rs = 0.f;
            #pragma unroll
            for (int j = 0; j < 8; j++) {
                S[j][2] = __expf((S[j][2] - mnew) * SCALE);
                S[j][3] = __expf((S[j][3] - mnew) * SCALE);
                rs += S[j][2] + S[j][3];
            }
            rs += __shfl_xor_sync(0xffffffffu, rs, 1);
            rs += __shfl_xor_sync(0xffffffffu, rs, 2);
            l1 = l1 * corr1 + rs;
            m1r = mnew;
        }

        // ---- pack P to bf16 hi/lo A-fragments ----
        uint32_t pah[4][4], pal[4][4];
        #pragma unroll
        for (int t4 = 0; t4 < 4; t4++) {
            split2(S[2*t4][0],   S[2*t4][1],   pah[t4][0], pal[t4][0]);
            split2(S[2*t4][2],   S[2*t4][3],   pah[t4][1], pal[t4][1]);
            split2(S[2*t4+1][0], S[2*t4+1][1], pah[t4][2], pal[t4][2]);
            split2(S[2*t4+1][2], S[2*t4+1][3], pah[t4][3], pal[t4][3]);
        }

        // ---- rescale O ----
        #pragma unroll
        for (int j = 0; j < 8; j++) {
            O[j][0] *= corr0; O[j][1] *= corr0;
            O[j][2] *= corr1; O[j][3] *= corr1;
        }

        // ---- O += P V (bf16x3, V via ldmatrix.trans) ----
        #pragma unroll
        for (int t4 = 0; t4 < 4; t4++) {
            #pragma unroll
            for (int jp = 0; jp < 4; jp++) {
                uint32_t vh[4], vl[4];
                const uint32_t off =
                    ((16 * t4 + (lane & 15)) * ASTRIDE + 16 * jp + a_c) * 2;
                ldm_x4_t(vh, sb + 2 * AARR + off);
                ldm_x4_t(vl, sb + 3 * AARR + off);
                mma_bf16(O[2*jp],   pah[t4], &vh[0]);
                mma_bf16(O[2*jp+1], pah[t4], &vh[2]);
                mma_bf16(O[2*jp],   pah[t4], &vl[0]);
                mma_bf16(O[2*jp+1], pah[t4], &vl[2]);
                mma_bf16(O[2*jp],   pal[t4], &vh[0]);
                mma_bf16(O[2*jp+1], pal[t4], &vh[2]);
            }
        }
    }

    // ---- epilogue: scale by 1/l, write bf16 hi/lo in [N, K, H*D] layout ----
    const float inv0 = 1.f / l0, inv1 = 1.f / l1;
    #pragma unroll
    for (int j = 0; j < 8; j++) {
        const int col = h * 64 + 8 * j + ((lane & 3) << 1);
        #pragma unroll
        for (int half = 0; half < 2; half++) {
            const int row = q0 + wid * 16 + (lane >> 2) + half * 8;
            const float inv = half ? inv1 : inv0;
            const float y0 = O[j][half * 2 + 0] * inv;
            const float y1 = O[j][half * 2 + 1] * inv;
            const size_t idx = ((size_t)(n * SEQ) + row) * DM + col;
            uint32_t hi, lo;
            split2(y0, y1, hi, lo);
            *(uint32_t*)&Yh[idx] = hi;
            *(uint32_t*)&Yl[idx] = lo;
        }
    }
}

// ---------------------------------------------------------------------------
extern "C" void kernel_launch(void* const* d_in, const int* in_sizes, int n_in,
                              void* d_out, int out_size)
{
    const float* q  = (const float*)d_in[0];
    const float* k  = (const float*)d_in[1];
    const float* v  = (const float*)d_in[2];
    const float* Wq = (const float*)d_in[3];
    const float* bq = (const float*)d_in[4];
    const float* Wk = (const float*)d_in[5];
    const float* bk = (const float*)d_in[6];
    const float* Wv = (const float*)d_in[7];
    const float* bv = (const float*)d_in[8];
    const float* Wo = (const float*)d_in[9];
    const float* bo = (const float*)d_in[10];
    float* out = (float*)d_out;

    __nv_bfloat16 *xh, *xl, *wh, *wl, *yh, *yl, *qh, *ql, *kh, *kl, *vh, *vl;
    cudaGetSymbolAddress((void**)&xh, g_xh);
    cudaGetSymbolAddress((void**)&xl, g_xl);
    cudaGetSymbolAddress((void**)&wh, g_wh);
    cudaGetSymbolAddress((void**)&wl, g_wl);
    cudaGetSymbolAddress((void**)&yh, g_yh);
    cudaGetSymbolAddress((void**)&yl, g_yl);
    cudaGetSymbolAddress((void**)&qh, g_qh);
    cudaGetSymbolAddress((void**)&ql, g_ql);
    cudaGetSymbolAddress((void**)&kh, g_kh);
    cudaGetSymbolAddress((void**)&kl, g_kl);
    cudaGetSymbolAddress((void**)&vh, g_vh);
    cudaGetSymbolAddress((void**)&vl, g_vl);

    const size_t XN = (size_t)ROWS * DM;
    const size_t WN = (size_t)DM * DM;

    { const dim3 gi((unsigned)(XN/4/256), 1, 3);
      split_in<<<gi, 256>>>((const float4*)q, (const float4*)k, (const float4*)v); }
    { const dim3 gw((unsigned)(WN/4/256), 1, 4);
      split_w<<<gw, 256>>>((const float4*)Wq, (const float4*)Wk,
                           (const float4*)Wv, (const float4*)Wo); }

    const int gsmem = 2 * STAGE_BYTES;
    cudaFuncSetAttribute((const void*)gemm_qkv,
                         cudaFuncAttributeMaxDynamicSharedMemorySize, gsmem);
    cudaFuncSetAttribute((const void*)gemm_out,
                         cudaFuncAttributeMaxDynamicSharedMemorySize, gsmem);
    const dim3 gq(DM/128, ROWS/128, 3);
    gemm_qkv<<<gq, 256, gsmem>>>(xh, xl, wh, wl, bq, bk, bv);

    const int asmem = 2 * ASTAGE;   // 73728
    cudaFuncSetAttribute((const void*)attn_mma,
                         cudaFuncAttributeMaxDynamicSharedMemorySize, asmem);
    const dim3 ga(SEQ/128, NH*NB);  // (16, 32)
    attn_mma<<<ga, 256, asmem>>>(qh, ql, kh, kl, vh, vl, yh, yl);

    const dim3 gg(DM/128, ROWS/128);
    gemm_out<<<gg, 256, gsmem>>>(yh, yl, wh + 3*WN, wl + 3*WN, bo, out);
}

// round 8
// speedup vs baseline: 3.3013x; 1.0842x over previous
#include <cuda_runtime.h>
#include <cuda_bf16.h>
#include <cstdint>

#define NB   2
#define SEQ  2048
#define DM   1024
#define NH   16
#define HD   64
#define ROWS (NB*SEQ)          // 4096
#define SCALE 0.125f           // 1/sqrt(64)

// ---------------------------------------------------------------------------
// Scratch (allocation-free: __device__ globals)
// ---------------------------------------------------------------------------
#define PROJN ((size_t)NH*NB*SEQ*HD)     // 4M elems
__device__ __align__(256) __nv_bfloat16 g_qh[PROJN], g_ql[PROJN];
__device__ __align__(256) __nv_bfloat16 g_kh[PROJN], g_kl[PROJN];
__device__ __align__(256) __nv_bfloat16 g_vh[PROJN], g_vl[PROJN];
__device__ __align__(256) __nv_bfloat16 g_xh[3][(size_t)ROWS*DM];
__device__ __align__(256) __nv_bfloat16 g_xl[3][(size_t)ROWS*DM];
__device__ __align__(256) __nv_bfloat16 g_wh[4][(size_t)DM*DM];
__device__ __align__(256) __nv_bfloat16 g_wl[4][(size_t)DM*DM];
__device__ __align__(256) __nv_bfloat16 g_yh[(size_t)ROWS*DM];
__device__ __align__(256) __nv_bfloat16 g_yl[(size_t)ROWS*DM];

// ---------------------------------------------------------------------------
// PTX helpers (baseline sm_80+ features: mma.sync / ldmatrix / cp.async)
// ---------------------------------------------------------------------------
__device__ __forceinline__ uint32_t smem_u32(const void* p) {
    uint32_t a;
    asm("{ .reg .u64 t; cvta.to.shared.u64 t, %1; cvt.u32.u64 %0, t; }"
        : "=r"(a) : "l"(p));
    return a;
}

#define CP_ASYNC16(dst, src) \
    asm volatile("cp.async.cg.shared.global [%0], [%1], 16;" :: "r"(dst), "l"(src))
#define CP_COMMIT() asm volatile("cp.async.commit_group;" ::: "memory")
#define CP_WAIT0()  asm volatile("cp.async.wait_group 0;" ::: "memory")

__device__ __forceinline__ void ldm_x4(uint32_t* r, uint32_t addr) {
    asm volatile("ldmatrix.sync.aligned.m8n8.x4.shared.b16 {%0,%1,%2,%3}, [%4];"
                 : "=r"(r[0]), "=r"(r[1]), "=r"(r[2]), "=r"(r[3]) : "r"(addr));
}
__device__ __forceinline__ void ldm_x4_t(uint32_t* r, uint32_t addr) {
    asm volatile("ldmatrix.sync.aligned.m8n8.x4.trans.shared.b16 {%0,%1,%2,%3}, [%4];"
                 : "=r"(r[0]), "=r"(r[1]), "=r"(r[2]), "=r"(r[3]) : "r"(addr));
}

__device__ __forceinline__ void mma_bf16(float* d, const uint32_t* a, const uint32_t* b) {
    asm volatile(
        "mma.sync.aligned.m16n8k16.row.col.f32.bf16.bf16.f32 "
        "{%0,%1,%2,%3}, {%4,%5,%6,%7}, {%8,%9}, {%0,%1,%2,%3};"
        : "+f"(d[0]), "+f"(d[1]), "+f"(d[2]), "+f"(d[3])
        : "r"(a[0]), "r"(a[1]), "r"(a[2]), "r"(a[3]), "r"(b[0]), "r"(b[1]));
}

// fp32 pair -> packed bf16x2 hi + bf16x2 lo  (a in low half)
__device__ __forceinline__ void split2(float a, float b, uint32_t& hi, uint32_t& lo) {
    asm("cvt.rn.bf16x2.f32 %0, %1, %2;" : "=r"(hi) : "f"(b), "f"(a));
    const float ha = __uint_as_float(hi << 16);
    const float hb = __uint_as_float(hi & 0xffff0000u);
    const float la = a - ha, lb = b - hb;
    asm("cvt.rn.bf16x2.f32 %0, %1, %2;" : "=r"(lo) : "f"(lb), "f"(la));
}

// ---------------------------------------------------------------------------
// fp32 -> bf16 hi/lo splits (merged launches; z selects tensor)
// ---------------------------------------------------------------------------
__global__ void __launch_bounds__(256) split_in(
    const float4* __restrict__ q, const float4* __restrict__ k,
    const float4* __restrict__ v)
{
    const int z = blockIdx.z;
    const size_t XN4 = (size_t)ROWS * DM / 4;
    const float4* src = (z == 0) ? q : (z == 1) ? k : v;
    uint32_t* hp = (uint32_t*)(g_xh[z]);
    uint32_t* lp = (uint32_t*)(g_xl[z]);
    const size_t i = blockIdx.x * 256 + threadIdx.x;
    if (i >= XN4) return;
    float4 vv = src[i];
    uint32_t h0, l0, h1, l1;
    split2(vv.x, vv.y, h0, l0);
    split2(vv.z, vv.w, h1, l1);
    hp[2*i] = h0; hp[2*i+1] = h1;
    lp[2*i] = l0; lp[2*i+1] = l1;
}

__global__ void __launch_bounds__(256) split_w(
    const float4* __restrict__ wq, const float4* __restrict__ wk,
    const float4* __restrict__ wv, const float4* __restrict__ wo)
{
    const int z = blockIdx.z;
    const size_t WN4 = (size_t)DM * DM / 4;
    const float4* src = (z == 0) ? wq : (z == 1) ? wk : (z == 2) ? wv : wo;
    uint32_t* hp = (uint32_t*)(g_wh[z]);
    uint32_t* lp = (uint32_t*)(g_wl[z]);
    const size_t i = blockIdx.x * 256 + threadIdx.x;
    if (i >= WN4) return;
    float4 vv = src[i];
    uint32_t h0, l0, h1, l1;
    split2(vv.x, vv.y, h0, l0);
    split2(vv.z, vv.w, h1, l1);
    hp[2*i] = h0; hp[2*i+1] = h1;
    lp[2*i] = l0; lp[2*i+1] = l1;
}

// ---------------------------------------------------------------------------
// HMMA bf16x3 NT GEMM core, CTA 128x128, BK=32, 8 warps (2x4), warp 64x32.
// Double-buffered cp.async, ONE sync per stage, 2 CTAs/SM.
// ---------------------------------------------------------------------------
#define GSTRIDE 40
#define ARR_BYTES (128 * GSTRIDE * 2)
#define STAGE_BYTES (4 * ARR_BYTES)
#define NSTAGE (DM / 32)

template<int MODE>
__device__ __forceinline__ void gemm_body(
    const __nv_bfloat16* __restrict__ Ah, const __nv_bfloat16* __restrict__ Al,
    const __nv_bfloat16* __restrict__ Bh, const __nv_bfloat16* __restrict__ Bl,
    const float* __restrict__ bias, float* __restrict__ C,
    __nv_bfloat16* __restrict__ Ch, __nv_bfloat16* __restrict__ Cl)
{
    extern __shared__ __align__(128) char smraw[];
    const uint32_t smem0 = smem_u32(smraw);

    const int tid = threadIdx.x;
    const int lane = tid & 31;
    const int wid = tid >> 5;
    const int wm = wid >> 2;
    const int wn = wid & 3;

    const int m0 = blockIdx.y << 7;
    const int n0 = blockIdx.x << 7;

    const __nv_bfloat16* gsrc[4] = {
        Ah + (size_t)m0 * DM, Al + (size_t)m0 * DM,
        Bh + (size_t)n0 * DM, Bl + (size_t)n0 * DM
    };

    const int r0c = tid >> 2, cc0 = tid & 3;
    const int r1c = r0c + 64;

    auto load_stage = [&](int s) {
        const int kk = s * 32;
        const uint32_t sb = smem0 + (s & 1) * STAGE_BYTES;
        #pragma unroll
        for (int a = 0; a < 4; a++) {
            const __nv_bfloat16* g = gsrc[a];
            const uint32_t ab = sb + a * ARR_BYTES;
            CP_ASYNC16(ab + r0c * (GSTRIDE*2) + cc0 * 16,
                       g + (size_t)r0c * DM + kk + cc0 * 8);
            CP_ASYNC16(ab + r1c * (GSTRIDE*2) + cc0 * 16,
                       g + (size_t)r1c * DM + kk + cc0 * 8);
        }
    };

    float acc[4][4][4];
    #pragma unroll
    for (int i = 0; i < 4; i++)
        #pragma unroll
        for (int j = 0; j < 4; j++)
            #pragma unroll
            for (int e = 0; e < 4; e++) acc[i][j][e] = 0.f;

    const int a_r = lane & 15, a_c = (lane >> 4) << 3;
    const int b_r = (lane & 7) + (((lane >> 3) & 2) << 2);
    const int b_c = ((lane >> 3) & 1) << 3;

    load_stage(0);
    CP_COMMIT();

    for (int s = 0; s < NSTAGE; s++) {
        CP_WAIT0();
        __syncthreads();
        if (s + 1 < NSTAGE) { load_stage(s + 1); CP_COMMIT(); }

        const uint32_t sb = smem0 + (s & 1) * STAGE_BYTES;
        const uint32_t sAh = sb;
        const uint32_t sAl = sb + ARR_BYTES;
        const uint32_t sBh = sb + 2 * ARR_BYTES;
        const uint32_t sBl = sb + 3 * ARR_BYTES;

        #pragma unroll
        for (int k16 = 0; k16 < 2; k16++) {
            const int kc = k16 * 16;
            uint32_t bh[2][4], bl[2][4];
            #pragma unroll
            for (int np = 0; np < 2; np++) {
                const uint32_t off =
                    ((wn * 32 + np * 16 + b_r) * GSTRIDE + kc + b_c) * 2;
                ldm_x4(bh[np], sBh + off);
                ldm_x4(bl[np], sBl + off);
            }
            #pragma unroll
            for (int mt = 0; mt < 4; mt++) {
                uint32_t ah[4], al[4];
                const uint32_t off =
                    ((wm * 64 + mt * 16 + a_r) * GSTRIDE + kc + a_c) * 2;
                ldm_x4(ah, sAh + off);
                ldm_x4(al, sAl + off);
                #pragma unroll
                for (int nt = 0; nt < 4; nt++)
                    mma_bf16(acc[mt][nt], ah, &bh[nt >> 1][(nt & 1) * 2]);
                #pragma unroll
                for (int nt = 0; nt < 4; nt++)
                    mma_bf16(acc[mt][nt], ah, &bl[nt >> 1][(nt & 1) * 2]);
                #pragma unroll
                for (int nt = 0; nt < 4; nt++)
                    mma_bf16(acc[mt][nt], al, &bh[nt >> 1][(nt & 1) * 2]);
            }
        }
    }

    #pragma unroll
    for (int mt = 0; mt < 4; mt++) {
        #pragma unroll
        for (int nt = 0; nt < 4; nt++) {
            const int col = n0 + wn * 32 + nt * 8 + ((lane & 3) << 1);
            const float b0 = bias[col], b1 = bias[col + 1];
            #pragma unroll
            for (int half = 0; half < 2; half++) {
                const int row = m0 + wm * 64 + mt * 16 + (lane >> 2) + half * 8;
                const float vx = acc[mt][nt][half * 2 + 0] + b0;
                const float vy = acc[mt][nt][half * 2 + 1] + b1;
                if (MODE == 0) {
                    float2 v; v.x = vx; v.y = vy;
                    *(float2*)&C[(size_t)row * DM + col] = v;
                } else {
                    const int h = col >> 6, d = col & 63;
                    const int nb = row >> 11, kq = row & 2047;
                    const size_t idx = (((size_t)(h * NB + nb)) * SEQ + kq) * HD + d;
                    uint32_t hi, lo;
                    split2(vx, vy, hi, lo);
                    *(uint32_t*)&Ch[idx] = hi;
                    *(uint32_t*)&Cl[idx] = lo;
                }
            }
        }
    }
}

__global__ void __launch_bounds__(256, 2) gemm_qkv(
    const __nv_bfloat16* __restrict__ xh, const __nv_bfloat16* __restrict__ xl,
    const __nv_bfloat16* __restrict__ wh, const __nv_bfloat16* __restrict__ wl,
    const float* __restrict__ bq, const float* __restrict__ bk,
    const float* __restrict__ bv)
{
    const int z = blockIdx.z;
    const size_t XN = (size_t)ROWS * DM, WN = (size_t)DM * DM;
    const float* bias = (z == 0) ? bq : (z == 1) ? bk : bv;
    __nv_bfloat16* Ch = (z == 0) ? g_qh : (z == 1) ? g_kh : g_vh;
    __nv_bfloat16* Cl = (z == 0) ? g_ql : (z == 1) ? g_kl : g_vl;
    gemm_body<2>(xh + z * XN, xl + z * XN, wh + z * WN, wl + z * WN,
                 bias, nullptr, Ch, Cl);
}

__global__ void __launch_bounds__(256, 2) gemm_out(
    const __nv_bfloat16* __restrict__ Ah, const __nv_bfloat16* __restrict__ Al,
    const __nv_bfloat16* __restrict__ Bh, const __nv_bfloat16* __restrict__ Bl,
    const float* __restrict__ bias, float* __restrict__ C)
{
    gemm_body<0>(Ah, Al, Bh, Bl, bias, C, nullptr, nullptr);
}

// ---------------------------------------------------------------------------
// FA2-style HMMA attention, 2 CTAs/SM, FULL 3-term PV (P-lo restored: the
// 2-term variant measured rel_err 1.4e-3 > 1e-3 threshold).
// CTA: 128 q-rows x (h,n). 8 warps x m16. K-tile 64, double-buffered cp.async.
// smem: [Qh 18432][Ql 18432][stage0 36864][stage1 36864] = 110592 B.
// Q-hi frags in regs; Q-lo frags reloaded per tile (regs ~121 < 128).
// ---------------------------------------------------------------------------
#define ASTRIDE 72
#define AARR    (64 * ASTRIDE * 2)          // 9216 B
#define ASTAGE  (4 * AARR)                  // 36864 B
#define QONE    (128 * ASTRIDE * 2)         // 18432 B (one Q array)
#define QARR    (2 * QONE)                  // 36864 B (Qh + Ql)

__global__ void __launch_bounds__(256, 2) attn_mma(
    const __nv_bfloat16* __restrict__ Qh_, const __nv_bfloat16* __restrict__ Ql_,
    const __nv_bfloat16* __restrict__ Kh_, const __nv_bfloat16* __restrict__ Kl_,
    const __nv_bfloat16* __restrict__ Vh_, const __nv_bfloat16* __restrict__ Vl_,
    __nv_bfloat16* __restrict__ Yh, __nv_bfloat16* __restrict__ Yl)
{
    extern __shared__ __align__(128) char smraw[];
    const uint32_t s0 = smem_u32(smraw);
    const uint32_t stg = s0 + QARR;          // stage base (after Qh AND Ql)

    const int tid = threadIdx.x;
    const int lane = tid & 31;
    const int wid = tid >> 5;
    const int hn = blockIdx.y;
    const int h = hn >> 1, n = hn & 1;
    const int q0 = blockIdx.x << 7;
    const size_t hoff = (size_t)hn * SEQ * HD;

    const int a_r = lane & 15, a_c = (lane >> 4) << 3;
    const int b_r = (lane & 7) + (((lane >> 3) & 2) << 2);
    const int b_c = ((lane >> 3) & 1) << 3;

    // ---- stage Q into dedicated smem region (stays resident) ----
    {
        const __nv_bfloat16* Qhg = Qh_ + hoff + (size_t)q0 * HD;
        const __nv_bfloat16* Qlg = Ql_ + hoff + (size_t)q0 * HD;
        #pragma unroll
        for (int c = 0; c < 4; c++) {
            const int ch = tid + c * 256;            // 0..1023
            const int row = ch >> 3, c16 = ch & 7;
            CP_ASYNC16(s0 + row * 144 + c16 * 16, Qhg + row * 64 + c16 * 8);
            CP_ASYNC16(s0 + QONE + row * 144 + c16 * 16, Qlg + row * 64 + c16 * 8);
        }
        CP_COMMIT();
    }

    const __nv_bfloat16* Khg = Kh_ + hoff;
    const __nv_bfloat16* Klg = Kl_ + hoff;
    const __nv_bfloat16* Vhg = Vh_ + hoff;
    const __nv_bfloat16* Vlg = Vl_ + hoff;

    auto load_stage = [&](int s) {
        const int kv0 = s << 6;
        const uint32_t sb = stg + (s & 1) * ASTAGE;
        const __nv_bfloat16* gs[4] = { Khg, Klg, Vhg, Vlg };
        #pragma unroll
        for (int a = 0; a < 4; a++) {
            #pragma unroll
            for (int c = 0; c < 2; c++) {
                const int ch = tid + c * 256;        // 0..511
                const int row = ch >> 3, c16 = ch & 7;
                CP_ASYNC16(sb + a * AARR + row * 144 + c16 * 16,
                           gs[a] + (size_t)(kv0 + row) * 64 + c16 * 8);
            }
        }
    };

    load_stage(0); CP_COMMIT();

    // Q-hi fragments resident in registers; Q-lo reloaded per tile.
    CP_WAIT0();            // Q + stage 0 landed
    __syncthreads();
    uint32_t qfh[4][4];
    #pragma unroll
    for (int t4 = 0; t4 < 4; t4++) {
        const uint32_t off = ((wid * 16 + a_r) * ASTRIDE + 16 * t4 + a_c) * 2;
        ldm_x4(qfh[t4], s0 + off);
    }

    float m0r = -1e30f, m1r = -1e30f, l0 = 0.f, l1 = 0.f;
    float O[8][4];
    #pragma unroll
    for (int j = 0; j < 8; j++)
        #pragma unroll
        for (int e = 0; e < 4; e++) O[j][e] = 0.f;

    for (int t = 0; t < SEQ / 64; t++) {
        if (t > 0) { CP_WAIT0(); __syncthreads(); }
        if (t + 1 < SEQ / 64) { load_stage(t + 1); CP_COMMIT(); }

        const uint32_t sb = stg + (t & 1) * ASTAGE;

        // ---- S = Q K^T (bf16x3; Q-lo frags reloaded from resident smem) ----
        float S[8][4];
        #pragma unroll
        for (int j = 0; j < 8; j++)
            #pragma unroll
            for (int e = 0; e < 4; e++) S[j][e] = 0.f;

        #pragma unroll
        for (int t4 = 0; t4 < 4; t4++) {
            uint32_t qfl[4];
            const uint32_t qoff = ((wid * 16 + a_r) * ASTRIDE + 16 * t4 + a_c) * 2;
            ldm_x4(qfl, s0 + QONE + qoff);
            #pragma unroll
            for (int jp = 0; jp < 4; jp++) {
                uint32_t bh[4], bl[4];
                const uint32_t off = ((16 * jp + b_r) * ASTRIDE + 16 * t4 + b_c) * 2;
                ldm_x4(bh, sb + off);
                ldm_x4(bl, sb + AARR + off);
                mma_bf16(S[2*jp],   qfh[t4], &bh[0]);
                mma_bf16(S[2*jp+1], qfh[t4], &bh[2]);
                mma_bf16(S[2*jp],   qfh[t4], &bl[0]);
                mma_bf16(S[2*jp+1], qfh[t4], &bl[2]);
                mma_bf16(S[2*jp],   qfl,     &bh[0]);
                mma_bf16(S[2*jp+1], qfl,     &bh[2]);
            }
        }

        // ---- online softmax ----
        float corr0, corr1;
        {
            float tm = S[0][0];
            #pragma unroll
            for (int j = 0; j < 8; j++) tm = fmaxf(tm, fmaxf(S[j][0], S[j][1]));
            tm = fmaxf(tm, __shfl_xor_sync(0xffffffffu, tm, 1));
            tm = fmaxf(tm, __shfl_xor_sync(0xffffffffu, tm, 2));
            const float mnew = fmaxf(m0r, tm);
            corr0 = __expf((m0r - mnew) * SCALE);
            float rs = 0.f;
            #pragma unroll
            for (int j = 0; j < 8; j++) {
                S[j][0] = __expf((S[j][0] - mnew) * SCALE);
                S[j][1] = __expf((S[j][1] - mnew) * SCALE);
                rs += S[j][0] + S[j][1];
            }
            rs += __shfl_xor_sync(0xffffffffu, rs, 1);
            rs += __shfl_xor_sync(0xffffffffu, rs, 2);
            l0 = l0 * corr0 + rs;
            m0r = mnew;
        }
        {
            float tm = S[0][2];
            #pragma unroll
            for (int j = 0; j < 8; j++) tm = fmaxf(tm, fmaxf(S[j][2], S[j][3]));
            tm = fmaxf(tm, __shfl_xor_sync(0xffffffffu, tm, 1));
            tm = fmaxf(tm, __shfl_xor_sync(0xffffffffu, tm, 2));
            const float mnew = fmaxf(m1r, tm);
            corr1 = __expf((m1r - mnew) * SCALE);
            float rs = 0.f;
            #pragma unroll
            for (int j = 0; j < 8; j++) {
                S[j][2] = __expf((S[j][2] - mnew) * SCALE);
                S[j][3] = __expf((S[j][3] - mnew) * SCALE);
                rs += S[j][2] + S[j][3];
            }
            rs += __shfl_xor_sync(0xffffffffu, rs, 1);
            rs += __shfl_xor_sync(0xffffffffu, rs, 2);
            l1 = l1 * corr1 + rs;
            m1r = mnew;
        }

        // ---- pack P to bf16 hi/lo A-fragments ----
        uint32_t pah[4][4], pal[4][4];
        #pragma unroll
        for (int t4 = 0; t4 < 4; t4++) {
            split2(S[2*t4][0],   S[2*t4][1],   pah[t4][0], pal[t4][0]);
            split2(S[2*t4][2],   S[2*t4][3],   pah[t4][1], pal[t4][1]);
            split2(S[2*t4+1][0], S[2*t4+1][1], pah[t4][2], pal[t4][2]);
            split2(S[2*t4+1][2], S[2*t4+1][3], pah[t4][3], pal[t4][3]);
        }

        // ---- rescale O ----
        #pragma unroll
        for (int j = 0; j < 8; j++) {
            O[j][0] *= corr0; O[j][1] *= corr0;
            O[j][2] *= corr1; O[j][3] *= corr1;
        }

        // ---- O += P V (3-term: Ph*Vh + Ph*Vl + Pl*Vh) ----
        #pragma unroll
        for (int t4 = 0; t4 < 4; t4++) {
            #pragma unroll
            for (int jp = 0; jp < 4; jp++) {
                uint32_t vh[4], vl[4];
                const uint32_t off =
                    ((16 * t4 + (lane & 15)) * ASTRIDE + 16 * jp + a_c) * 2;
                ldm_x4_t(vh, sb + 2 * AARR + off);
                ldm_x4_t(vl, sb + 3 * AARR + off);
                mma_bf16(O[2*jp],   pah[t4], &vh[0]);
                mma_bf16(O[2*jp+1], pah[t4], &vh[2]);
                mma_bf16(O[2*jp],   pah[t4], &vl[0]);
                mma_bf16(O[2*jp+1], pah[t4], &vl[2]);
                mma_bf16(O[2*jp],   pal[t4], &vh[0]);
                mma_bf16(O[2*jp+1], pal[t4], &vh[2]);
            }
        }
    }

    // ---- epilogue: scale by 1/l, write bf16 hi/lo in [N, K, H*D] layout ----
    const float inv0 = 1.f / l0, inv1 = 1.f / l1;
    #pragma unroll
    for (int j = 0; j < 8; j++) {
        const int col = h * 64 + 8 * j + ((lane & 3) << 1);
        #pragma unroll
        for (int half = 0; half < 2; half++) {
            const int row = q0 + wid * 16 + (lane >> 2) + half * 8;
            const float inv = half ? inv1 : inv0;
            const float y0 = O[j][half * 2 + 0] * inv;
            const float y1 = O[j][half * 2 + 1] * inv;
            const size_t idx = ((size_t)(n * SEQ) + row) * DM + col;
            uint32_t hi, lo;
            split2(y0, y1, hi, lo);
            *(uint32_t*)&Yh[idx] = hi;
            *(uint32_t*)&Yl[idx] = lo;
        }
    }
}

// ---------------------------------------------------------------------------
extern "C" void kernel_launch(void* const* d_in, const int* in_sizes, int n_in,
                              void* d_out, int out_size)
{
    const float* q  = (const float*)d_in[0];
    const float* k  = (const float*)d_in[1];
    const float* v  = (const float*)d_in[2];
    const float* Wq = (const float*)d_in[3];
    const float* bq = (const float*)d_in[4];
    const float* Wk = (const float*)d_in[5];
    const float* bk = (const float*)d_in[6];
    const float* Wv = (const float*)d_in[7];
    const float* bv = (const float*)d_in[8];
    const float* Wo = (const float*)d_in[9];
    const float* bo = (const float*)d_in[10];
    float* out = (float*)d_out;

    __nv_bfloat16 *xh, *xl, *wh, *wl, *yh, *yl, *qh, *ql, *kh, *kl, *vh, *vl;
    cudaGetSymbolAddress((void**)&xh, g_xh);
    cudaGetSymbolAddress((void**)&xl, g_xl);
    cudaGetSymbolAddress((void**)&wh, g_wh);
    cudaGetSymbolAddress((void**)&wl, g_wl);
    cudaGetSymbolAddress((void**)&yh, g_yh);
    cudaGetSymbolAddress((void**)&yl, g_yl);
    cudaGetSymbolAddress((void**)&qh, g_qh);
    cudaGetSymbolAddress((void**)&ql, g_ql);
    cudaGetSymbolAddress((void**)&kh, g_kh);
    cudaGetSymbolAddress((void**)&kl, g_kl);
    cudaGetSymbolAddress((void**)&vh, g_vh);
    cudaGetSymbolAddress((void**)&vl, g_vl);

    const size_t XN = (size_t)ROWS * DM;
    const size_t WN = (size_t)DM * DM;

    { const dim3 gi((unsigned)(XN/4/256), 1, 3);
      split_in<<<gi, 256>>>((const float4*)q, (const float4*)k, (const float4*)v); }
    { const dim3 gw((unsigned)(WN/4/256), 1, 4);
      split_w<<<gw, 256>>>((const float4*)Wq, (const float4*)Wk,
                           (const float4*)Wv, (const float4*)Wo); }

    const int gsmem = 2 * STAGE_BYTES;
    cudaFuncSetAttribute((const void*)gemm_qkv,
                         cudaFuncAttributeMaxDynamicSharedMemorySize, gsmem);
    cudaFuncSetAttribute((const void*)gemm_out,
                         cudaFuncAttributeMaxDynamicSharedMemorySize, gsmem);
    const dim3 gq(DM/128, ROWS/128, 3);
    gemm_qkv<<<gq, 256, gsmem>>>(xh, xl, wh, wl, bq, bk, bv);

    const int asmem = QARR + 2 * ASTAGE;   // 36864 + 73728 = 110592
    cudaFuncSetAttribute((const void*)attn_mma,
                         cudaFuncAttributeMaxDynamicSharedMemorySize, asmem);
    const dim3 ga(SEQ/128, NH*NB);  // (16, 32)
    attn_mma<<<ga, 256, asmem>>>(qh, ql, kh, kl, vh, vl, yh, yl);

    const dim3 gg(DM/128, ROWS/128);
    gemm_out<<<gg, 256, gsmem>>>(yh, yl, wh + 3*WN, wl + 3*WN, bo, out);
}

// round 9
// speedup vs baseline: 3.3123x; 1.0033x over previous
#include <cuda_runtime.h>
#include <cuda_bf16.h>
#include <cstdint>

#define NB   2
#define SEQ  2048
#define DM   1024
#define NH   16
#define HD   64
#define ROWS (NB*SEQ)          // 4096
// softmax scale 1/sqrt(64) folded into Q projection together with log2(e):
#define QSCALE 0.18033688011112042f   // 0.125 * log2(e)

// ---------------------------------------------------------------------------
// Scratch (allocation-free: __device__ globals)
// ---------------------------------------------------------------------------
#define PROJN ((size_t)NH*NB*SEQ*HD)     // 4M elems
__device__ __align__(256) __nv_bfloat16 g_qh[PROJN], g_ql[PROJN];
__device__ __align__(256) __nv_bfloat16 g_kh[PROJN], g_kl[PROJN];
__device__ __align__(256) __nv_bfloat16 g_vh[PROJN], g_vl[PROJN];
__device__ __align__(256) __nv_bfloat16 g_xh[3][(size_t)ROWS*DM];
__device__ __align__(256) __nv_bfloat16 g_xl[3][(size_t)ROWS*DM];
__device__ __align__(256) __nv_bfloat16 g_wh[4][(size_t)DM*DM];
__device__ __align__(256) __nv_bfloat16 g_wl[4][(size_t)DM*DM];
__device__ __align__(256) __nv_bfloat16 g_yh[(size_t)ROWS*DM];
__device__ __align__(256) __nv_bfloat16 g_yl[(size_t)ROWS*DM];

// ---------------------------------------------------------------------------
// PTX helpers (baseline sm_80+ features: mma.sync / ldmatrix / cp.async)
// ---------------------------------------------------------------------------
__device__ __forceinline__ uint32_t smem_u32(const void* p) {
    uint32_t a;
    asm("{ .reg .u64 t; cvta.to.shared.u64 t, %1; cvt.u32.u64 %0, t; }"
        : "=r"(a) : "l"(p));
    return a;
}

#define CP_ASYNC16(dst, src) \
    asm volatile("cp.async.cg.shared.global [%0], [%1], 16;" :: "r"(dst), "l"(src))
#define CP_COMMIT() asm volatile("cp.async.commit_group;" ::: "memory")
#define CP_WAIT0()  asm volatile("cp.async.wait_group 0;" ::: "memory")

__device__ __forceinline__ void ldm_x4(uint32_t* r, uint32_t addr) {
    asm volatile("ldmatrix.sync.aligned.m8n8.x4.shared.b16 {%0,%1,%2,%3}, [%4];"
                 : "=r"(r[0]), "=r"(r[1]), "=r"(r[2]), "=r"(r[3]) : "r"(addr));
}
__device__ __forceinline__ void ldm_x4_t(uint32_t* r, uint32_t addr) {
    asm volatile("ldmatrix.sync.aligned.m8n8.x4.trans.shared.b16 {%0,%1,%2,%3}, [%4];"
                 : "=r"(r[0]), "=r"(r[1]), "=r"(r[2]), "=r"(r[3]) : "r"(addr));
}

__device__ __forceinline__ void mma_bf16(float* d, const uint32_t* a, const uint32_t* b) {
    asm volatile(
        "mma.sync.aligned.m16n8k16.row.col.f32.bf16.bf16.f32 "
        "{%0,%1,%2,%3}, {%4,%5,%6,%7}, {%8,%9}, {%0,%1,%2,%3};"
        : "+f"(d[0]), "+f"(d[1]), "+f"(d[2]), "+f"(d[3])
        : "r"(a[0]), "r"(a[1]), "r"(a[2]), "r"(a[3]), "r"(b[0]), "r"(b[1]));
}

// fast exp2 via MUFU (score scale pre-folded into Q, so argument is raw diff)
__device__ __forceinline__ float ex2(float x) {
    float r;
    asm("ex2.approx.f32 %0, %1;" : "=f"(r) : "f"(x));
    return r;
}
__device__ __forceinline__ float frcp(float x) {
    float r;
    asm("rcp.approx.f32 %0, %1;" : "=f"(r) : "f"(x));
    return r;
}

// fp32 pair -> packed bf16x2 hi + bf16x2 lo  (a in low half)
__device__ __forceinline__ void split2(float a, float b, uint32_t& hi, uint32_t& lo) {
    asm("cvt.rn.bf16x2.f32 %0, %1, %2;" : "=r"(hi) : "f"(b), "f"(a));
    const float ha = __uint_as_float(hi << 16);
    const float hb = __uint_as_float(hi & 0xffff0000u);
    const float la = a - ha, lb = b - hb;
    asm("cvt.rn.bf16x2.f32 %0, %1, %2;" : "=r"(lo) : "f"(lb), "f"(la));
}

// ---------------------------------------------------------------------------
// fp32 -> bf16 hi/lo splits (merged launches; z selects tensor)
// ---------------------------------------------------------------------------
__global__ void __launch_bounds__(256) split_in(
    const float4* __restrict__ q, const float4* __restrict__ k,
    const float4* __restrict__ v)
{
    const int z = blockIdx.z;
    const size_t XN4 = (size_t)ROWS * DM / 4;
    const float4* src = (z == 0) ? q : (z == 1) ? k : v;
    uint32_t* hp = (uint32_t*)(g_xh[z]);
    uint32_t* lp = (uint32_t*)(g_xl[z]);
    const size_t i = blockIdx.x * 256 + threadIdx.x;
    if (i >= XN4) return;
    float4 vv = src[i];
    uint32_t h0, l0, h1, l1;
    split2(vv.x, vv.y, h0, l0);
    split2(vv.z, vv.w, h1, l1);
    hp[2*i] = h0; hp[2*i+1] = h1;
    lp[2*i] = l0; lp[2*i+1] = l1;
}

__global__ void __launch_bounds__(256) split_w(
    const float4* __restrict__ wq, const float4* __restrict__ wk,
    const float4* __restrict__ wv, const float4* __restrict__ wo)
{
    const int z = blockIdx.z;
    const size_t WN4 = (size_t)DM * DM / 4;
    const float4* src = (z == 0) ? wq : (z == 1) ? wk : (z == 2) ? wv : wo;
    uint32_t* hp = (uint32_t*)(g_wh[z]);
    uint32_t* lp = (uint32_t*)(g_wl[z]);
    const size_t i = blockIdx.x * 256 + threadIdx.x;
    if (i >= WN4) return;
    float4 vv = src[i];
    uint32_t h0, l0, h1, l1;
    split2(vv.x, vv.y, h0, l0);
    split2(vv.z, vv.w, h1, l1);
    hp[2*i] = h0; hp[2*i+1] = h1;
    lp[2*i] = l0; lp[2*i+1] = l1;
}

// ---------------------------------------------------------------------------
// HMMA bf16x3 NT GEMM core, CTA 128x128, BK=32, 8 warps (2x4), warp 64x32.
// Double-buffered cp.async, ONE sync per stage, 2 CTAs/SM.
// oscale: epilogue scale applied before bf16 split (MODE 2 only; folds the
// softmax scale * log2(e) into the Q projection).
// ---------------------------------------------------------------------------
#define GSTRIDE 40
#define ARR_BYTES (128 * GSTRIDE * 2)
#define STAGE_BYTES (4 * ARR_BYTES)
#define NSTAGE (DM / 32)

template<int MODE>
__device__ __forceinline__ void gemm_body(
    const __nv_bfloat16* __restrict__ Ah, const __nv_bfloat16* __restrict__ Al,
    const __nv_bfloat16* __restrict__ Bh, const __nv_bfloat16* __restrict__ Bl,
    const float* __restrict__ bias, float* __restrict__ C,
    __nv_bfloat16* __restrict__ Ch, __nv_bfloat16* __restrict__ Cl,
    float oscale)
{
    extern __shared__ __align__(128) char smraw[];
    const uint32_t smem0 = smem_u32(smraw);

    const int tid = threadIdx.x;
    const int lane = tid & 31;
    const int wid = tid >> 5;
    const int wm = wid >> 2;
    const int wn = wid & 3;

    const int m0 = blockIdx.y << 7;
    const int n0 = blockIdx.x << 7;

    const __nv_bfloat16* gsrc[4] = {
        Ah + (size_t)m0 * DM, Al + (size_t)m0 * DM,
        Bh + (size_t)n0 * DM, Bl + (size_t)n0 * DM
    };

    const int r0c = tid >> 2, cc0 = tid & 3;
    const int r1c = r0c + 64;

    auto load_stage = [&](int s) {
        const int kk = s * 32;
        const uint32_t sb = smem0 + (s & 1) * STAGE_BYTES;
        #pragma unroll
        for (int a = 0; a < 4; a++) {
            const __nv_bfloat16* g = gsrc[a];
            const uint32_t ab = sb + a * ARR_BYTES;
            CP_ASYNC16(ab + r0c * (GSTRIDE*2) + cc0 * 16,
                       g + (size_t)r0c * DM + kk + cc0 * 8);
            CP_ASYNC16(ab + r1c * (GSTRIDE*2) + cc0 * 16,
                       g + (size_t)r1c * DM + kk + cc0 * 8);
        }
    };

    float acc[4][4][4];
    #pragma unroll
    for (int i = 0; i < 4; i++)
        #pragma unroll
        for (int j = 0; j < 4; j++)
            #pragma unroll
            for (int e = 0; e < 4; e++) acc[i][j][e] = 0.f;

    const int a_r = lane & 15, a_c = (lane >> 4) << 3;
    const int b_r = (lane & 7) + (((lane >> 3) & 2) << 2);
    const int b_c = ((lane >> 3) & 1) << 3;

    load_stage(0);
    CP_COMMIT();

    for (int s = 0; s < NSTAGE; s++) {
        CP_WAIT0();
        __syncthreads();
        if (s + 1 < NSTAGE) { load_stage(s + 1); CP_COMMIT(); }

        const uint32_t sb = smem0 + (s & 1) * STAGE_BYTES;
        const uint32_t sAh = sb;
        const uint32_t sAl = sb + ARR_BYTES;
        const uint32_t sBh = sb + 2 * ARR_BYTES;
        const uint32_t sBl = sb + 3 * ARR_BYTES;

        #pragma unroll
        for (int k16 = 0; k16 < 2; k16++) {
            const int kc = k16 * 16;
            uint32_t bh[2][4], bl[2][4];
            #pragma unroll
            for (int np = 0; np < 2; np++) {
                const uint32_t off =
                    ((wn * 32 + np * 16 + b_r) * GSTRIDE + kc + b_c) * 2;
                ldm_x4(bh[np], sBh + off);
                ldm_x4(bl[np], sBl + off);
            }
            #pragma unroll
            for (int mt = 0; mt < 4; mt++) {
                uint32_t ah[4], al[4];
                const uint32_t off =
                    ((wm * 64 + mt * 16 + a_r) * GSTRIDE + kc + a_c) * 2;
                ldm_x4(ah, sAh + off);
                ldm_x4(al, sAl + off);
                #pragma unroll
                for (int nt = 0; nt < 4; nt++)
                    mma_bf16(acc[mt][nt], ah, &bh[nt >> 1][(nt & 1) * 2]);
                #pragma unroll
                for (int nt = 0; nt < 4; nt++)
                    mma_bf16(acc[mt][nt], ah, &bl[nt >> 1][(nt & 1) * 2]);
                #pragma unroll
                for (int nt = 0; nt < 4; nt++)
                    mma_bf16(acc[mt][nt], al, &bh[nt >> 1][(nt & 1) * 2]);
            }
        }
    }

    #pragma unroll
    for (int mt = 0; mt < 4; mt++) {
        #pragma unroll
        for (int nt = 0; nt < 4; nt++) {
            const int col = n0 + wn * 32 + nt * 8 + ((lane & 3) << 1);
            const float b0 = bias[col], b1 = bias[col + 1];
            #pragma unroll
            for (int half = 0; half < 2; half++) {
                const int row = m0 + wm * 64 + mt * 16 + (lane >> 2) + half * 8;
                const float vx = (acc[mt][nt][half * 2 + 0] + b0) * oscale;
                const float vy = (acc[mt][nt][half * 2 + 1] + b1) * oscale;
                if (MODE == 0) {
                    float2 v; v.x = vx; v.y = vy;
                    *(float2*)&C[(size_t)row * DM + col] = v;
                } else {
                    const int h = col >> 6, d = col & 63;
                    const int nb = row >> 11, kq = row & 2047;
                    const size_t idx = (((size_t)(h * NB + nb)) * SEQ + kq) * HD + d;
                    uint32_t hi, lo;
                    split2(vx, vy, hi, lo);
                    *(uint32_t*)&Ch[idx] = hi;
                    *(uint32_t*)&Cl[idx] = lo;
                }
            }
        }
    }
}

__global__ void __launch_bounds__(256, 2) gemm_qkv(
    const __nv_bfloat16* __restrict__ xh, const __nv_bfloat16* __restrict__ xl,
    const __nv_bfloat16* __restrict__ wh, const __nv_bfloat16* __restrict__ wl,
    const float* __restrict__ bq, const float* __restrict__ bk,
    const float* __restrict__ bv)
{
    const int z = blockIdx.z;
    const size_t XN = (size_t)ROWS * DM, WN = (size_t)DM * DM;
    const float* bias = (z == 0) ? bq : (z == 1) ? bk : bv;
    __nv_bfloat16* Ch = (z == 0) ? g_qh : (z == 1) ? g_kh : g_vh;
    __nv_bfloat16* Cl = (z == 0) ? g_ql : (z == 1) ? g_kl : g_vl;
    const float osc = (z == 0) ? QSCALE : 1.f;   // fold softmax scale into Q
    gemm_body<2>(xh + z * XN, xl + z * XN, wh + z * WN, wl + z * WN,
                 bias, nullptr, Ch, Cl, osc);
}

__global__ void __launch_bounds__(256, 2) gemm_out(
    const __nv_bfloat16* __restrict__ Ah, const __nv_bfloat16* __restrict__ Al,
    const __nv_bfloat16* __restrict__ Bh, const __nv_bfloat16* __restrict__ Bl,
    const float* __restrict__ bias, float* __restrict__ C)
{
    gemm_body<0>(Ah, Al, Bh, Bl, bias, C, nullptr, nullptr, 1.f);
}

// ---------------------------------------------------------------------------
// FA2-style HMMA attention, 2 CTAs/SM, 3-term S and PV.
// Scale folded into Q -> softmax uses bare ex2.approx (no multiplies).
// smem: [Qh 18432][Ql 18432][stage0 36864][stage1 36864] = 110592 B.
// Q-hi frags resident; Q-lo frags reloaded per tile with distance-1 prefetch.
// ---------------------------------------------------------------------------
#define ASTRIDE 72
#define AARR    (64 * ASTRIDE * 2)          // 9216 B
#define ASTAGE  (4 * AARR)                  // 36864 B
#define QONE    (128 * ASTRIDE * 2)         // 18432 B (one Q array)
#define QARR    (2 * QONE)                  // 36864 B (Qh + Ql)

__global__ void __launch_bounds__(256, 2) attn_mma(
    const __nv_bfloat16* __restrict__ Qh_, const __nv_bfloat16* __restrict__ Ql_,
    const __nv_bfloat16* __restrict__ Kh_, const __nv_bfloat16* __restrict__ Kl_,
    const __nv_bfloat16* __restrict__ Vh_, const __nv_bfloat16* __restrict__ Vl_,
    __nv_bfloat16* __restrict__ Yh, __nv_bfloat16* __restrict__ Yl)
{
    extern __shared__ __align__(128) char smraw[];
    const uint32_t s0 = smem_u32(smraw);
    const uint32_t stg = s0 + QARR;          // stage base (after Qh AND Ql)

    const int tid = threadIdx.x;
    const int lane = tid & 31;
    const int wid = tid >> 5;
    const int hn = blockIdx.y;
    const int h = hn >> 1, n = hn & 1;
    const int q0 = blockIdx.x << 7;
    const size_t hoff = (size_t)hn * SEQ * HD;

    const int a_r = lane & 15, a_c = (lane >> 4) << 3;
    const int b_r = (lane & 7) + (((lane >> 3) & 2) << 2);
    const int b_c = ((lane >> 3) & 1) << 3;

    // ---- stage Q into dedicated smem region (stays resident) ----
    {
        const __nv_bfloat16* Qhg = Qh_ + hoff + (size_t)q0 * HD;
        const __nv_bfloat16* Qlg = Ql_ + hoff + (size_t)q0 * HD;
        #pragma unroll
        for (int c = 0; c < 4; c++) {
            const int ch = tid + c * 256;            // 0..1023
            const int row = ch >> 3, c16 = ch & 7;
            CP_ASYNC16(s0 + row * 144 + c16 * 16, Qhg + row * 64 + c16 * 8);
            CP_ASYNC16(s0 + QONE + row * 144 + c16 * 16, Qlg + row * 64 + c16 * 8);
        }
        CP_COMMIT();
    }

    const __nv_bfloat16* Khg = Kh_ + hoff;
    const __nv_bfloat16* Klg = Kl_ + hoff;
    const __nv_bfloat16* Vhg = Vh_ + hoff;
    const __nv_bfloat16* Vlg = Vl_ + hoff;

    auto load_stage = [&](int s) {
        const int kv0 = s << 6;
        const uint32_t sb = stg + (s & 1) * ASTAGE;
        const __nv_bfloat16* gs[4] = { Khg, Klg, Vhg, Vlg };
        #pragma unroll
        for (int a = 0; a < 4; a++) {
            #pragma unroll
            for (int c = 0; c < 2; c++) {
                const int ch = tid + c * 256;        // 0..511
                const int row = ch >> 3, c16 = ch & 7;
                CP_ASYNC16(sb + a * AARR + row * 144 + c16 * 16,
                           gs[a] + (size_t)(kv0 + row) * 64 + c16 * 8);
            }
        }
    };

    load_stage(0); CP_COMMIT();

    // Q-hi fragments resident in registers; Q-lo reloaded per tile.
    CP_WAIT0();            // Q + stage 0 landed
    __syncthreads();
    uint32_t qfh[4][4];
    const uint32_t qbase = ((wid * 16 + a_r) * ASTRIDE + a_c) * 2;
    #pragma unroll
    for (int t4 = 0; t4 < 4; t4++)
        ldm_x4(qfh[t4], s0 + qbase + t4 * 32);
    __syncthreads();

    float m0r = -1e30f, m1r = -1e30f, l0 = 0.f, l1 = 0.f;
    float O[8][4];
    #pragma unroll
    for (int j = 0; j < 8; j++)
        #pragma unroll
        for (int e = 0; e < 4; e++) O[j][e] = 0.f;

    for (int t = 0; t < SEQ / 64; t++) {
        if (t > 0) { CP_WAIT0(); __syncthreads(); }
        if (t + 1 < SEQ / 64) { load_stage(t + 1); CP_COMMIT(); }

        const uint32_t sb = stg + (t & 1) * ASTAGE;

        // ---- S = Q K^T (bf16x3; Q-lo frags prefetched one t4 ahead) ----
        float S[8][4];
        #pragma unroll
        for (int j = 0; j < 8; j++)
            #pragma unroll
            for (int e = 0; e < 4; e++) S[j][e] = 0.f;

        uint32_t qfl[4], qfln[4];
        ldm_x4(qfl, s0 + QONE + qbase);             // t4=0
        #pragma unroll
        for (int t4 = 0; t4 < 4; t4++) {
            if (t4 < 3)
                ldm_x4(qfln, s0 + QONE + qbase + (t4 + 1) * 32);
            #pragma unroll
            for (int jp = 0; jp < 4; jp++) {
                uint32_t bh[4], bl[4];
                const uint32_t off = ((16 * jp + b_r) * ASTRIDE + 16 * t4 + b_c) * 2;
                ldm_x4(bh, sb + off);
                ldm_x4(bl, sb + AARR + off);
                mma_bf16(S[2*jp],   qfh[t4], &bh[0]);
                mma_bf16(S[2*jp+1], qfh[t4], &bh[2]);
                mma_bf16(S[2*jp],   qfh[t4], &bl[0]);
                mma_bf16(S[2*jp+1], qfh[t4], &bl[2]);
                mma_bf16(S[2*jp],   qfl,     &bh[0]);
                mma_bf16(S[2*jp+1], qfl,     &bh[2]);
            }
            qfl[0] = qfln[0]; qfl[1] = qfln[1];
            qfl[2] = qfln[2]; qfl[3] = qfln[3];
        }

        // ---- online softmax (scale pre-folded; bare exp2) ----
        float corr0, corr1;
        {
            float tm = S[0][0];
            #pragma unroll
            for (int j = 0; j < 8; j++) tm = fmaxf(tm, fmaxf(S[j][0], S[j][1]));
            tm = fmaxf(tm, __shfl_xor_sync(0xffffffffu, tm, 1));
            tm = fmaxf(tm, __shfl_xor_sync(0xffffffffu, tm, 2));
            const float mnew = fmaxf(m0r, tm);
            corr0 = ex2(m0r - mnew);
            float rs = 0.f;
            #pragma unroll
            for (int j = 0; j < 8; j++) {
                S[j][0] = ex2(S[j][0] - mnew);
                S[j][1] = ex2(S[j][1] - mnew);
                rs += S[j][0] + S[j][1];
            }
            rs += __shfl_xor_sync(0xffffffffu, rs, 1);
            rs += __shfl_xor_sync(0xffffffffu, rs, 2);
            l0 = l0 * corr0 + rs;
            m0r = mnew;
        }
        {
            float tm = S[0][2];
            #pragma unroll
            for (int j = 0; j < 8; j++) tm = fmaxf(tm, fmaxf(S[j][2], S[j][3]));
            tm = fmaxf(tm, __shfl_xor_sync(0xffffffffu, tm, 1));
            tm = fmaxf(tm, __shfl_xor_sync(0xffffffffu, tm, 2));
            const float mnew = fmaxf(m1r, tm);
            corr1 = ex2(m1r - mnew);
            float rs = 0.f;
            #pragma unroll
            for (int j = 0; j < 8; j++) {
                S[j][2] = ex2(S[j][2] - mnew);
                S[j][3] = ex2(S[j][3] - mnew);
                rs += S[j][2] + S[j][3];
            }
            rs += __shfl_xor_sync(0xffffffffu, rs, 1);
            rs += __shfl_xor_sync(0xffffffffu, rs, 2);
            l1 = l1 * corr1 + rs;
            m1r = mnew;
        }

        // ---- pack P to bf16 hi/lo A-fragments ----
        uint32_t pah[4][4], pal[4][4];
        #pragma unroll
        for (int t4 = 0; t4 < 4; t4++) {
            split2(S[2*t4][0],   S[2*t4][1],   pah[t4][0], pal[t4][0]);
            split2(S[2*t4][2],   S[2*t4][3],   pah[t4][1], pal[t4][1]);
            split2(S[2*t4+1][0], S[2*t4+1][1], pah[t4][2], pal[t4][2]);
            split2(S[2*t4+1][2], S[2*t4+1][3], pah[t4][3], pal[t4][3]);
        }

        // ---- rescale O ----
        #pragma unroll
        for (int j = 0; j < 8; j++) {
            O[j][0] *= corr0; O[j][1] *= corr0;
            O[j][2] *= corr1; O[j][3] *= corr1;
        }

        // ---- O += P V (3-term: Ph*Vh + Ph*Vl + Pl*Vh) ----
        #pragma unroll
        for (int t4 = 0; t4 < 4; t4++) {
            #pragma unroll
            for (int jp = 0; jp < 4; jp++) {
                uint32_t vh[4], vl[4];
                const uint32_t off =
                    ((16 * t4 + (lane & 15)) * ASTRIDE + 16 * jp + a_c) * 2;
                ldm_x4_t(vh, sb + 2 * AARR + off);
                ldm_x4_t(vl, sb + 3 * AARR + off);
                mma_bf16(O[2*jp],   pah[t4], &vh[0]);
                mma_bf16(O[2*jp+1], pah[t4], &vh[2]);
                mma_bf16(O[2*jp],   pah[t4], &vl[0]);
                mma_bf16(O[2*jp+1], pah[t4], &vl[2]);
                mma_bf16(O[2*jp],   pal[t4], &vh[0]);
                mma_bf16(O[2*jp+1], pal[t4], &vh[2]);
            }
        }
    }

    // ---- epilogue: scale by 1/l, write bf16 hi/lo in [N, K, H*D] layout ----
    const float inv0 = frcp(l0), inv1 = frcp(l1);
    #pragma unroll
    for (int j = 0; j < 8; j++) {
        const int col = h * 64 + 8 * j + ((lane & 3) << 1);
        #pragma unroll
        for (int half = 0; half < 2; half++) {
            const int row = q0 + wid * 16 + (lane >> 2) + half * 8;
            const float inv = half ? inv1 : inv0;
            const float y0 = O[j][half * 2 + 0] * inv;
            const float y1 = O[j][half * 2 + 1] * inv;
            const size_t idx = ((size_t)(n * SEQ) + row) * DM + col;
            uint32_t hi, lo;
            split2(y0, y1, hi, lo);
            *(uint32_t*)&Yh[idx] = hi;
            *(uint32_t*)&Yl[idx] = lo;
        }
    }
}

// ---------------------------------------------------------------------------
extern "C" void kernel_launch(void* const* d_in, const int* in_sizes, int n_in,
                              void* d_out, int out_size)
{
    const float* q  = (const float*)d_in[0];
    const float* k  = (const float*)d_in[1];
    const float* v  = (const float*)d_in[2];
    const float* Wq = (const float*)d_in[3];
    const float* bq = (const float*)d_in[4];
    const float* Wk = (const float*)d_in[5];
    const float* bk = (const float*)d_in[6];
    const float* Wv = (const float*)d_in[7];
    const float* bv = (const float*)d_in[8];
    const float* Wo = (const float*)d_in[9];
    const float* bo = (const float*)d_in[10];
    float* out = (float*)d_out;

    __nv_bfloat16 *xh, *xl, *wh, *wl, *yh, *yl, *qh, *ql, *kh, *kl, *vh, *vl;
    cudaGetSymbolAddress((void**)&xh, g_xh);
    cudaGetSymbolAddress((void**)&xl, g_xl);
    cudaGetSymbolAddress((void**)&wh, g_wh);
    cudaGetSymbolAddress((void**)&wl, g_wl);
    cudaGetSymbolAddress((void**)&yh, g_yh);
    cudaGetSymbolAddress((void**)&yl, g_yl);
    cudaGetSymbolAddress((void**)&qh, g_qh);
    cudaGetSymbolAddress((void**)&ql, g_ql);
    cudaGetSymbolAddress((void**)&kh, g_kh);
    cudaGetSymbolAddress((void**)&kl, g_kl);
    cudaGetSymbolAddress((void**)&vh, g_vh);
    cudaGetSymbolAddress((void**)&vl, g_vl);

    const size_t XN = (size_t)ROWS * DM;
    const size_t WN = (size_t)DM * DM;

    { const dim3 gi((unsigned)(XN/4/256), 1, 3);
      split_in<<<gi, 256>>>((const float4*)q, (const float4*)k, (const float4*)v); }
    { const dim3 gw((unsigned)(WN/4/256), 1, 4);
      split_w<<<gw, 256>>>((const float4*)Wq, (const float4*)Wk,
                           (const float4*)Wv, (const float4*)Wo); }

    const int gsmem = 2 * STAGE_BYTES;
    cudaFuncSetAttribute((const void*)gemm_qkv,
                         cudaFuncAttributeMaxDynamicSharedMemorySize, gsmem);
    cudaFuncSetAttribute((const void*)gemm_out,
                         cudaFuncAttributeMaxDynamicSharedMemorySize, gsmem);
    const dim3 gq(DM/128, ROWS/128, 3);
    gemm_qkv<<<gq, 256, gsmem>>>(xh, xl, wh, wl, bq, bk, bv);

    const int asmem = QARR + 2 * ASTAGE;   // 110592
    cudaFuncSetAttribute((const void*)attn_mma,
                         cudaFuncAttributeMaxDynamicSharedMemorySize, asmem);
    const dim3 ga(SEQ/128, NH*NB);  // (16, 32)
    attn_mma<<<ga, 256, asmem>>>(qh, ql, kh, kl, vh, vl, yh, yl);

    const dim3 gg(DM/128, ROWS/128);
    gemm_out<<<gg, 256, gsmem>>>(yh, yl, wh + 3*WN, wl + 3*WN, bo, out);
}

// round 10
// speedup vs baseline: 3.5909x; 1.0841x over previous
#include <cuda_runtime.h>
#include <cuda_bf16.h>
#include <cuda_fp16.h>
#include <cstdint>

#define NB   2
#define SEQ  2048
#define DM   1024
#define NH   16
#define HD   64
#define ROWS (NB*SEQ)          // 4096
// softmax scale 1/sqrt(64) folded into Q projection together with log2(e):
#define QSCALE 0.18033688011112042f   // 0.125 * log2(e)

// ---------------------------------------------------------------------------
// Scratch (allocation-free: __device__ globals)
// ---------------------------------------------------------------------------
#define PROJN ((size_t)NH*NB*SEQ*HD)     // 4M elems
__device__ __align__(256) __nv_bfloat16 g_qh[PROJN], g_ql[PROJN];
__device__ __align__(256) __nv_bfloat16 g_kh[PROJN], g_kl[PROJN];
__device__ __align__(256) __half        g_vh[PROJN], g_vl[PROJN];   // fp16 V
__device__ __align__(256) __nv_bfloat16 g_xh[3][(size_t)ROWS*DM];
__device__ __align__(256) __nv_bfloat16 g_xl[3][(size_t)ROWS*DM];
__device__ __align__(256) __nv_bfloat16 g_wh[4][(size_t)DM*DM];
__device__ __align__(256) __nv_bfloat16 g_wl[4][(size_t)DM*DM];
__device__ __align__(256) __nv_bfloat16 g_yh[(size_t)ROWS*DM];
__device__ __align__(256) __nv_bfloat16 g_yl[(size_t)ROWS*DM];

// ---------------------------------------------------------------------------
// PTX helpers (baseline sm_80+ features: mma.sync / ldmatrix / cp.async)
// ---------------------------------------------------------------------------
__device__ __forceinline__ uint32_t smem_u32(const void* p) {
    uint32_t a;
    asm("{ .reg .u64 t; cvta.to.shared.u64 t, %1; cvt.u32.u64 %0, t; }"
        : "=r"(a) : "l"(p));
    return a;
}

#define CP_ASYNC16(dst, src) \
    asm volatile("cp.async.cg.shared.global [%0], [%1], 16;" :: "r"(dst), "l"(src))
#define CP_COMMIT() asm volatile("cp.async.commit_group;" ::: "memory")
#define CP_WAIT0()  asm volatile("cp.async.wait_group 0;" ::: "memory")

__device__ __forceinline__ void ldm_x4(uint32_t* r, uint32_t addr) {
    asm volatile("ldmatrix.sync.aligned.m8n8.x4.shared.b16 {%0,%1,%2,%3}, [%4];"
                 : "=r"(r[0]), "=r"(r[1]), "=r"(r[2]), "=r"(r[3]) : "r"(addr));
}
__device__ __forceinline__ void ldm_x4_t(uint32_t* r, uint32_t addr) {
    asm volatile("ldmatrix.sync.aligned.m8n8.x4.trans.shared.b16 {%0,%1,%2,%3}, [%4];"
                 : "=r"(r[0]), "=r"(r[1]), "=r"(r[2]), "=r"(r[3]) : "r"(addr));
}

__device__ __forceinline__ void mma_bf16(float* d, const uint32_t* a, const uint32_t* b) {
    asm volatile(
        "mma.sync.aligned.m16n8k16.row.col.f32.bf16.bf16.f32 "
        "{%0,%1,%2,%3}, {%4,%5,%6,%7}, {%8,%9}, {%0,%1,%2,%3};"
        : "+f"(d[0]), "+f"(d[1]), "+f"(d[2]), "+f"(d[3])
        : "r"(a[0]), "r"(a[1]), "r"(a[2]), "r"(a[3]), "r"(b[0]), "r"(b[1]));
}
__device__ __forceinline__ void mma_f16(float* d, const uint32_t* a, const uint32_t* b) {
    asm volatile(
        "mma.sync.aligned.m16n8k16.row.col.f32.f16.f16.f32 "
        "{%0,%1,%2,%3}, {%4,%5,%6,%7}, {%8,%9}, {%0,%1,%2,%3};"
        : "+f"(d[0]), "+f"(d[1]), "+f"(d[2]), "+f"(d[3])
        : "r"(a[0]), "r"(a[1]), "r"(a[2]), "r"(a[3]), "r"(b[0]), "r"(b[1]));
}

// fast exp2 / rcp via MUFU
__device__ __forceinline__ float ex2(float x) {
    float r; asm("ex2.approx.f32 %0, %1;" : "=f"(r) : "f"(x)); return r;
}
__device__ __forceinline__ float frcp(float x) {
    float r; asm("rcp.approx.f32 %0, %1;" : "=f"(r) : "f"(x)); return r;
}

// fp32 pair -> packed bf16x2 hi + bf16x2 lo  (a in low half)
__device__ __forceinline__ void split2(float a, float b, uint32_t& hi, uint32_t& lo) {
    asm("cvt.rn.bf16x2.f32 %0, %1, %2;" : "=r"(hi) : "f"(b), "f"(a));
    const float ha = __uint_as_float(hi << 16);
    const float hb = __uint_as_float(hi & 0xffff0000u);
    const float la = a - ha, lb = b - hb;
    asm("cvt.rn.bf16x2.f32 %0, %1, %2;" : "=r"(lo) : "f"(lb), "f"(la));
}
// fp32 pair -> packed f16x2 (a in low half)
__device__ __forceinline__ uint32_t pack_f16(float a, float b) {
    uint32_t r; asm("cvt.rn.f16x2.f32 %0, %1, %2;" : "=r"(r) : "f"(b), "f"(a));
    return r;
}
// fp32 pair -> f16x2 hi + f16x2 lo
__device__ __forceinline__ void split2h(float a, float b, uint32_t& hi, uint32_t& lo) {
    hi = pack_f16(a, b);
    __half2 h = *(__half2*)&hi;
    const float la = a - __half2float(h.x);
    const float lb = b - __half2float(h.y);
    lo = pack_f16(la, lb);
}

// ---------------------------------------------------------------------------
// fp32 -> bf16 hi/lo splits (merged launches; z selects tensor)
// ---------------------------------------------------------------------------
__global__ void __launch_bounds__(256) split_in(
    const float4* __restrict__ q, const float4* __restrict__ k,
    const float4* __restrict__ v)
{
    const int z = blockIdx.z;
    const size_t XN4 = (size_t)ROWS * DM / 4;
    const float4* src = (z == 0) ? q : (z == 1) ? k : v;
    uint32_t* hp = (uint32_t*)(g_xh[z]);
    uint32_t* lp = (uint32_t*)(g_xl[z]);
    const size_t i = blockIdx.x * 256 + threadIdx.x;
    if (i >= XN4) return;
    float4 vv = src[i];
    uint32_t h0, l0, h1, l1;
    split2(vv.x, vv.y, h0, l0);
    split2(vv.z, vv.w, h1, l1);
    hp[2*i] = h0; hp[2*i+1] = h1;
    lp[2*i] = l0; lp[2*i+1] = l1;
}

__global__ void __launch_bounds__(256) split_w(
    const float4* __restrict__ wq, const float4* __restrict__ wk,
    const float4* __restrict__ wv, const float4* __restrict__ wo)
{
    const int z = blockIdx.z;
    const size_t WN4 = (size_t)DM * DM / 4;
    const float4* src = (z == 0) ? wq : (z == 1) ? wk : (z == 2) ? wv : wo;
    uint32_t* hp = (uint32_t*)(g_wh[z]);
    uint32_t* lp = (uint32_t*)(g_wl[z]);
    const size_t i = blockIdx.x * 256 + threadIdx.x;
    if (i >= WN4) return;
    float4 vv = src[i];
    uint32_t h0, l0, h1, l1;
    split2(vv.x, vv.y, h0, l0);
    split2(vv.z, vv.w, h1, l1);
    hp[2*i] = h0; hp[2*i+1] = h1;
    lp[2*i] = l0; lp[2*i+1] = l1;
}

// ---------------------------------------------------------------------------
// HMMA bf16x3 NT GEMM core, CTA 128x128, BK=32, 8 warps (2x4), warp 64x32.
// Double-buffered cp.async, ONE sync per stage, 2 CTAs/SM.
// MODE 0: fp32 C row-major; MODE 2: bf16 hi/lo QKV scatter;
// MODE 3: fp16 hi/lo QKV scatter (for V).
// ---------------------------------------------------------------------------
#define GSTRIDE 40
#define ARR_BYTES (128 * GSTRIDE * 2)
#define STAGE_BYTES (4 * ARR_BYTES)
#define NSTAGE (DM / 32)

template<int MODE>
__device__ __forceinline__ void gemm_body(
    const __nv_bfloat16* __restrict__ Ah, const __nv_bfloat16* __restrict__ Al,
    const __nv_bfloat16* __restrict__ Bh, const __nv_bfloat16* __restrict__ Bl,
    const float* __restrict__ bias, float* __restrict__ C,
    void* __restrict__ Ch, void* __restrict__ Cl,
    float oscale)
{
    extern __shared__ __align__(128) char smraw[];
    const uint32_t smem0 = smem_u32(smraw);

    const int tid = threadIdx.x;
    const int lane = tid & 31;
    const int wid = tid >> 5;
    const int wm = wid >> 2;
    const int wn = wid & 3;

    const int m0 = blockIdx.y << 7;
    const int n0 = blockIdx.x << 7;

    const __nv_bfloat16* gsrc[4] = {
        Ah + (size_t)m0 * DM, Al + (size_t)m0 * DM,
        Bh + (size_t)n0 * DM, Bl + (size_t)n0 * DM
    };

    const int r0c = tid >> 2, cc0 = tid & 3;
    const int r1c = r0c + 64;

    auto load_stage = [&](int s) {
        const int kk = s * 32;
        const uint32_t sb = smem0 + (s & 1) * STAGE_BYTES;
        #pragma unroll
        for (int a = 0; a < 4; a++) {
            const __nv_bfloat16* g = gsrc[a];
            const uint32_t ab = sb + a * ARR_BYTES;
            CP_ASYNC16(ab + r0c * (GSTRIDE*2) + cc0 * 16,
                       g + (size_t)r0c * DM + kk + cc0 * 8);
            CP_ASYNC16(ab + r1c * (GSTRIDE*2) + cc0 * 16,
                       g + (size_t)r1c * DM + kk + cc0 * 8);
        }
    };

    float acc[4][4][4];
    #pragma unroll
    for (int i = 0; i < 4; i++)
        #pragma unroll
        for (int j = 0; j < 4; j++)
            #pragma unroll
            for (int e = 0; e < 4; e++) acc[i][j][e] = 0.f;

    const int a_r = lane & 15, a_c = (lane >> 4) << 3;
    const int b_r = (lane & 7) + (((lane >> 3) & 2) << 2);
    const int b_c = ((lane >> 3) & 1) << 3;

    load_stage(0);
    CP_COMMIT();

    for (int s = 0; s < NSTAGE; s++) {
        CP_WAIT0();
        __syncthreads();
        if (s + 1 < NSTAGE) { load_stage(s + 1); CP_COMMIT(); }

        const uint32_t sb = smem0 + (s & 1) * STAGE_BYTES;
        const uint32_t sAh = sb;
        const uint32_t sAl = sb + ARR_BYTES;
        const uint32_t sBh = sb + 2 * ARR_BYTES;
        const uint32_t sBl = sb + 3 * ARR_BYTES;

        #pragma unroll
        for (int k16 = 0; k16 < 2; k16++) {
            const int kc = k16 * 16;
            uint32_t bh[2][4], bl[2][4];
            #pragma unroll
            for (int np = 0; np < 2; np++) {
                const uint32_t off =
                    ((wn * 32 + np * 16 + b_r) * GSTRIDE + kc + b_c) * 2;
                ldm_x4(bh[np], sBh + off);
                ldm_x4(bl[np], sBl + off);
            }
            #pragma unroll
            for (int mt = 0; mt < 4; mt++) {
                uint32_t ah[4], al[4];
                const uint32_t off =
                    ((wm * 64 + mt * 16 + a_r) * GSTRIDE + kc + a_c) * 2;
                ldm_x4(ah, sAh + off);
                ldm_x4(al, sAl + off);
                #pragma unroll
                for (int nt = 0; nt < 4; nt++)
                    mma_bf16(acc[mt][nt], ah, &bh[nt >> 1][(nt & 1) * 2]);
                #pragma unroll
                for (int nt = 0; nt < 4; nt++)
                    mma_bf16(acc[mt][nt], ah, &bl[nt >> 1][(nt & 1) * 2]);
                #pragma unroll
                for (int nt = 0; nt < 4; nt++)
                    mma_bf16(acc[mt][nt], al, &bh[nt >> 1][(nt & 1) * 2]);
            }
        }
    }

    #pragma unroll
    for (int mt = 0; mt < 4; mt++) {
        #pragma unroll
        for (int nt = 0; nt < 4; nt++) {
            const int col = n0 + wn * 32 + nt * 8 + ((lane & 3) << 1);
            const float b0 = bias[col], b1 = bias[col + 1];
            #pragma unroll
            for (int half = 0; half < 2; half++) {
                const int row = m0 + wm * 64 + mt * 16 + (lane >> 2) + half * 8;
                const float vx = (acc[mt][nt][half * 2 + 0] + b0) * oscale;
                const float vy = (acc[mt][nt][half * 2 + 1] + b1) * oscale;
                if (MODE == 0) {
                    float2 v; v.x = vx; v.y = vy;
                    *(float2*)&C[(size_t)row * DM + col] = v;
                } else {
                    const int h = col >> 6, d = col & 63;
                    const int nb = row >> 11, kq = row & 2047;
                    const size_t idx = (((size_t)(h * NB + nb)) * SEQ + kq) * HD + d;
                    uint32_t hi, lo;
                    if (MODE == 2) {
                        split2(vx, vy, hi, lo);
                        *(uint32_t*)&((__nv_bfloat16*)Ch)[idx] = hi;
                        *(uint32_t*)&((__nv_bfloat16*)Cl)[idx] = lo;
                    } else {
                        split2h(vx, vy, hi, lo);
                        *(uint32_t*)&((__half*)Ch)[idx] = hi;
                        *(uint32_t*)&((__half*)Cl)[idx] = lo;
                    }
                }
            }
        }
    }
}

__global__ void __launch_bounds__(256, 2) gemm_qkv(
    const __nv_bfloat16* __restrict__ xh, const __nv_bfloat16* __restrict__ xl,
    const __nv_bfloat16* __restrict__ wh, const __nv_bfloat16* __restrict__ wl,
    const float* __restrict__ bq, const float* __restrict__ bk,
    const float* __restrict__ bv)
{
    const int z = blockIdx.z;
    const size_t XN = (size_t)ROWS * DM, WN = (size_t)DM * DM;
    if (z == 0) {
        gemm_body<2>(xh, xl, wh, wl, bq, nullptr, g_qh, g_ql, QSCALE);
    } else if (z == 1) {
        gemm_body<2>(xh + XN, xl + XN, wh + WN, wl + WN, bk, nullptr,
                     g_kh, g_kl, 1.f);
    } else {
        gemm_body<3>(xh + 2*XN, xl + 2*XN, wh + 2*WN, wl + 2*WN, bv, nullptr,
                     g_vh, g_vl, 1.f);
    }
}

__global__ void __launch_bounds__(256, 2) gemm_out(
    const __nv_bfloat16* __restrict__ Ah, const __nv_bfloat16* __restrict__ Al,
    const __nv_bfloat16* __restrict__ Bh, const __nv_bfloat16* __restrict__ Bl,
    const float* __restrict__ bias, float* __restrict__ C)
{
    gemm_body<0>(Ah, Al, Bh, Bl, bias, C, nullptr, nullptr, 1.f);
}

// ---------------------------------------------------------------------------
// FA2-style HMMA attention, 2 CTAs/SM.
// S: bf16x3 (unchanged, proven).  PV: 2-term fp16 (P_fp16*Vh + P_fp16*Vl) —
// anchored error 1.4e-3/4 = 3.5e-4 from the round-7 bf16-P measurement.
// smem: [Qh 18432][Ql 18432][stage0 36864][stage1 36864] = 110592 B.
// ---------------------------------------------------------------------------
#define ASTRIDE 72
#define AARR    (64 * ASTRIDE * 2)          // 9216 B
#define ASTAGE  (4 * AARR)                  // 36864 B
#define QONE    (128 * ASTRIDE * 2)         // 18432 B (one Q array)
#define QARR    (2 * QONE)                  // 36864 B (Qh + Ql)

__global__ void __launch_bounds__(256, 2) attn_mma(
    const __nv_bfloat16* __restrict__ Qh_, const __nv_bfloat16* __restrict__ Ql_,
    const __nv_bfloat16* __restrict__ Kh_, const __nv_bfloat16* __restrict__ Kl_,
    const __half* __restrict__ Vh_, const __half* __restrict__ Vl_,
    __nv_bfloat16* __restrict__ Yh, __nv_bfloat16* __restrict__ Yl)
{
    extern __shared__ __align__(128) char smraw[];
    const uint32_t s0 = smem_u32(smraw);
    const uint32_t stg = s0 + QARR;          // stage base (after Qh AND Ql)

    const int tid = threadIdx.x;
    const int lane = tid & 31;
    const int wid = tid >> 5;
    const int hn = blockIdx.y;
    const int h = hn >> 1, n = hn & 1;
    const int q0 = blockIdx.x << 7;
    const size_t hoff = (size_t)hn * SEQ * HD;

    const int a_r = lane & 15, a_c = (lane >> 4) << 3;
    const int b_r = (lane & 7) + (((lane >> 3) & 2) << 2);
    const int b_c = ((lane >> 3) & 1) << 3;

    // ---- stage Q into dedicated smem region (stays resident) ----
    {
        const __nv_bfloat16* Qhg = Qh_ + hoff + (size_t)q0 * HD;
        const __nv_bfloat16* Qlg = Ql_ + hoff + (size_t)q0 * HD;
        #pragma unroll
        for (int c = 0; c < 4; c++) {
            const int ch = tid + c * 256;            // 0..1023
            const int row = ch >> 3, c16 = ch & 7;
            CP_ASYNC16(s0 + row * 144 + c16 * 16, Qhg + row * 64 + c16 * 8);
            CP_ASYNC16(s0 + QONE + row * 144 + c16 * 16, Qlg + row * 64 + c16 * 8);
        }
        CP_COMMIT();
    }

    // byte-generic sources: Kh, Kl (bf16), Vh, Vl (fp16) — all 2B/elem
    const char* gs0 = (const char*)(Kh_ + hoff);
    const char* gs1 = (const char*)(Kl_ + hoff);
    const char* gs2 = (const char*)(Vh_ + hoff);
    const char* gs3 = (const char*)(Vl_ + hoff);

    auto load_stage = [&](int s) {
        const int kv0 = s << 6;
        const uint32_t sb = stg + (s & 1) * ASTAGE;
        const char* gs[4] = { gs0, gs1, gs2, gs3 };
        #pragma unroll
        for (int a = 0; a < 4; a++) {
            #pragma unroll
            for (int c = 0; c < 2; c++) {
                const int ch = tid + c * 256;        // 0..511
                const int row = ch >> 3, c16 = ch & 7;
                CP_ASYNC16(sb + a * AARR + row * 144 + c16 * 16,
                           gs[a] + (size_t)(kv0 + row) * 128 + c16 * 16);
            }
        }
    };

    load_stage(0); CP_COMMIT();

    // Q-hi fragments resident in registers; Q-lo reloaded per tile.
    CP_WAIT0();            // Q + stage 0 landed
    __syncthreads();
    uint32_t qfh[4][4];
    const uint32_t qbase = ((wid * 16 + a_r) * ASTRIDE + a_c) * 2;
    #pragma unroll
    for (int t4 = 0; t4 < 4; t4++)
        ldm_x4(qfh[t4], s0 + qbase + t4 * 32);
    __syncthreads();

    float m0r = -1e30f, m1r = -1e30f, l0 = 0.f, l1 = 0.f;
    float O[8][4];
    #pragma unroll
    for (int j = 0; j < 8; j++)
        #pragma unroll
        for (int e = 0; e < 4; e++) O[j][e] = 0.f;

    for (int t = 0; t < SEQ / 64; t++) {
        if (t > 0) { CP_WAIT0(); __syncthreads(); }
        if (t + 1 < SEQ / 64) { load_stage(t + 1); CP_COMMIT(); }

        const uint32_t sb = stg + (t & 1) * ASTAGE;

        // ---- S = Q K^T (bf16x3; Q-lo frags prefetched one t4 ahead) ----
        float S[8][4];
        #pragma unroll
        for (int j = 0; j < 8; j++)
            #pragma unroll
            for (int e = 0; e < 4; e++) S[j][e] = 0.f;

        uint32_t qfl[4], qfln[4];
        ldm_x4(qfl, s0 + QONE + qbase);             // t4=0
        #pragma unroll
        for (int t4 = 0; t4 < 4; t4++) {
            if (t4 < 3)
                ldm_x4(qfln, s0 + QONE + qbase + (t4 + 1) * 32);
            #pragma unroll
            for (int jp = 0; jp < 4; jp++) {
                uint32_t bh[4], bl[4];
                const uint32_t off = ((16 * jp + b_r) * ASTRIDE + 16 * t4 + b_c) * 2;
                ldm_x4(bh, sb + off);
                ldm_x4(bl, sb + AARR + off);
                mma_bf16(S[2*jp],   qfh[t4], &bh[0]);
                mma_bf16(S[2*jp+1], qfh[t4], &bh[2]);
                mma_bf16(S[2*jp],   qfh[t4], &bl[0]);
                mma_bf16(S[2*jp+1], qfh[t4], &bl[2]);
                mma_bf16(S[2*jp],   qfl,     &bh[0]);
                mma_bf16(S[2*jp+1], qfl,     &bh[2]);
            }
            qfl[0] = qfln[0]; qfl[1] = qfln[1];
            qfl[2] = qfln[2]; qfl[3] = qfln[3];
        }

        // ---- online softmax (scale pre-folded; bare exp2) ----
        float corr0, corr1;
        {
            float tm = S[0][0];
            #pragma unroll
            for (int j = 0; j < 8; j++) tm = fmaxf(tm, fmaxf(S[j][0], S[j][1]));
            tm = fmaxf(tm, __shfl_xor_sync(0xffffffffu, tm, 1));
            tm = fmaxf(tm, __shfl_xor_sync(0xffffffffu, tm, 2));
            const float mnew = fmaxf(m0r, tm);
            corr0 = ex2(m0r - mnew);
            float rs = 0.f;
            #pragma unroll
            for (int j = 0; j < 8; j++) {
                S[j][0] = ex2(S[j][0] - mnew);
                S[j][1] = ex2(S[j][1] - mnew);
                rs += S[j][0] + S[j][1];
            }
            rs += __shfl_xor_sync(0xffffffffu, rs, 1);
            rs += __shfl_xor_sync(0xffffffffu, rs, 2);
            l0 = l0 * corr0 + rs;
            m0r = mnew;
        }
        {
            float tm = S[0][2];
            #pragma unroll
            for (int j = 0; j < 8; j++) tm = fmaxf(tm, fmaxf(S[j][2], S[j][3]));
            tm = fmaxf(tm, __shfl_xor_sync(0xffffffffu, tm, 1));
            tm = fmaxf(tm, __shfl_xor_sync(0xffffffffu, tm, 2));
            const float mnew = fmaxf(m1r, tm);
            corr1 = ex2(m1r - mnew);
            float rs = 0.f;
            #pragma unroll
            for (int j = 0; j < 8; j++) {
                S[j][2] = ex2(S[j][2] - mnew);
                S[j][3] = ex2(S[j][3] - mnew);
                rs += S[j][2] + S[j][3];
            }
            rs += __shfl_xor_sync(0xffffffffu, rs, 1);
            rs += __shfl_xor_sync(0xffffffffu, rs, 2);
            l1 = l1 * corr1 + rs;
            m1r = mnew;
        }

        // ---- pack P to fp16 A-fragments (single array; no hi/lo split) ----
        uint32_t pa[4][4];
        #pragma unroll
        for (int t4 = 0; t4 < 4; t4++) {
            pa[t4][0] = pack_f16(S[2*t4][0],   S[2*t4][1]);
            pa[t4][1] = pack_f16(S[2*t4][2],   S[2*t4][3]);
            pa[t4][2] = pack_f16(S[2*t4+1][0], S[2*t4+1][1]);
            pa[t4][3] = pack_f16(S[2*t4+1][2], S[2*t4+1][3]);
        }

        // ---- rescale O ----
        #pragma unroll
        for (int j = 0; j < 8; j++) {
            O[j][0] *= corr0; O[j][1] *= corr0;
            O[j][2] *= corr1; O[j][3] *= corr1;
        }

        // ---- O += P V (fp16 2-term: P*Vh + P*Vl) ----
        #pragma unroll
        for (int t4 = 0; t4 < 4; t4++) {
            #pragma unroll
            for (int jp = 0; jp < 4; jp++) {
                uint32_t vh[4], vl[4];
                const uint32_t off =
                    ((16 * t4 + (lane & 15)) * ASTRIDE + 16 * jp + a_c) * 2;
                ldm_x4_t(vh, sb + 2 * AARR + off);
                ldm_x4_t(vl, sb + 3 * AARR + off);
                mma_f16(O[2*jp],   pa[t4], &vh[0]);
                mma_f16(O[2*jp+1], pa[t4], &vh[2]);
                mma_f16(O[2*jp],   pa[t4], &vl[0]);
                mma_f16(O[2*jp+1], pa[t4], &vl[2]);
            }
        }
    }

    // ---- epilogue: scale by 1/l, write bf16 hi/lo in [N, K, H*D] layout ----
    const float inv0 = frcp(l0), inv1 = frcp(l1);
    #pragma unroll
    for (int j = 0; j < 8; j++) {
        const int col = h * 64 + 8 * j + ((lane & 3) << 1);
        #pragma unroll
        for (int half = 0; half < 2; half++) {
            const int row = q0 + wid * 16 + (lane >> 2) + half * 8;
            const float inv = half ? inv1 : inv0;
            const float y0 = O[j][half * 2 + 0] * inv;
            const float y1 = O[j][half * 2 + 1] * inv;
            const size_t idx = ((size_t)(n * SEQ) + row) * DM + col;
            uint32_t hi, lo;
            split2(y0, y1, hi, lo);
            *(uint32_t*)&Yh[idx] = hi;
            *(uint32_t*)&Yl[idx] = lo;
        }
    }
}

// ---------------------------------------------------------------------------
extern "C" void kernel_launch(void* const* d_in, const int* in_sizes, int n_in,
                              void* d_out, int out_size)
{
    const float* q  = (const float*)d_in[0];
    const float* k  = (const float*)d_in[1];
    const float* v  = (const float*)d_in[2];
    const float* Wq = (const float*)d_in[3];
    const float* bq = (const float*)d_in[4];
    const float* Wk = (const float*)d_in[5];
    const float* bk = (const float*)d_in[6];
    const float* Wv = (const float*)d_in[7];
    const float* bv = (const float*)d_in[8];
    const float* Wo = (const float*)d_in[9];
    const float* bo = (const float*)d_in[10];
    float* out = (float*)d_out;

    __nv_bfloat16 *xh, *xl, *wh, *wl, *yh, *yl, *qh, *ql, *kh, *kl;
    __half *vh, *vl;
    cudaGetSymbolAddress((void**)&xh, g_xh);
    cudaGetSymbolAddress((void**)&xl, g_xl);
    cudaGetSymbolAddress((void**)&wh, g_wh);
    cudaGetSymbolAddress((void**)&wl, g_wl);
    cudaGetSymbolAddress((void**)&yh, g_yh);
    cudaGetSymbolAddress((void**)&yl, g_yl);
    cudaGetSymbolAddress((void**)&qh, g_qh);
    cudaGetSymbolAddress((void**)&ql, g_ql);
    cudaGetSymbolAddress((void**)&kh, g_kh);
    cudaGetSymbolAddress((void**)&kl, g_kl);
    cudaGetSymbolAddress((void**)&vh, g_vh);
    cudaGetSymbolAddress((void**)&vl, g_vl);

    const size_t XN = (size_t)ROWS * DM;
    const size_t WN = (size_t)DM * DM;

    { const dim3 gi((unsigned)(XN/4/256), 1, 3);
      split_in<<<gi, 256>>>((const float4*)q, (const float4*)k, (const float4*)v); }
    { const dim3 gw((unsigned)(WN/4/256), 1, 4);
      split_w<<<gw, 256>>>((const float4*)Wq, (const float4*)Wk,
                           (const float4*)Wv, (const float4*)Wo); }

    const int gsmem = 2 * STAGE_BYTES;
    cudaFuncSetAttribute((const void*)gemm_qkv,
                         cudaFuncAttributeMaxDynamicSharedMemorySize, gsmem);
    cudaFuncSetAttribute((const void*)gemm_out,
                         cudaFuncAttributeMaxDynamicSharedMemorySize, gsmem);
    const dim3 gq(DM/128, ROWS/128, 3);
    gemm_qkv<<<gq, 256, gsmem>>>(xh, xl, wh, wl, bq, bk, bv);

    const int asmem = QARR + 2 * ASTAGE;   // 110592
    cudaFuncSetAttribute((const void*)attn_mma,
                         cudaFuncAttributeMaxDynamicSharedMemorySize, asmem);
    const dim3 ga(SEQ/128, NH*NB);  // (16, 32)
    attn_mma<<<ga, 256, asmem>>>(qh, ql, kh, kl, vh, vl, yh, yl);

    const dim3 gg(DM/128, ROWS/128);
    gemm_out<<<gg, 256, gsmem>>>(yh, yl, wh + 3*WN, wl + 3*WN, bo, out);
}

// round 11
// speedup vs baseline: 3.7950x; 1.0569x over previous
#include <cuda_runtime.h>
#include <cuda_bf16.h>
#include <cuda_fp16.h>
#include <cstdint>

#define NB   2
#define SEQ  2048
#define DM   1024
#define NH   16
#define HD   64
#define ROWS (NB*SEQ)          // 4096
// softmax scale 1/sqrt(64) folded into Q projection together with log2(e):
#define QSCALE 0.18033688011112042f   // 0.125 * log2(e)

// ---------------------------------------------------------------------------
// Scratch (allocation-free: __device__ globals)
// ---------------------------------------------------------------------------
#define PROJN ((size_t)NH*NB*SEQ*HD)     // 4M elems
__device__ __align__(256) __half g_qf[PROJN];                       // fp16 Q (single)
__device__ __align__(256) __half g_kh[PROJN], g_kl[PROJN];          // fp16 K hi/lo
__device__ __align__(256) __half g_vh[PROJN], g_vl[PROJN];          // fp16 V hi/lo
__device__ __align__(256) __nv_bfloat16 g_xh[3][(size_t)ROWS*DM];
__device__ __align__(256) __nv_bfloat16 g_xl[3][(size_t)ROWS*DM];
__device__ __align__(256) __nv_bfloat16 g_wh[4][(size_t)DM*DM];
__device__ __align__(256) __nv_bfloat16 g_wl[4][(size_t)DM*DM];
__device__ __align__(256) __nv_bfloat16 g_yh[(size_t)ROWS*DM];
__device__ __align__(256) __nv_bfloat16 g_yl[(size_t)ROWS*DM];

// ---------------------------------------------------------------------------
// PTX helpers (baseline sm_80+ features: mma.sync / ldmatrix / cp.async)
// ---------------------------------------------------------------------------
__device__ __forceinline__ uint32_t smem_u32(const void* p) {
    uint32_t a;
    asm("{ .reg .u64 t; cvta.to.shared.u64 t, %1; cvt.u32.u64 %0, t; }"
        : "=r"(a) : "l"(p));
    return a;
}

#define CP_ASYNC16(dst, src) \
    asm volatile("cp.async.cg.shared.global [%0], [%1], 16;" :: "r"(dst), "l"(src))
#define CP_COMMIT() asm volatile("cp.async.commit_group;" ::: "memory")
#define CP_WAIT0()  asm volatile("cp.async.wait_group 0;" ::: "memory")

__device__ __forceinline__ void ldm_x4(uint32_t* r, uint32_t addr) {
    asm volatile("ldmatrix.sync.aligned.m8n8.x4.shared.b16 {%0,%1,%2,%3}, [%4];"
                 : "=r"(r[0]), "=r"(r[1]), "=r"(r[2]), "=r"(r[3]) : "r"(addr));
}
__device__ __forceinline__ void ldm_x4_t(uint32_t* r, uint32_t addr) {
    asm volatile("ldmatrix.sync.aligned.m8n8.x4.trans.shared.b16 {%0,%1,%2,%3}, [%4];"
                 : "=r"(r[0]), "=r"(r[1]), "=r"(r[2]), "=r"(r[3]) : "r"(addr));
}

__device__ __forceinline__ void mma_bf16(float* d, const uint32_t* a, const uint32_t* b) {
    asm volatile(
        "mma.sync.aligned.m16n8k16.row.col.f32.bf16.bf16.f32 "
        "{%0,%1,%2,%3}, {%4,%5,%6,%7}, {%8,%9}, {%0,%1,%2,%3};"
        : "+f"(d[0]), "+f"(d[1]), "+f"(d[2]), "+f"(d[3])
        : "r"(a[0]), "r"(a[1]), "r"(a[2]), "r"(a[3]), "r"(b[0]), "r"(b[1]));
}
__device__ __forceinline__ void mma_f16(float* d, const uint32_t* a, const uint32_t* b) {
    asm volatile(
        "mma.sync.aligned.m16n8k16.row.col.f32.f16.f16.f32 "
        "{%0,%1,%2,%3}, {%4,%5,%6,%7}, {%8,%9}, {%0,%1,%2,%3};"
        : "+f"(d[0]), "+f"(d[1]), "+f"(d[2]), "+f"(d[3])
        : "r"(a[0]), "r"(a[1]), "r"(a[2]), "r"(a[3]), "r"(b[0]), "r"(b[1]));
}

// fast exp2 / rcp via MUFU
__device__ __forceinline__ float ex2(float x) {
    float r; asm("ex2.approx.f32 %0, %1;" : "=f"(r) : "f"(x)); return r;
}
__device__ __forceinline__ float frcp(float x) {
    float r; asm("rcp.approx.f32 %0, %1;" : "=f"(r) : "f"(x)); return r;
}

// fp32 pair -> packed bf16x2 hi + bf16x2 lo  (a in low half)
__device__ __forceinline__ void split2(float a, float b, uint32_t& hi, uint32_t& lo) {
    asm("cvt.rn.bf16x2.f32 %0, %1, %2;" : "=r"(hi) : "f"(b), "f"(a));
    const float ha = __uint_as_float(hi << 16);
    const float hb = __uint_as_float(hi & 0xffff0000u);
    const float la = a - ha, lb = b - hb;
    asm("cvt.rn.bf16x2.f32 %0, %1, %2;" : "=r"(lo) : "f"(lb), "f"(la));
}
// fp32 pair -> packed f16x2 (a in low half)
__device__ __forceinline__ uint32_t pack_f16(float a, float b) {
    uint32_t r; asm("cvt.rn.f16x2.f32 %0, %1, %2;" : "=r"(r) : "f"(b), "f"(a));
    return r;
}
// fp32 pair -> f16x2 hi + f16x2 lo
__device__ __forceinline__ void split2h(float a, float b, uint32_t& hi, uint32_t& lo) {
    hi = pack_f16(a, b);
    __half2 h = *(__half2*)&hi;
    const float la = a - __half2float(h.x);
    const float lb = b - __half2float(h.y);
    lo = pack_f16(la, lb);
}

// ---------------------------------------------------------------------------
// fp32 -> bf16 hi/lo splits (merged launches; z selects tensor)
// ---------------------------------------------------------------------------
__global__ void __launch_bounds__(256) split_in(
    const float4* __restrict__ q, const float4* __restrict__ k,
    const float4* __restrict__ v)
{
    const int z = blockIdx.z;
    const size_t XN4 = (size_t)ROWS * DM / 4;
    const float4* src = (z == 0) ? q : (z == 1) ? k : v;
    uint32_t* hp = (uint32_t*)(g_xh[z]);
    uint32_t* lp = (uint32_t*)(g_xl[z]);
    const size_t i = blockIdx.x * 256 + threadIdx.x;
    if (i >= XN4) return;
    float4 vv = src[i];
    uint32_t h0, l0, h1, l1;
    split2(vv.x, vv.y, h0, l0);
    split2(vv.z, vv.w, h1, l1);
    hp[2*i] = h0; hp[2*i+1] = h1;
    lp[2*i] = l0; lp[2*i+1] = l1;
}

__global__ void __launch_bounds__(256) split_w(
    const float4* __restrict__ wq, const float4* __restrict__ wk,
    const float4* __restrict__ wv, const float4* __restrict__ wo)
{
    const int z = blockIdx.z;
    const size_t WN4 = (size_t)DM * DM / 4;
    const float4* src = (z == 0) ? wq : (z == 1) ? wk : (z == 2) ? wv : wo;
    uint32_t* hp = (uint32_t*)(g_wh[z]);
    uint32_t* lp = (uint32_t*)(g_wl[z]);
    const size_t i = blockIdx.x * 256 + threadIdx.x;
    if (i >= WN4) return;
    float4 vv = src[i];
    uint32_t h0, l0, h1, l1;
    split2(vv.x, vv.y, h0, l0);
    split2(vv.z, vv.w, h1, l1);
    hp[2*i] = h0; hp[2*i+1] = h1;
    lp[2*i] = l0; lp[2*i+1] = l1;
}

// ---------------------------------------------------------------------------
// HMMA bf16x3 NT GEMM core, CTA 128x128, BK=32, 8 warps (2x4), warp 64x32.
// Double-buffered cp.async, ONE sync per stage, 2 CTAs/SM.
// MODE 0: fp32 C row-major; MODE 3: fp16 hi/lo QKV scatter;
// MODE 4: fp16 single QKV scatter (for Q).
// ---------------------------------------------------------------------------
#define GSTRIDE 40
#define ARR_BYTES (128 * GSTRIDE * 2)
#define STAGE_BYTES (4 * ARR_BYTES)
#define NSTAGE (DM / 32)

template<int MODE>
__device__ __forceinline__ void gemm_body(
    const __nv_bfloat16* __restrict__ Ah, const __nv_bfloat16* __restrict__ Al,
    const __nv_bfloat16* __restrict__ Bh, const __nv_bfloat16* __restrict__ Bl,
    const float* __restrict__ bias, float* __restrict__ C,
    void* __restrict__ Ch, void* __restrict__ Cl,
    float oscale)
{
    extern __shared__ __align__(128) char smraw[];
    const uint32_t smem0 = smem_u32(smraw);

    const int tid = threadIdx.x;
    const int lane = tid & 31;
    const int wid = tid >> 5;
    const int wm = wid >> 2;
    const int wn = wid & 3;

    const int m0 = blockIdx.y << 7;
    const int n0 = blockIdx.x << 7;

    const __nv_bfloat16* gsrc[4] = {
        Ah + (size_t)m0 * DM, Al + (size_t)m0 * DM,
        Bh + (size_t)n0 * DM, Bl + (size_t)n0 * DM
    };

    const int r0c = tid >> 2, cc0 = tid & 3;
    const int r1c = r0c + 64;

    auto load_stage = [&](int s) {
        const int kk = s * 32;
        const uint32_t sb = smem0 + (s & 1) * STAGE_BYTES;
        #pragma unroll
        for (int a = 0; a < 4; a++) {
            const __nv_bfloat16* g = gsrc[a];
            const uint32_t ab = sb + a * ARR_BYTES;
            CP_ASYNC16(ab + r0c * (GSTRIDE*2) + cc0 * 16,
                       g + (size_t)r0c * DM + kk + cc0 * 8);
            CP_ASYNC16(ab + r1c * (GSTRIDE*2) + cc0 * 16,
                       g + (size_t)r1c * DM + kk + cc0 * 8);
        }
    };

    float acc[4][4][4];
    #pragma unroll
    for (int i = 0; i < 4; i++)
        #pragma unroll
        for (int j = 0; j < 4; j++)
            #pragma unroll
            for (int e = 0; e < 4; e++) acc[i][j][e] = 0.f;

    const int a_r = lane & 15, a_c = (lane >> 4) << 3;
    const int b_r = (lane & 7) + (((lane >> 3) & 2) << 2);
    const int b_c = ((lane >> 3) & 1) << 3;

    load_stage(0);
    CP_COMMIT();

    for (int s = 0; s < NSTAGE; s++) {
        CP_WAIT0();
        __syncthreads();
        if (s + 1 < NSTAGE) { load_stage(s + 1); CP_COMMIT(); }

        const uint32_t sb = smem0 + (s & 1) * STAGE_BYTES;
        const uint32_t sAh = sb;
        const uint32_t sAl = sb + ARR_BYTES;
        const uint32_t sBh = sb + 2 * ARR_BYTES;
        const uint32_t sBl = sb + 3 * ARR_BYTES;

        #pragma unroll
        for (int k16 = 0; k16 < 2; k16++) {
            const int kc = k16 * 16;
            uint32_t bh[2][4], bl[2][4];
            #pragma unroll
            for (int np = 0; np < 2; np++) {
                const uint32_t off =
                    ((wn * 32 + np * 16 + b_r) * GSTRIDE + kc + b_c) * 2;
                ldm_x4(bh[np], sBh + off);
                ldm_x4(bl[np], sBl + off);
            }
            #pragma unroll
            for (int mt = 0; mt < 4; mt++) {
                uint32_t ah[4], al[4];
                const uint32_t off =
                    ((wm * 64 + mt * 16 + a_r) * GSTRIDE + kc + a_c) * 2;
                ldm_x4(ah, sAh + off);
                ldm_x4(al, sAl + off);
                #pragma unroll
                for (int nt = 0; nt < 4; nt++)
                    mma_bf16(acc[mt][nt], ah, &bh[nt >> 1][(nt & 1) * 2]);
                #pragma unroll
                for (int nt = 0; nt < 4; nt++)
                    mma_bf16(acc[mt][nt], ah, &bl[nt >> 1][(nt & 1) * 2]);
                #pragma unroll
                for (int nt = 0; nt < 4; nt++)
                    mma_bf16(acc[mt][nt], al, &bh[nt >> 1][(nt & 1) * 2]);
            }
        }
    }

    #pragma unroll
    for (int mt = 0; mt < 4; mt++) {
        #pragma unroll
        for (int nt = 0; nt < 4; nt++) {
            const int col = n0 + wn * 32 + nt * 8 + ((lane & 3) << 1);
            const float b0 = bias[col], b1 = bias[col + 1];
            #pragma unroll
            for (int half = 0; half < 2; half++) {
                const int row = m0 + wm * 64 + mt * 16 + (lane >> 2) + half * 8;
                const float vx = (acc[mt][nt][half * 2 + 0] + b0) * oscale;
                const float vy = (acc[mt][nt][half * 2 + 1] + b1) * oscale;
                if (MODE == 0) {
                    float2 v; v.x = vx; v.y = vy;
                    *(float2*)&C[(size_t)row * DM + col] = v;
                } else {
                    const int h = col >> 6, d = col & 63;
                    const int nb = row >> 11, kq = row & 2047;
                    const size_t idx = (((size_t)(h * NB + nb)) * SEQ + kq) * HD + d;
                    if (MODE == 3) {
                        uint32_t hi, lo;
                        split2h(vx, vy, hi, lo);
                        *(uint32_t*)&((__half*)Ch)[idx] = hi;
                        *(uint32_t*)&((__half*)Cl)[idx] = lo;
                    } else {       // MODE 4: single fp16
                        *(uint32_t*)&((__half*)Ch)[idx] = pack_f16(vx, vy);
                    }
                }
            }
        }
    }
}

__global__ void __launch_bounds__(256, 2) gemm_qkv(
    const __nv_bfloat16* __restrict__ xh, const __nv_bfloat16* __restrict__ xl,
    const __nv_bfloat16* __restrict__ wh, const __nv_bfloat16* __restrict__ wl,
    const float* __restrict__ bq, const float* __restrict__ bk,
    const float* __restrict__ bv)
{
    const int z = blockIdx.z;
    const size_t XN = (size_t)ROWS * DM, WN = (size_t)DM * DM;
    if (z == 0) {
        gemm_body<4>(xh, xl, wh, wl, bq, nullptr, g_qf, nullptr, QSCALE);
    } else if (z == 1) {
        gemm_body<3>(xh + XN, xl + XN, wh + WN, wl + WN, bk, nullptr,
                     g_kh, g_kl, 1.f);
    } else {
        gemm_body<3>(xh + 2*XN, xl + 2*XN, wh + 2*WN, wl + 2*WN, bv, nullptr,
                     g_vh, g_vl, 1.f);
    }
}

__global__ void __launch_bounds__(256, 2) gemm_out(
    const __nv_bfloat16* __restrict__ Ah, const __nv_bfloat16* __restrict__ Al,
    const __nv_bfloat16* __restrict__ Bh, const __nv_bfloat16* __restrict__ Bl,
    const float* __restrict__ bias, float* __restrict__ C)
{
    gemm_body<0>(Ah, Al, Bh, Bl, bias, C, nullptr, nullptr, 1.f);
}

// ---------------------------------------------------------------------------
// FA2-style HMMA attention, 2 CTAs/SM, all-fp16 MMA.
// S:  2-term fp16 (Qf*Kh + Qf*Kl)  — only Q's sub-fp16 bits dropped.
// PV: 2-term fp16 (P*Vh + P*Vl)    — anchored at rel_err 1.76e-4 (round 10).
// smem: [Qf 18432][stage0 36864][stage1 36864] = 92160 B.
// ---------------------------------------------------------------------------
#define ASTRIDE 72
#define AARR    (64 * ASTRIDE * 2)          // 9216 B
#define ASTAGE  (4 * AARR)                  // 36864 B
#define QONE    (128 * ASTRIDE * 2)         // 18432 B (single fp16 Q array)

__global__ void __launch_bounds__(256, 2) attn_mma(
    const __half* __restrict__ Qf_,
    const __half* __restrict__ Kh_, const __half* __restrict__ Kl_,
    const __half* __restrict__ Vh_, const __half* __restrict__ Vl_,
    __nv_bfloat16* __restrict__ Yh, __nv_bfloat16* __restrict__ Yl)
{
    extern __shared__ __align__(128) char smraw[];
    const uint32_t s0 = smem_u32(smraw);
    const uint32_t stg = s0 + QONE;          // stage base

    const int tid = threadIdx.x;
    const int lane = tid & 31;
    const int wid = tid >> 5;
    const int hn = blockIdx.y;
    const int h = hn >> 1, n = hn & 1;
    const int q0 = blockIdx.x << 7;
    const size_t hoff = (size_t)hn * SEQ * HD;

    const int a_r = lane & 15, a_c = (lane >> 4) << 3;
    const int b_r = (lane & 7) + (((lane >> 3) & 2) << 2);
    const int b_c = ((lane >> 3) & 1) << 3;

    // ---- stage Q (single fp16 array) into resident smem ----
    {
        const __half* Qg = Qf_ + hoff + (size_t)q0 * HD;
        #pragma unroll
        for (int c = 0; c < 4; c++) {
            const int ch = tid + c * 256;            // 0..1023
            const int row = ch >> 3, c16 = ch & 7;
            CP_ASYNC16(s0 + row * 144 + c16 * 16, Qg + row * 64 + c16 * 8);
        }
        CP_COMMIT();
    }

    const char* gs0 = (const char*)(Kh_ + hoff);
    const char* gs1 = (const char*)(Kl_ + hoff);
    const char* gs2 = (const char*)(Vh_ + hoff);
    const char* gs3 = (const char*)(Vl_ + hoff);

    auto load_stage = [&](int s) {
        const int kv0 = s << 6;
        const uint32_t sb = stg + (s & 1) * ASTAGE;
        const char* gs[4] = { gs0, gs1, gs2, gs3 };
        #pragma unroll
        for (int a = 0; a < 4; a++) {
            #pragma unroll
            for (int c = 0; c < 2; c++) {
                const int ch = tid + c * 256;        // 0..511
                const int row = ch >> 3, c16 = ch & 7;
                CP_ASYNC16(sb + a * AARR + row * 144 + c16 * 16,
                           gs[a] + (size_t)(kv0 + row) * 128 + c16 * 16);
            }
        }
    };

    load_stage(0); CP_COMMIT();

    // Q fragments resident in registers.
    CP_WAIT0();            // Q + stage 0 landed
    __syncthreads();
    uint32_t qf[4][4];
    const uint32_t qbase = ((wid * 16 + a_r) * ASTRIDE + a_c) * 2;
    #pragma unroll
    for (int t4 = 0; t4 < 4; t4++)
        ldm_x4(qf[t4], s0 + qbase + t4 * 32);

    float m0r = -1e30f, m1r = -1e30f, l0 = 0.f, l1 = 0.f;
    float O[8][4];
    #pragma unroll
    for (int j = 0; j < 8; j++)
        #pragma unroll
        for (int e = 0; e < 4; e++) O[j][e] = 0.f;

    for (int t = 0; t < SEQ / 64; t++) {
        if (t > 0) { CP_WAIT0(); __syncthreads(); }
        if (t + 1 < SEQ / 64) { load_stage(t + 1); CP_COMMIT(); }

        const uint32_t sb = stg + (t & 1) * ASTAGE;

        // ---- S = Q K^T (fp16 2-term: Qf*Kh + Qf*Kl) ----
        float S[8][4];
        #pragma unroll
        for (int j = 0; j < 8; j++)
            #pragma unroll
            for (int e = 0; e < 4; e++) S[j][e] = 0.f;

        #pragma unroll
        for (int t4 = 0; t4 < 4; t4++) {
            #pragma unroll
            for (int jp = 0; jp < 4; jp++) {
                uint32_t bh[4], bl[4];
                const uint32_t off = ((16 * jp + b_r) * ASTRIDE + 16 * t4 + b_c) * 2;
                ldm_x4(bh, sb + off);
                ldm_x4(bl, sb + AARR + off);
                mma_f16(S[2*jp],   qf[t4], &bh[0]);
                mma_f16(S[2*jp+1], qf[t4], &bh[2]);
                mma_f16(S[2*jp],   qf[t4], &bl[0]);
                mma_f16(S[2*jp+1], qf[t4], &bl[2]);
            }
        }

        // ---- online softmax (scale pre-folded; bare exp2) ----
        float corr0, corr1;
        {
            float tm = S[0][0];
            #pragma unroll
            for (int j = 0; j < 8; j++) tm = fmaxf(tm, fmaxf(S[j][0], S[j][1]));
            tm = fmaxf(tm, __shfl_xor_sync(0xffffffffu, tm, 1));
            tm = fmaxf(tm, __shfl_xor_sync(0xffffffffu, tm, 2));
            const float mnew = fmaxf(m0r, tm);
            corr0 = ex2(m0r - mnew);
            float rs = 0.f;
            #pragma unroll
            for (int j = 0; j < 8; j++) {
                S[j][0] = ex2(S[j][0] - mnew);
                S[j][1] = ex2(S[j][1] - mnew);
                rs += S[j][0] + S[j][1];
            }
            rs += __shfl_xor_sync(0xffffffffu, rs, 1);
            rs += __shfl_xor_sync(0xffffffffu, rs, 2);
            l0 = l0 * corr0 + rs;
            m0r = mnew;
        }
        {
            float tm = S[0][2];
            #pragma unroll
            for (int j = 0; j < 8; j++) tm = fmaxf(tm, fmaxf(S[j][2], S[j][3]));
            tm = fmaxf(tm, __shfl_xor_sync(0xffffffffu, tm, 1));
            tm = fmaxf(tm, __shfl_xor_sync(0xffffffffu, tm, 2));
            const float mnew = fmaxf(m1r, tm);
            corr1 = ex2(m1r - mnew);
            float rs = 0.f;
            #pragma unroll
            for (int j = 0; j < 8; j++) {
                S[j][2] = ex2(S[j][2] - mnew);
                S[j][3] = ex2(S[j][3] - mnew);
                rs += S[j][2] + S[j][3];
            }
            rs += __shfl_xor_sync(0xffffffffu, rs, 1);
            rs += __shfl_xor_sync(0xffffffffu, rs, 2);
            l1 = l1 * corr1 + rs;
            m1r = mnew;
        }

        // ---- pack P to fp16 A-fragments ----
        uint32_t pa[4][4];
        #pragma unroll
        for (int t4 = 0; t4 < 4; t4++) {
            pa[t4][0] = pack_f16(S[2*t4][0],   S[2*t4][1]);
            pa[t4][1] = pack_f16(S[2*t4][2],   S[2*t4][3]);
            pa[t4][2] = pack_f16(S[2*t4+1][0], S[2*t4+1][1]);
            pa[t4][3] = pack_f16(S[2*t4+1][2], S[2*t4+1][3]);
        }

        // ---- rescale O ----
        #pragma unroll
        for (int j = 0; j < 8; j++) {
            O[j][0] *= corr0; O[j][1] *= corr0;
            O[j][2] *= corr1; O[j][3] *= corr1;
        }

        // ---- O += P V (fp16 2-term: P*Vh + P*Vl) ----
        #pragma unroll
        for (int t4 = 0; t4 < 4; t4++) {
            #pragma unroll
            for (int jp = 0; jp < 4; jp++) {
                uint32_t vh[4], vl[4];
                const uint32_t off =
                    ((16 * t4 + (lane & 15)) * ASTRIDE + 16 * jp + a_c) * 2;
                ldm_x4_t(vh, sb + 2 * AARR + off);
                ldm_x4_t(vl, sb + 3 * AARR + off);
                mma_f16(O[2*jp],   pa[t4], &vh[0]);
                mma_f16(O[2*jp+1], pa[t4], &vh[2]);
                mma_f16(O[2*jp],   pa[t4], &vl[0]);
                mma_f16(O[2*jp+1], pa[t4], &vl[2]);
            }
        }
    }

    // ---- epilogue: scale by 1/l, write bf16 hi/lo in [N, K, H*D] layout ----
    const float inv0 = frcp(l0), inv1 = frcp(l1);
    #pragma unroll
    for (int j = 0; j < 8; j++) {
        const int col = h * 64 + 8 * j + ((lane & 3) << 1);
        #pragma unroll
        for (int half = 0; half < 2; half++) {
            const int row = q0 + wid * 16 + (lane >> 2) + half * 8;
            const float inv = half ? inv1 : inv0;
            const float y0 = O[j][half * 2 + 0] * inv;
            const float y1 = O[j][half * 2 + 1] * inv;
            const size_t idx = ((size_t)(n * SEQ) + row) * DM + col;
            uint32_t hi, lo;
            split2(y0, y1, hi, lo);
            *(uint32_t*)&Yh[idx] = hi;
            *(uint32_t*)&Yl[idx] = lo;
        }
    }
}

// ---------------------------------------------------------------------------
extern "C" void kernel_launch(void* const* d_in, const int* in_sizes, int n_in,
                              void* d_out, int out_size)
{
    const float* q  = (const float*)d_in[0];
    const float* k  = (const float*)d_in[1];
    const float* v  = (const float*)d_in[2];
    const float* Wq = (const float*)d_in[3];
    const float* bq = (const float*)d_in[4];
    const float* Wk = (const float*)d_in[5];
    const float* bk = (const float*)d_in[6];
    const float* Wv = (const float*)d_in[7];
    const float* bv = (const float*)d_in[8];
    const float* Wo = (const float*)d_in[9];
    const float* bo = (const float*)d_in[10];
    float* out = (float*)d_out;

    __nv_bfloat16 *xh, *xl, *wh, *wl, *yh, *yl;
    __half *qf, *kh, *kl, *vh, *vl;
    cudaGetSymbolAddress((void**)&xh, g_xh);
    cudaGetSymbolAddress((void**)&xl, g_xl);
    cudaGetSymbolAddress((void**)&wh, g_wh);
    cudaGetSymbolAddress((void**)&wl, g_wl);
    cudaGetSymbolAddress((void**)&yh, g_yh);
    cudaGetSymbolAddress((void**)&yl, g_yl);
    cudaGetSymbolAddress((void**)&qf, g_qf);
    cudaGetSymbolAddress((void**)&kh, g_kh);
    cudaGetSymbolAddress((void**)&kl, g_kl);
    cudaGetSymbolAddress((void**)&vh, g_vh);
    cudaGetSymbolAddress((void**)&vl, g_vl);

    const size_t XN = (size_t)ROWS * DM;
    const size_t WN = (size_t)DM * DM;

    { const dim3 gi((unsigned)(XN/4/256), 1, 3);
      split_in<<<gi, 256>>>((const float4*)q, (const float4*)k, (const float4*)v); }
    { const dim3 gw((unsigned)(WN/4/256), 1, 4);
      split_w<<<gw, 256>>>((const float4*)Wq, (const float4*)Wk,
                           (const float4*)Wv, (const float4*)Wo); }

    const int gsmem = 2 * STAGE_BYTES;
    cudaFuncSetAttribute((const void*)gemm_qkv,
                         cudaFuncAttributeMaxDynamicSharedMemorySize, gsmem);
    cudaFuncSetAttribute((const void*)gemm_out,
                         cudaFuncAttributeMaxDynamicSharedMemorySize, gsmem);
    const dim3 gq(DM/128, ROWS/128, 3);
    gemm_qkv<<<gq, 256, gsmem>>>(xh, xl, wh, wl, bq, bk, bv);

    const int asmem = QONE + 2 * ASTAGE;   // 18432 + 73728 = 92160
    cudaFuncSetAttribute((const void*)attn_mma,
                         cudaFuncAttributeMaxDynamicSharedMemorySize, asmem);
    const dim3 ga(SEQ/128, NH*NB);  // (16, 32)
    attn_mma<<<ga, 256, asmem>>>(qf, kh, kl, vh, vl, yh, yl);

    const dim3 gg(DM/128, ROWS/128);
    gemm_out<<<gg, 256, gsmem>>>(yh, yl, wh + 3*WN, wl + 3*WN, bo, out);
}

// round 12
// speedup vs baseline: 4.3856x; 1.1556x over previous
#include <cuda_runtime.h>
#include <cuda_bf16.h>
#include <cuda_fp16.h>
#include <cstdint>

#define NB   2
#define SEQ  2048
#define DM   1024
#define NH   16
#define HD   64
#define ROWS (NB*SEQ)          // 4096
// softmax scale 1/sqrt(64) folded into Q projection together with log2(e):
#define QSCALE 0.18033688011112042f   // 0.125 * log2(e)

// ---------------------------------------------------------------------------
// Scratch (allocation-free: __device__ globals)
// ---------------------------------------------------------------------------
#define PROJN ((size_t)NH*NB*SEQ*HD)     // 4M elems
__device__ __align__(256) __half g_qf[PROJN];                       // fp16 Q (single)
__device__ __align__(256) __half g_kh[PROJN], g_kl[PROJN];          // fp16 K hi/lo
__device__ __align__(256) __half g_vh[PROJN], g_vl[PROJN];          // fp16 V hi/lo
__device__ __align__(256) __half g_xf[3][(size_t)ROWS*DM];          // fp16 inputs (single)
__device__ __align__(256) __half g_wfh[3][(size_t)DM*DM];           // fp16 Wq/Wk/Wv hi
__device__ __align__(256) __half g_wfl[3][(size_t)DM*DM];           // fp16 Wq/Wk/Wv lo
__device__ __align__(256) __nv_bfloat16 g_woh[(size_t)DM*DM];       // bf16 Wo hi
__device__ __align__(256) __nv_bfloat16 g_wol[(size_t)DM*DM];       // bf16 Wo lo
__device__ __align__(256) __nv_bfloat16 g_yh[(size_t)ROWS*DM];
__device__ __align__(256) __nv_bfloat16 g_yl[(size_t)ROWS*DM];

// ---------------------------------------------------------------------------
// PTX helpers (baseline sm_80+ features: mma.sync / ldmatrix / cp.async)
// ---------------------------------------------------------------------------
__device__ __forceinline__ uint32_t smem_u32(const void* p) {
    uint32_t a;
    asm("{ .reg .u64 t; cvta.to.shared.u64 t, %1; cvt.u32.u64 %0, t; }"
        : "=r"(a) : "l"(p));
    return a;
}

#define CP_ASYNC16(dst, src) \
    asm volatile("cp.async.cg.shared.global [%0], [%1], 16;" :: "r"(dst), "l"(src))
#define CP_COMMIT() asm volatile("cp.async.commit_group;" ::: "memory")
#define CP_WAIT0()  asm volatile("cp.async.wait_group 0;" ::: "memory")

__device__ __forceinline__ void ldm_x4(uint32_t* r, uint32_t addr) {
    asm volatile("ldmatrix.sync.aligned.m8n8.x4.shared.b16 {%0,%1,%2,%3}, [%4];"
                 : "=r"(r[0]), "=r"(r[1]), "=r"(r[2]), "=r"(r[3]) : "r"(addr));
}
__device__ __forceinline__ void ldm_x4_t(uint32_t* r, uint32_t addr) {
    asm volatile("ldmatrix.sync.aligned.m8n8.x4.trans.shared.b16 {%0,%1,%2,%3}, [%4];"
                 : "=r"(r[0]), "=r"(r[1]), "=r"(r[2]), "=r"(r[3]) : "r"(addr));
}

__device__ __forceinline__ void mma_bf16(float* d, const uint32_t* a, const uint32_t* b) {
    asm volatile(
        "mma.sync.aligned.m16n8k16.row.col.f32.bf16.bf16.f32 "
        "{%0,%1,%2,%3}, {%4,%5,%6,%7}, {%8,%9}, {%0,%1,%2,%3};"
        : "+f"(d[0]), "+f"(d[1]), "+f"(d[2]), "+f"(d[3])
        : "r"(a[0]), "r"(a[1]), "r"(a[2]), "r"(a[3]), "r"(b[0]), "r"(b[1]));
}
__device__ __forceinline__ void mma_f16(float* d, const uint32_t* a, const uint32_t* b) {
    asm volatile(
        "mma.sync.aligned.m16n8k16.row.col.f32.f16.f16.f32 "
        "{%0,%1,%2,%3}, {%4,%5,%6,%7}, {%8,%9}, {%0,%1,%2,%3};"
        : "+f"(d[0]), "+f"(d[1]), "+f"(d[2]), "+f"(d[3])
        : "r"(a[0]), "r"(a[1]), "r"(a[2]), "r"(a[3]), "r"(b[0]), "r"(b[1]));
}

// fast exp2 / rcp via MUFU
__device__ __forceinline__ float ex2(float x) {
    float r; asm("ex2.approx.f32 %0, %1;" : "=f"(r) : "f"(x)); return r;
}
__device__ __forceinline__ float frcp(float x) {
    float r; asm("rcp.approx.f32 %0, %1;" : "=f"(r) : "f"(x)); return r;
}

// fp32 pair -> packed bf16x2 hi + bf16x2 lo  (a in low half)
__device__ __forceinline__ void split2(float a, float b, uint32_t& hi, uint32_t& lo) {
    asm("cvt.rn.bf16x2.f32 %0, %1, %2;" : "=r"(hi) : "f"(b), "f"(a));
    const float ha = __uint_as_float(hi << 16);
    const float hb = __uint_as_float(hi & 0xffff0000u);
    const float la = a - ha, lb = b - hb;
    asm("cvt.rn.bf16x2.f32 %0, %1, %2;" : "=r"(lo) : "f"(lb), "f"(la));
}
// fp32 pair -> packed f16x2 (a in low half)
__device__ __forceinline__ uint32_t pack_f16(float a, float b) {
    uint32_t r; asm("cvt.rn.f16x2.f32 %0, %1, %2;" : "=r"(r) : "f"(b), "f"(a));
    return r;
}
// fp32 pair -> f16x2 hi + f16x2 lo
__device__ __forceinline__ void split2h(float a, float b, uint32_t& hi, uint32_t& lo) {
    hi = pack_f16(a, b);
    __half2 h = *(__half2*)&hi;
    const float la = a - __half2float(h.x);
    const float lb = b - __half2float(h.y);
    lo = pack_f16(la, lb);
}

// ---------------------------------------------------------------------------
// input split: fp32 -> fp16 single (z selects q/k/v)
// ---------------------------------------------------------------------------
__global__ void __launch_bounds__(256) split_in(
    const float4* __restrict__ q, const float4* __restrict__ k,
    const float4* __restrict__ v)
{
    const int z = blockIdx.z;
    const size_t XN4 = (size_t)ROWS * DM / 4;
    const float4* src = (z == 0) ? q : (z == 1) ? k : v;
    uint32_t* fp = (uint32_t*)(g_xf[z]);
    const size_t i = blockIdx.x * 256 + threadIdx.x;
    if (i >= XN4) return;
    float4 vv = src[i];
    fp[2*i]   = pack_f16(vv.x, vv.y);
    fp[2*i+1] = pack_f16(vv.z, vv.w);
}

// weight split: z<3 -> fp16 hi/lo (Wq/Wk/Wv); z=3 -> bf16 hi/lo (Wo)
__global__ void __launch_bounds__(256) split_w(
    const float4* __restrict__ wq, const float4* __restrict__ wk,
    const float4* __restrict__ wv, const float4* __restrict__ wo)
{
    const int z = blockIdx.z;
    const size_t WN4 = (size_t)DM * DM / 4;
    const float4* src = (z == 0) ? wq : (z == 1) ? wk : (z == 2) ? wv : wo;
    const size_t i = blockIdx.x * 256 + threadIdx.x;
    if (i >= WN4) return;
    float4 vv = src[i];
    uint32_t h0, l0, h1, l1;
    if (z < 3) {
        split2h(vv.x, vv.y, h0, l0);
        split2h(vv.z, vv.w, h1, l1);
        uint32_t* hp = (uint32_t*)(g_wfh[z]);
        uint32_t* lp = (uint32_t*)(g_wfl[z]);
        hp[2*i] = h0; hp[2*i+1] = h1;
        lp[2*i] = l0; lp[2*i+1] = l1;
    } else {
        split2(vv.x, vv.y, h0, l0);
        split2(vv.z, vv.w, h1, l1);
        uint32_t* hp = (uint32_t*)g_woh;
        uint32_t* lp = (uint32_t*)g_wol;
        hp[2*i] = h0; hp[2*i+1] = h1;
        lp[2*i] = l0; lp[2*i+1] = l1;
    }
}

// ---------------------------------------------------------------------------
// Shared tile geometry
// ---------------------------------------------------------------------------
#define GSTRIDE 40
#define ARR_BYTES (128 * GSTRIDE * 2)       // 10240 B per 128x32 array
#define NSTAGE (DM / 32)

// ---------------------------------------------------------------------------
// fp16 2-term QKV GEMM: C = Xf16 * (Wh + Wl)^T + bias.
// CTA 128x128, BK=32, 8 warps. Stage = A, Bh, Bl (3 arrays, 30720 B).
// MODE 3: fp16 hi/lo scatter (K/V); MODE 4: fp16 single scatter (Q).
// ---------------------------------------------------------------------------
#define G16_STAGE (3 * ARR_BYTES)           // 30720 B

template<int MODE>
__device__ __forceinline__ void gemm16_body(
    const __half* __restrict__ A, const __half* __restrict__ Bh,
    const __half* __restrict__ Bl, const float* __restrict__ bias,
    void* __restrict__ Ch, void* __restrict__ Cl, float oscale)
{
    extern __shared__ __align__(128) char smraw[];
    const uint32_t smem0 = smem_u32(smraw);

    const int tid = threadIdx.x;
    const int lane = tid & 31;
    const int wid = tid >> 5;
    const int wm = wid >> 2;
    const int wn = wid & 3;

    const int m0 = blockIdx.y << 7;
    const int n0 = blockIdx.x << 7;

    const __half* gsrc[3] = {
        A + (size_t)m0 * DM, Bh + (size_t)n0 * DM, Bl + (size_t)n0 * DM
    };

    const int r0c = tid >> 2, cc0 = tid & 3;
    const int r1c = r0c + 64;

    auto load_stage = [&](int s) {
        const int kk = s * 32;
        const uint32_t sb = smem0 + (s & 1) * G16_STAGE;
        #pragma unroll
        for (int a = 0; a < 3; a++) {
            const __half* g = gsrc[a];
            const uint32_t ab = sb + a * ARR_BYTES;
            CP_ASYNC16(ab + r0c * (GSTRIDE*2) + cc0 * 16,
                       g + (size_t)r0c * DM + kk + cc0 * 8);
            CP_ASYNC16(ab + r1c * (GSTRIDE*2) + cc0 * 16,
                       g + (size_t)r1c * DM + kk + cc0 * 8);
        }
    };

    float acc[4][4][4];
    #pragma unroll
    for (int i = 0; i < 4; i++)
        #pragma unroll
        for (int j = 0; j < 4; j++)
            #pragma unroll
            for (int e = 0; e < 4; e++) acc[i][j][e] = 0.f;

    const int a_r = lane & 15, a_c = (lane >> 4) << 3;
    const int b_r = (lane & 7) + (((lane >> 3) & 2) << 2);
    const int b_c = ((lane >> 3) & 1) << 3;

    load_stage(0);
    CP_COMMIT();

    for (int s = 0; s < NSTAGE; s++) {
        CP_WAIT0();
        __syncthreads();
        if (s + 1 < NSTAGE) { load_stage(s + 1); CP_COMMIT(); }

        const uint32_t sb = smem0 + (s & 1) * G16_STAGE;
        const uint32_t sA  = sb;
        const uint32_t sBh = sb + ARR_BYTES;
        const uint32_t sBl = sb + 2 * ARR_BYTES;

        #pragma unroll
        for (int k16 = 0; k16 < 2; k16++) {
            const int kc = k16 * 16;
            uint32_t bh[2][4], bl[2][4];
            #pragma unroll
            for (int np = 0; np < 2; np++) {
                const uint32_t off =
                    ((wn * 32 + np * 16 + b_r) * GSTRIDE + kc + b_c) * 2;
                ldm_x4(bh[np], sBh + off);
                ldm_x4(bl[np], sBl + off);
            }
            #pragma unroll
            for (int mt = 0; mt < 4; mt++) {
                uint32_t af[4];
                const uint32_t off =
                    ((wm * 64 + mt * 16 + a_r) * GSTRIDE + kc + a_c) * 2;
                ldm_x4(af, sA + off);
                #pragma unroll
                for (int nt = 0; nt < 4; nt++)
                    mma_f16(acc[mt][nt], af, &bh[nt >> 1][(nt & 1) * 2]);
                #pragma unroll
                for (int nt = 0; nt < 4; nt++)
                    mma_f16(acc[mt][nt], af, &bl[nt >> 1][(nt & 1) * 2]);
            }
        }
    }

    #pragma unroll
    for (int mt = 0; mt < 4; mt++) {
        #pragma unroll
        for (int nt = 0; nt < 4; nt++) {
            const int col = n0 + wn * 32 + nt * 8 + ((lane & 3) << 1);
            const float b0 = bias[col], b1 = bias[col + 1];
            #pragma unroll
            for (int half = 0; half < 2; half++) {
                const int row = m0 + wm * 64 + mt * 16 + (lane >> 2) + half * 8;
                const float vx = (acc[mt][nt][half * 2 + 0] + b0) * oscale;
                const float vy = (acc[mt][nt][half * 2 + 1] + b1) * oscale;
                const int h = col >> 6, d = col & 63;
                const int nb = row >> 11, kq = row & 2047;
                const size_t idx = (((size_t)(h * NB + nb)) * SEQ + kq) * HD + d;
                if (MODE == 3) {
                    uint32_t hi, lo;
                    split2h(vx, vy, hi, lo);
                    *(uint32_t*)&((__half*)Ch)[idx] = hi;
                    *(uint32_t*)&((__half*)Cl)[idx] = lo;
                } else {           // MODE 4: single fp16
                    *(uint32_t*)&((__half*)Ch)[idx] = pack_f16(vx, vy);
                }
            }
        }
    }
}

__global__ void __launch_bounds__(256, 2) gemm_qkv16(
    const float* __restrict__ bq, const float* __restrict__ bk,
    const float* __restrict__ bv)
{
    const int z = blockIdx.z;
    if (z == 0) {
        gemm16_body<4>(g_xf[0], g_wfh[0], g_wfl[0], bq, g_qf, nullptr, QSCALE);
    } else if (z == 1) {
        gemm16_body<3>(g_xf[1], g_wfh[1], g_wfl[1], bk, g_kh, g_kl, 1.f);
    } else {
        gemm16_body<3>(g_xf[2], g_wfh[2], g_wfl[2], bv, g_vh, g_vl, 1.f);
    }
}

// ---------------------------------------------------------------------------
// bf16x3 output GEMM (unchanged precision — directly produces final result)
// ---------------------------------------------------------------------------
#define STAGE_BYTES (4 * ARR_BYTES)

__global__ void __launch_bounds__(256, 2) gemm_out(
    const __nv_bfloat16* __restrict__ Ah, const __nv_bfloat16* __restrict__ Al,
    const __nv_bfloat16* __restrict__ Bh, const __nv_bfloat16* __restrict__ Bl,
    const float* __restrict__ bias, float* __restrict__ C)
{
    extern __shared__ __align__(128) char smraw[];
    const uint32_t smem0 = smem_u32(smraw);

    const int tid = threadIdx.x;
    const int lane = tid & 31;
    const int wid = tid >> 5;
    const int wm = wid >> 2;
    const int wn = wid & 3;

    const int m0 = blockIdx.y << 7;
    const int n0 = blockIdx.x << 7;

    const __nv_bfloat16* gsrc[4] = {
        Ah + (size_t)m0 * DM, Al + (size_t)m0 * DM,
        Bh + (size_t)n0 * DM, Bl + (size_t)n0 * DM
    };

    const int r0c = tid >> 2, cc0 = tid & 3;
    const int r1c = r0c + 64;

    auto load_stage = [&](int s) {
        const int kk = s * 32;
        const uint32_t sb = smem0 + (s & 1) * STAGE_BYTES;
        #pragma unroll
        for (int a = 0; a < 4; a++) {
            const __nv_bfloat16* g = gsrc[a];
            const uint32_t ab = sb + a * ARR_BYTES;
            CP_ASYNC16(ab + r0c * (GSTRIDE*2) + cc0 * 16,
                       g + (size_t)r0c * DM + kk + cc0 * 8);
            CP_ASYNC16(ab + r1c * (GSTRIDE*2) + cc0 * 16,
                       g + (size_t)r1c * DM + kk + cc0 * 8);
        }
    };

    float acc[4][4][4];
    #pragma unroll
    for (int i = 0; i < 4; i++)
        #pragma unroll
        for (int j = 0; j < 4; j++)
            #pragma unroll
            for (int e = 0; e < 4; e++) acc[i][j][e] = 0.f;

    const int a_r = lane & 15, a_c = (lane >> 4) << 3;
    const int b_r = (lane & 7) + (((lane >> 3) & 2) << 2);
    const int b_c = ((lane >> 3) & 1) << 3;

    load_stage(0);
    CP_COMMIT();

    for (int s = 0; s < NSTAGE; s++) {
        CP_WAIT0();
        __syncthreads();
        if (s + 1 < NSTAGE) { load_stage(s + 1); CP_COMMIT(); }

        const uint32_t sb = smem0 + (s & 1) * STAGE_BYTES;
        const uint32_t sAh = sb;
        const uint32_t sAl = sb + ARR_BYTES;
        const uint32_t sBh = sb + 2 * ARR_BYTES;
        const uint32_t sBl = sb + 3 * ARR_BYTES;

        #pragma unroll
        for (int k16 = 0; k16 < 2; k16++) {
            const int kc = k16 * 16;
            uint32_t bh[2][4], bl[2][4];
            #pragma unroll
            for (int np = 0; np < 2; np++) {
                const uint32_t off =
                    ((wn * 32 + np * 16 + b_r) * GSTRIDE + kc + b_c) * 2;
                ldm_x4(bh[np], sBh + off);
                ldm_x4(bl[np], sBl + off);
            }
            #pragma unroll
            for (int mt = 0; mt < 4; mt++) {
                uint32_t ah[4], al[4];
                const uint32_t off =
                    ((wm * 64 + mt * 16 + a_r) * GSTRIDE + kc + a_c) * 2;
                ldm_x4(ah, sAh + off);
                ldm_x4(al, sAl + off);
                #pragma unroll
                for (int nt = 0; nt < 4; nt++)
                    mma_bf16(acc[mt][nt], ah, &bh[nt >> 1][(nt & 1) * 2]);
                #pragma unroll
                for (int nt = 0; nt < 4; nt++)
                    mma_bf16(acc[mt][nt], ah, &bl[nt >> 1][(nt & 1) * 2]);
                #pragma unroll
                for (int nt = 0; nt < 4; nt++)
                    mma_bf16(acc[mt][nt], al, &bh[nt >> 1][(nt & 1) * 2]);
            }
        }
    }

    #pragma unroll
    for (int mt = 0; mt < 4; mt++) {
        #pragma unroll
        for (int nt = 0; nt < 4; nt++) {
            const int col = n0 + wn * 32 + nt * 8 + ((lane & 3) << 1);
            const float b0 = bias[col], b1 = bias[col + 1];
            #pragma unroll
            for (int half = 0; half < 2; half++) {
                const int row = m0 + wm * 64 + mt * 16 + (lane >> 2) + half * 8;
                float2 v;
                v.x = acc[mt][nt][half * 2 + 0] + b0;
                v.y = acc[mt][nt][half * 2 + 1] + b1;
                *(float2*)&C[(size_t)row * DM + col] = v;
            }
        }
    }
}

// ---------------------------------------------------------------------------
// FA2-style HMMA attention, 2 CTAs/SM, all-fp16 MMA (unchanged from round 11).
// smem: [Qf 18432][stage0 36864][stage1 36864] = 92160 B.
// ---------------------------------------------------------------------------
#define ASTRIDE 72
#define AARR    (64 * ASTRIDE * 2)          // 9216 B
#define ASTAGE  (4 * AARR)                  // 36864 B
#define QONE    (128 * ASTRIDE * 2)         // 18432 B

__global__ void __launch_bounds__(256, 2) attn_mma(
    const __half* __restrict__ Qf_,
    const __half* __restrict__ Kh_, const __half* __restrict__ Kl_,
    const __half* __restrict__ Vh_, const __half* __restrict__ Vl_,
    __nv_bfloat16* __restrict__ Yh, __nv_bfloat16* __restrict__ Yl)
{
    extern __shared__ __align__(128) char smraw[];
    const uint32_t s0 = smem_u32(smraw);
    const uint32_t stg = s0 + QONE;

    const int tid = threadIdx.x;
    const int lane = tid & 31;
    const int wid = tid >> 5;
    const int hn = blockIdx.y;
    const int h = hn >> 1, n = hn & 1;
    const int q0 = blockIdx.x << 7;
    const size_t hoff = (size_t)hn * SEQ * HD;

    const int a_r = lane & 15, a_c = (lane >> 4) << 3;
    const int b_r = (lane & 7) + (((lane >> 3) & 2) << 2);
    const int b_c = ((lane >> 3) & 1) << 3;

    {
        const __half* Qg = Qf_ + hoff + (size_t)q0 * HD;
        #pragma unroll
        for (int c = 0; c < 4; c++) {
            const int ch = tid + c * 256;
            const int row = ch >> 3, c16 = ch & 7;
            CP_ASYNC16(s0 + row * 144 + c16 * 16, Qg + row * 64 + c16 * 8);
        }
        CP_COMMIT();
    }

    const char* gs0 = (const char*)(Kh_ + hoff);
    const char* gs1 = (const char*)(Kl_ + hoff);
    const char* gs2 = (const char*)(Vh_ + hoff);
    const char* gs3 = (const char*)(Vl_ + hoff);

    auto load_stage = [&](int s) {
        const int kv0 = s << 6;
        const uint32_t sb = stg + (s & 1) * ASTAGE;
        const char* gs[4] = { gs0, gs1, gs2, gs3 };
        #pragma unroll
        for (int a = 0; a < 4; a++) {
            #pragma unroll
            for (int c = 0; c < 2; c++) {
                const int ch = tid + c * 256;
                const int row = ch >> 3, c16 = ch & 7;
                CP_ASYNC16(sb + a * AARR + row * 144 + c16 * 16,
                           gs[a] + (size_t)(kv0 + row) * 128 + c16 * 16);
            }
        }
    };

    load_stage(0); CP_COMMIT();

    CP_WAIT0();
    __syncthreads();
    uint32_t qf[4][4];
    const uint32_t qbase = ((wid * 16 + a_r) * ASTRIDE + a_c) * 2;
    #pragma unroll
    for (int t4 = 0; t4 < 4; t4++)
        ldm_x4(qf[t4], s0 + qbase + t4 * 32);

    float m0r = -1e30f, m1r = -1e30f, l0 = 0.f, l1 = 0.f;
    float O[8][4];
    #pragma unroll
    for (int j = 0; j < 8; j++)
        #pragma unroll
        for (int e = 0; e < 4; e++) O[j][e] = 0.f;

    for (int t = 0; t < SEQ / 64; t++) {
        if (t > 0) { CP_WAIT0(); __syncthreads(); }
        if (t + 1 < SEQ / 64) { load_stage(t + 1); CP_COMMIT(); }

        const uint32_t sb = stg + (t & 1) * ASTAGE;

        float S[8][4];
        #pragma unroll
        for (int j = 0; j < 8; j++)
            #pragma unroll
            for (int e = 0; e < 4; e++) S[j][e] = 0.f;

        #pragma unroll
        for (int t4 = 0; t4 < 4; t4++) {
            #pragma unroll
            for (int jp = 0; jp < 4; jp++) {
                uint32_t bh[4], bl[4];
                const uint32_t off = ((16 * jp + b_r) * ASTRIDE + 16 * t4 + b_c) * 2;
                ldm_x4(bh, sb + off);
                ldm_x4(bl, sb + AARR + off);
                mma_f16(S[2*jp],   qf[t4], &bh[0]);
                mma_f16(S[2*jp+1], qf[t4], &bh[2]);
                mma_f16(S[2*jp],   qf[t4], &bl[0]);
                mma_f16(S[2*jp+1], qf[t4], &bl[2]);
            }
        }

        float corr0, corr1;
        {
            float tm = S[0][0];
            #pragma unroll
            for (int j = 0; j < 8; j++) tm = fmaxf(tm, fmaxf(S[j][0], S[j][1]));
            tm = fmaxf(tm, __shfl_xor_sync(0xffffffffu, tm, 1));
            tm = fmaxf(tm, __shfl_xor_sync(0xffffffffu, tm, 2));
            const float mnew = fmaxf(m0r, tm);
            corr0 = ex2(m0r - mnew);
            float rs = 0.f;
            #pragma unroll
            for (int j = 0; j < 8; j++) {
                S[j][0] = ex2(S[j][0] - mnew);
                S[j][1] = ex2(S[j][1] - mnew);
                rs += S[j][0] + S[j][1];
            }
            rs += __shfl_xor_sync(0xffffffffu, rs, 1);
            rs += __shfl_xor_sync(0xffffffffu, rs, 2);
            l0 = l0 * corr0 + rs;
            m0r = mnew;
        }
        {
            float tm = S[0][2];
            #pragma unroll
            for (int j = 0; j < 8; j++) tm = fmaxf(tm, fmaxf(S[j][2], S[j][3]));
            tm = fmaxf(tm, __shfl_xor_sync(0xffffffffu, tm, 1));
            tm = fmaxf(tm, __shfl_xor_sync(0xffffffffu, tm, 2));
            const float mnew = fmaxf(m1r, tm);
            corr1 = ex2(m1r - mnew);
            float rs = 0.f;
            #pragma unroll
            for (int j = 0; j < 8; j++) {
                S[j][2] = ex2(S[j][2] - mnew);
                S[j][3] = ex2(S[j][3] - mnew);
                rs += S[j][2] + S[j][3];
            }
            rs += __shfl_xor_sync(0xffffffffu, rs, 1);
            rs += __shfl_xor_sync(0xffffffffu, rs, 2);
            l1 = l1 * corr1 + rs;
            m1r = mnew;
        }

        uint32_t pa[4][4];
        #pragma unroll
        for (int t4 = 0; t4 < 4; t4++) {
            pa[t4][0] = pack_f16(S[2*t4][0],   S[2*t4][1]);
            pa[t4][1] = pack_f16(S[2*t4][2],   S[2*t4][3]);
            pa[t4][2] = pack_f16(S[2*t4+1][0], S[2*t4+1][1]);
            pa[t4][3] = pack_f16(S[2*t4+1][2], S[2*t4+1][3]);
        }

        #pragma unroll
        for (int j = 0; j < 8; j++) {
            O[j][0] *= corr0; O[j][1] *= corr0;
            O[j][2] *= corr1; O[j][3] *= corr1;
        }

        #pragma unroll
        for (int t4 = 0; t4 < 4; t4++) {
            #pragma unroll
            for (int jp = 0; jp < 4; jp++) {
                uint32_t vh[4], vl[4];
                const uint32_t off =
                    ((16 * t4 + (lane & 15)) * ASTRIDE + 16 * jp + a_c) * 2;
                ldm_x4_t(vh, sb + 2 * AARR + off);
                ldm_x4_t(vl, sb + 3 * AARR + off);
                mma_f16(O[2*jp],   pa[t4], &vh[0]);
                mma_f16(O[2*jp+1], pa[t4], &vh[2]);
                mma_f16(O[2*jp],   pa[t4], &vl[0]);
                mma_f16(O[2*jp+1], pa[t4], &vl[2]);
            }
        }
    }

    const float inv0 = frcp(l0), inv1 = frcp(l1);
    #pragma unroll
    for (int j = 0; j < 8; j++) {
        const int col = h * 64 + 8 * j + ((lane & 3) << 1);
        #pragma unroll
        for (int half = 0; half < 2; half++) {
            const int row = q0 + wid * 16 + (lane >> 2) + half * 8;
            const float inv = half ? inv1 : inv0;
            const float y0 = O[j][half * 2 + 0] * inv;
            const float y1 = O[j][half * 2 + 1] * inv;
            const size_t idx = ((size_t)(n * SEQ) + row) * DM + col;
            uint32_t hi, lo;
            split2(y0, y1, hi, lo);
            *(uint32_t*)&Yh[idx] = hi;
            *(uint32_t*)&Yl[idx] = lo;
        }
    }
}

// ---------------------------------------------------------------------------
extern "C" void kernel_launch(void* const* d_in, const int* in_sizes, int n_in,
                              void* d_out, int out_size)
{
    const float* q  = (const float*)d_in[0];
    const float* k  = (const float*)d_in[1];
    const float* v  = (const float*)d_in[2];
    const float* Wq = (const float*)d_in[3];
    const float* bq = (const float*)d_in[4];
    const float* Wk = (const float*)d_in[5];
    const float* bk = (const float*)d_in[6];
    const float* Wv = (const float*)d_in[7];
    const float* bv = (const float*)d_in[8];
    const float* Wo = (const float*)d_in[9];
    const float* bo = (const float*)d_in[10];
    float* out = (float*)d_out;

    __nv_bfloat16 *yh, *yl, *woh, *wol;
    __half *qf, *kh, *kl, *vh, *vl;
    cudaGetSymbolAddress((void**)&yh, g_yh);
    cudaGetSymbolAddress((void**)&yl, g_yl);
    cudaGetSymbolAddress((void**)&woh, g_woh);
    cudaGetSymbolAddress((void**)&wol, g_wol);
    cudaGetSymbolAddress((void**)&qf, g_qf);
    cudaGetSymbolAddress((void**)&kh, g_kh);
    cudaGetSymbolAddress((void**)&kl, g_kl);
    cudaGetSymbolAddress((void**)&vh, g_vh);
    cudaGetSymbolAddress((void**)&vl, g_vl);

    const size_t XN = (size_t)ROWS * DM;
    const size_t WN = (size_t)DM * DM;

    { const dim3 gi((unsigned)(XN/4/256), 1, 3);
      split_in<<<gi, 256>>>((const float4*)q, (const float4*)k, (const float4*)v); }
    { const dim3 gw((unsigned)(WN/4/256), 1, 4);
      split_w<<<gw, 256>>>((const float4*)Wq, (const float4*)Wk,
                           (const float4*)Wv, (const float4*)Wo); }

    const int g16smem = 2 * G16_STAGE;   // 61440
    cudaFuncSetAttribute((const void*)gemm_qkv16,
                         cudaFuncAttributeMaxDynamicSharedMemorySize, g16smem);
    const dim3 gq(DM/128, ROWS/128, 3);
    gemm_qkv16<<<gq, 256, g16smem>>>(bq, bk, bv);

    const int asmem = QONE + 2 * ASTAGE;   // 92160
    cudaFuncSetAttribute((const void*)attn_mma,
                         cudaFuncAttributeMaxDynamicSharedMemorySize, asmem);
    const dim3 ga(SEQ/128, NH*NB);  // (16, 32)
    attn_mma<<<ga, 256, asmem>>>(qf, kh, kl, vh, vl, yh, yl);

    const int gsmem = 2 * STAGE_BYTES;   // 81920
    cudaFuncSetAttribute((const void*)gemm_out,
                         cudaFuncAttributeMaxDynamicSharedMemorySize, gsmem);
    const dim3 gg(DM/128, ROWS/128);
    gemm_out<<<gg, 256, gsmem>>>(yh, yl, woh, wol, bo, out);
}

// round 13
// speedup vs baseline: 4.6443x; 1.0590x over previous
#include <cuda_runtime.h>
#include <cuda_bf16.h>
#include <cuda_fp16.h>
#include <cstdint>

#define NB   2
#define SEQ  2048
#define DM   1024
#define NH   16
#define HD   64
#define ROWS (NB*SEQ)          // 4096
// softmax scale 1/sqrt(64) folded into Q projection together with log2(e):
#define QSCALE 0.18033688011112042f   // 0.125 * log2(e)

// ---------------------------------------------------------------------------
// Scratch (allocation-free: __device__ globals)
// ---------------------------------------------------------------------------
#define PROJN ((size_t)NH*NB*SEQ*HD)     // 4M elems
__device__ __align__(256) __half g_qf[PROJN];                       // fp16 Q (single)
__device__ __align__(256) __half g_kh[PROJN], g_kl[PROJN];          // fp16 K hi/lo
__device__ __align__(256) __half g_vh[PROJN], g_vl[PROJN];          // fp16 V hi/lo
__device__ __align__(256) __half g_xf[3][(size_t)ROWS*DM];          // fp16 inputs (single)
__device__ __align__(256) __half g_wfh[4][(size_t)DM*DM];           // fp16 W hi (q,k,v,o)
__device__ __align__(256) __half g_wfl[4][(size_t)DM*DM];           // fp16 W lo (q,k,v,o)
__device__ __align__(256) __half g_yf[(size_t)ROWS*DM];             // fp16 Y (single)

// ---------------------------------------------------------------------------
// PTX helpers (baseline sm_80+ features: mma.sync / ldmatrix / cp.async)
// ---------------------------------------------------------------------------
__device__ __forceinline__ uint32_t smem_u32(const void* p) {
    uint32_t a;
    asm("{ .reg .u64 t; cvta.to.shared.u64 t, %1; cvt.u32.u64 %0, t; }"
        : "=r"(a) : "l"(p));
    return a;
}

#define CP_ASYNC16(dst, src) \
    asm volatile("cp.async.cg.shared.global [%0], [%1], 16;" :: "r"(dst), "l"(src))
#define CP_COMMIT() asm volatile("cp.async.commit_group;" ::: "memory")
#define CP_WAIT0()  asm volatile("cp.async.wait_group 0;" ::: "memory")

__device__ __forceinline__ void ldm_x4(uint32_t* r, uint32_t addr) {
    asm volatile("ldmatrix.sync.aligned.m8n8.x4.shared.b16 {%0,%1,%2,%3}, [%4];"
                 : "=r"(r[0]), "=r"(r[1]), "=r"(r[2]), "=r"(r[3]) : "r"(addr));
}
__device__ __forceinline__ void ldm_x4_t(uint32_t* r, uint32_t addr) {
    asm volatile("ldmatrix.sync.aligned.m8n8.x4.trans.shared.b16 {%0,%1,%2,%3}, [%4];"
                 : "=r"(r[0]), "=r"(r[1]), "=r"(r[2]), "=r"(r[3]) : "r"(addr));
}

__device__ __forceinline__ void mma_f16(float* d, const uint32_t* a, const uint32_t* b) {
    asm volatile(
        "mma.sync.aligned.m16n8k16.row.col.f32.f16.f16.f32 "
        "{%0,%1,%2,%3}, {%4,%5,%6,%7}, {%8,%9}, {%0,%1,%2,%3};"
        : "+f"(d[0]), "+f"(d[1]), "+f"(d[2]), "+f"(d[3])
        : "r"(a[0]), "r"(a[1]), "r"(a[2]), "r"(a[3]), "r"(b[0]), "r"(b[1]));
}

// fast exp2 / rcp via MUFU
__device__ __forceinline__ float ex2(float x) {
    float r; asm("ex2.approx.f32 %0, %1;" : "=f"(r) : "f"(x)); return r;
}
__device__ __forceinline__ float frcp(float x) {
    float r; asm("rcp.approx.f32 %0, %1;" : "=f"(r) : "f"(x)); return r;
}

// fp32 pair -> packed f16x2 (a in low half)
__device__ __forceinline__ uint32_t pack_f16(float a, float b) {
    uint32_t r; asm("cvt.rn.f16x2.f32 %0, %1, %2;" : "=r"(r) : "f"(b), "f"(a));
    return r;
}
// fp32 pair -> f16x2 hi + f16x2 lo
__device__ __forceinline__ void split2h(float a, float b, uint32_t& hi, uint32_t& lo) {
    hi = pack_f16(a, b);
    __half2 h = *(__half2*)&hi;
    const float la = a - __half2float(h.x);
    const float lb = b - __half2float(h.y);
    lo = pack_f16(la, lb);
}

// ---------------------------------------------------------------------------
// input split: fp32 -> fp16 single (z selects q/k/v)
// ---------------------------------------------------------------------------
__global__ void __launch_bounds__(256) split_in(
    const float4* __restrict__ q, const float4* __restrict__ k,
    const float4* __restrict__ v)
{
    const int z = blockIdx.z;
    const size_t XN4 = (size_t)ROWS * DM / 4;
    const float4* src = (z == 0) ? q : (z == 1) ? k : v;
    uint32_t* fp = (uint32_t*)(g_xf[z]);
    const size_t i = blockIdx.x * 256 + threadIdx.x;
    if (i >= XN4) return;
    float4 vv = src[i];
    fp[2*i]   = pack_f16(vv.x, vv.y);
    fp[2*i+1] = pack_f16(vv.z, vv.w);
}

// weight split: all four weights -> fp16 hi/lo
__global__ void __launch_bounds__(256) split_w(
    const float4* __restrict__ wq, const float4* __restrict__ wk,
    const float4* __restrict__ wv, const float4* __restrict__ wo)
{
    const int z = blockIdx.z;
    const size_t WN4 = (size_t)DM * DM / 4;
    const float4* src = (z == 0) ? wq : (z == 1) ? wk : (z == 2) ? wv : wo;
    uint32_t* hp = (uint32_t*)(g_wfh[z]);
    uint32_t* lp = (uint32_t*)(g_wfl[z]);
    const size_t i = blockIdx.x * 256 + threadIdx.x;
    if (i >= WN4) return;
    float4 vv = src[i];
    uint32_t h0, l0, h1, l1;
    split2h(vv.x, vv.y, h0, l0);
    split2h(vv.z, vv.w, h1, l1);
    hp[2*i] = h0; hp[2*i+1] = h1;
    lp[2*i] = l0; lp[2*i+1] = l1;
}

// ---------------------------------------------------------------------------
// Shared tile geometry
// ---------------------------------------------------------------------------
#define GSTRIDE 40
#define ARR_BYTES (128 * GSTRIDE * 2)       // 10240 B per 128x32 array
#define NSTAGE (DM / 32)
#define G16_STAGE (3 * ARR_BYTES)           // 30720 B

// ---------------------------------------------------------------------------
// fp16 2-term GEMM: C = A_f16 * (Wh + Wl)^T + bias.
// CTA 128x128, BK=32, 8 warps. Stage = A, Bh, Bl (3 arrays).
// MODE 0: fp32 C row-major; MODE 3: fp16 hi/lo scatter (K/V);
// MODE 4: fp16 single scatter (Q).
// ---------------------------------------------------------------------------
template<int MODE>
__device__ __forceinline__ void gemm16_body(
    const __half* __restrict__ A, const __half* __restrict__ Bh,
    const __half* __restrict__ Bl, const float* __restrict__ bias,
    float* __restrict__ C, void* __restrict__ Ch, void* __restrict__ Cl,
    float oscale)
{
    extern __shared__ __align__(128) char smraw[];
    const uint32_t smem0 = smem_u32(smraw);

    const int tid = threadIdx.x;
    const int lane = tid & 31;
    const int wid = tid >> 5;
    const int wm = wid >> 2;
    const int wn = wid & 3;

    const int m0 = blockIdx.y << 7;
    const int n0 = blockIdx.x << 7;

    const __half* gsrc[3] = {
        A + (size_t)m0 * DM, Bh + (size_t)n0 * DM, Bl + (size_t)n0 * DM
    };

    const int r0c = tid >> 2, cc0 = tid & 3;
    const int r1c = r0c + 64;

    auto load_stage = [&](int s) {
        const int kk = s * 32;
        const uint32_t sb = smem0 + (s & 1) * G16_STAGE;
        #pragma unroll
        for (int a = 0; a < 3; a++) {
            const __half* g = gsrc[a];
            const uint32_t ab = sb + a * ARR_BYTES;
            CP_ASYNC16(ab + r0c * (GSTRIDE*2) + cc0 * 16,
                       g + (size_t)r0c * DM + kk + cc0 * 8);
            CP_ASYNC16(ab + r1c * (GSTRIDE*2) + cc0 * 16,
                       g + (size_t)r1c * DM + kk + cc0 * 8);
        }
    };

    float acc[4][4][4];
    #pragma unroll
    for (int i = 0; i < 4; i++)
        #pragma unroll
        for (int j = 0; j < 4; j++)
            #pragma unroll
            for (int e = 0; e < 4; e++) acc[i][j][e] = 0.f;

    const int a_r = lane & 15, a_c = (lane >> 4) << 3;
    const int b_r = (lane & 7) + (((lane >> 3) & 2) << 2);
    const int b_c = ((lane >> 3) & 1) << 3;

    load_stage(0);
    CP_COMMIT();

    for (int s = 0; s < NSTAGE; s++) {
        CP_WAIT0();
        __syncthreads();
        if (s + 1 < NSTAGE) { load_stage(s + 1); CP_COMMIT(); }

        const uint32_t sb = smem0 + (s & 1) * G16_STAGE;
        const uint32_t sA  = sb;
        const uint32_t sBh = sb + ARR_BYTES;
        const uint32_t sBl = sb + 2 * ARR_BYTES;

        #pragma unroll
        for (int k16 = 0; k16 < 2; k16++) {
            const int kc = k16 * 16;
            uint32_t bh[2][4], bl[2][4];
            #pragma unroll
            for (int np = 0; np < 2; np++) {
                const uint32_t off =
                    ((wn * 32 + np * 16 + b_r) * GSTRIDE + kc + b_c) * 2;
                ldm_x4(bh[np], sBh + off);
                ldm_x4(bl[np], sBl + off);
            }
            #pragma unroll
            for (int mt = 0; mt < 4; mt++) {
                uint32_t af[4];
                const uint32_t off =
                    ((wm * 64 + mt * 16 + a_r) * GSTRIDE + kc + a_c) * 2;
                ldm_x4(af, sA + off);
                #pragma unroll
                for (int nt = 0; nt < 4; nt++)
                    mma_f16(acc[mt][nt], af, &bh[nt >> 1][(nt & 1) * 2]);
                #pragma unroll
                for (int nt = 0; nt < 4; nt++)
                    mma_f16(acc[mt][nt], af, &bl[nt >> 1][(nt & 1) * 2]);
            }
        }
    }

    #pragma unroll
    for (int mt = 0; mt < 4; mt++) {
        #pragma unroll
        for (int nt = 0; nt < 4; nt++) {
            const int col = n0 + wn * 32 + nt * 8 + ((lane & 3) << 1);
            const float b0 = bias[col], b1 = bias[col + 1];
            #pragma unroll
            for (int half = 0; half < 2; half++) {
                const int row = m0 + wm * 64 + mt * 16 + (lane >> 2) + half * 8;
                const float vx = (acc[mt][nt][half * 2 + 0] + b0) * oscale;
                const float vy = (acc[mt][nt][half * 2 + 1] + b1) * oscale;
                if (MODE == 0) {
                    float2 vo; vo.x = vx; vo.y = vy;
                    *(float2*)&C[(size_t)row * DM + col] = vo;
                } else {
                    const int h = col >> 6, d = col & 63;
                    const int nb = row >> 11, kq = row & 2047;
                    const size_t idx = (((size_t)(h * NB + nb)) * SEQ + kq) * HD + d;
                    if (MODE == 3) {
                        uint32_t hi, lo;
                        split2h(vx, vy, hi, lo);
                        *(uint32_t*)&((__half*)Ch)[idx] = hi;
                        *(uint32_t*)&((__half*)Cl)[idx] = lo;
                    } else {           // MODE 4: single fp16
                        *(uint32_t*)&((__half*)Ch)[idx] = pack_f16(vx, vy);
                    }
                }
            }
        }
    }
}

__global__ void __launch_bounds__(256, 2) gemm_qkv16(
    const float* __restrict__ bq, const float* __restrict__ bk,
    const float* __restrict__ bv)
{
    const int z = blockIdx.z;
    if (z == 0) {
        gemm16_body<4>(g_xf[0], g_wfh[0], g_wfl[0], bq, nullptr, g_qf, nullptr, QSCALE);
    } else if (z == 1) {
        gemm16_body<3>(g_xf[1], g_wfh[1], g_wfl[1], bk, nullptr, g_kh, g_kl, 1.f);
    } else {
        gemm16_body<3>(g_xf[2], g_wfh[2], g_wfl[2], bv, nullptr, g_vh, g_vl, 1.f);
    }
}

__global__ void __launch_bounds__(256, 2) gemm_out16(
    const float* __restrict__ bo, float* __restrict__ C)
{
    gemm16_body<0>(g_yf, g_wfh[3], g_wfl[3], bo, C, nullptr, nullptr, 1.f);
}

// ---------------------------------------------------------------------------
// FA2-style HMMA attention, 2 CTAs/SM, all-fp16 MMA.
// Y written as single fp16 (feeds the fp16 2-term output GEMM).
// smem: [Qf 18432][stage0 36864][stage1 36864] = 92160 B.
// ---------------------------------------------------------------------------
#define ASTRIDE 72
#define AARR    (64 * ASTRIDE * 2)          // 9216 B
#define ASTAGE  (4 * AARR)                  // 36864 B
#define QONE    (128 * ASTRIDE * 2)         // 18432 B

__global__ void __launch_bounds__(256, 2) attn_mma(
    const __half* __restrict__ Qf_,
    const __half* __restrict__ Kh_, const __half* __restrict__ Kl_,
    const __half* __restrict__ Vh_, const __half* __restrict__ Vl_,
    __half* __restrict__ Yf)
{
    extern __shared__ __align__(128) char smraw[];
    const uint32_t s0 = smem_u32(smraw);
    const uint32_t stg = s0 + QONE;

    const int tid = threadIdx.x;
    const int lane = tid & 31;
    const int wid = tid >> 5;
    const int hn = blockIdx.y;
    const int h = hn >> 1, n = hn & 1;
    const int q0 = blockIdx.x << 7;
    const size_t hoff = (size_t)hn * SEQ * HD;

    const int a_r = lane & 15, a_c = (lane >> 4) << 3;
    const int b_r = (lane & 7) + (((lane >> 3) & 2) << 2);
    const int b_c = ((lane >> 3) & 1) << 3;

    {
        const __half* Qg = Qf_ + hoff + (size_t)q0 * HD;
        #pragma unroll
        for (int c = 0; c < 4; c++) {
            const int ch = tid + c * 256;
            const int row = ch >> 3, c16 = ch & 7;
            CP_ASYNC16(s0 + row * 144 + c16 * 16, Qg + row * 64 + c16 * 8);
        }
        CP_COMMIT();
    }

    const char* gs0 = (const char*)(Kh_ + hoff);
    const char* gs1 = (const char*)(Kl_ + hoff);
    const char* gs2 = (const char*)(Vh_ + hoff);
    const char* gs3 = (const char*)(Vl_ + hoff);

    auto load_stage = [&](int s) {
        const int kv0 = s << 6;
        const uint32_t sb = stg + (s & 1) * ASTAGE;
        const char* gs[4] = { gs0, gs1, gs2, gs3 };
        #pragma unroll
        for (int a = 0; a < 4; a++) {
            #pragma unroll
            for (int c = 0; c < 2; c++) {
                const int ch = tid + c * 256;
                const int row = ch >> 3, c16 = ch & 7;
                CP_ASYNC16(sb + a * AARR + row * 144 + c16 * 16,
                           gs[a] + (size_t)(kv0 + row) * 128 + c16 * 16);
            }
        }
    };

    load_stage(0); CP_COMMIT();

    CP_WAIT0();
    __syncthreads();
    uint32_t qf[4][4];
    const uint32_t qbase = ((wid * 16 + a_r) * ASTRIDE + a_c) * 2;
    #pragma unroll
    for (int t4 = 0; t4 < 4; t4++)
        ldm_x4(qf[t4], s0 + qbase + t4 * 32);

    float m0r = -1e30f, m1r = -1e30f, l0 = 0.f, l1 = 0.f;
    float O[8][4];
    #pragma unroll
    for (int j = 0; j < 8; j++)
        #pragma unroll
        for (int e = 0; e < 4; e++) O[j][e] = 0.f;

    for (int t = 0; t < SEQ / 64; t++) {
        if (t > 0) { CP_WAIT0(); __syncthreads(); }
        if (t + 1 < SEQ / 64) { load_stage(t + 1); CP_COMMIT(); }

        const uint32_t sb = stg + (t & 1) * ASTAGE;

        float S[8][4];
        #pragma unroll
        for (int j = 0; j < 8; j++)
            #pragma unroll
            for (int e = 0; e < 4; e++) S[j][e] = 0.f;

        #pragma unroll
        for (int t4 = 0; t4 < 4; t4++) {
            #pragma unroll
            for (int jp = 0; jp < 4; jp++) {
                uint32_t bh[4], bl[4];
                const uint32_t off = ((16 * jp + b_r) * ASTRIDE + 16 * t4 + b_c) * 2;
                ldm_x4(bh, sb + off);
                ldm_x4(bl, sb + AARR + off);
                mma_f16(S[2*jp],   qf[t4], &bh[0]);
                mma_f16(S[2*jp+1], qf[t4], &bh[2]);
                mma_f16(S[2*jp],   qf[t4], &bl[0]);
                mma_f16(S[2*jp+1], qf[t4], &bl[2]);
            }
        }

        float corr0, corr1;
        {
            float tm = S[0][0];
            #pragma unroll
            for (int j = 0; j < 8; j++) tm = fmaxf(tm, fmaxf(S[j][0], S[j][1]));
            tm = fmaxf(tm, __shfl_xor_sync(0xffffffffu, tm, 1));
            tm = fmaxf(tm, __shfl_xor_sync(0xffffffffu, tm, 2));
            const float mnew = fmaxf(m0r, tm);
            corr0 = ex2(m0r - mnew);
            float rs = 0.f;
            #pragma unroll
            for (int j = 0; j < 8; j++) {
                S[j][0] = ex2(S[j][0] - mnew);
                S[j][1] = ex2(S[j][1] - mnew);
                rs += S[j][0] + S[j][1];
            }
            rs += __shfl_xor_sync(0xffffffffu, rs, 1);
            rs += __shfl_xor_sync(0xffffffffu, rs, 2);
            l0 = l0 * corr0 + rs;
            m0r = mnew;
        }
        {
            float tm = S[0][2];
            #pragma unroll
            for (int j = 0; j < 8; j++) tm = fmaxf(tm, fmaxf(S[j][2], S[j][3]));
            tm = fmaxf(tm, __shfl_xor_sync(0xffffffffu, tm, 1));
            tm = fmaxf(tm, __shfl_xor_sync(0xffffffffu, tm, 2));
            const float mnew = fmaxf(m1r, tm);
            corr1 = ex2(m1r - mnew);
            float rs = 0.f;
            #pragma unroll
            for (int j = 0; j < 8; j++) {
                S[j][2] = ex2(S[j][2] - mnew);
                S[j][3] = ex2(S[j][3] - mnew);
                rs += S[j][2] + S[j][3];
            }
            rs += __shfl_xor_sync(0xffffffffu, rs, 1);
            rs += __shfl_xor_sync(0xffffffffu, rs, 2);
            l1 = l1 * corr1 + rs;
            m1r = mnew;
        }

        uint32_t pa[4][4];
        #pragma unroll
        for (int t4 = 0; t4 < 4; t4++) {
            pa[t4][0] = pack_f16(S[2*t4][0],   S[2*t4][1]);
            pa[t4][1] = pack_f16(S[2*t4][2],   S[2*t4][3]);
            pa[t4][2] = pack_f16(S[2*t4+1][0], S[2*t4+1][1]);
            pa[t4][3] = pack_f16(S[2*t4+1][2], S[2*t4+1][3]);
        }

        #pragma unroll
        for (int j = 0; j < 8; j++) {
            O[j][0] *= corr0; O[j][1] *= corr0;
            O[j][2] *= corr1; O[j][3] *= corr1;
        }

        #pragma unroll
        for (int t4 = 0; t4 < 4; t4++) {
            #pragma unroll
            for (int jp = 0; jp < 4; jp++) {
                uint32_t vh[4], vl[4];
                const uint32_t off =
                    ((16 * t4 + (lane & 15)) * ASTRIDE + 16 * jp + a_c) * 2;
                ldm_x4_t(vh, sb + 2 * AARR + off);
                ldm_x4_t(vl, sb + 3 * AARR + off);
                mma_f16(O[2*jp],   pa[t4], &vh[0]);
                mma_f16(O[2*jp+1], pa[t4], &vh[2]);
                mma_f16(O[2*jp],   pa[t4], &vl[0]);
                mma_f16(O[2*jp+1], pa[t4], &vl[2]);
            }
        }
    }

    // ---- epilogue: scale by 1/l, write single fp16 in [N, K, H*D] layout ----
    const float inv0 = frcp(l0), inv1 = frcp(l1);
    #pragma unroll
    for (int j = 0; j < 8; j++) {
        const int col = h * 64 + 8 * j + ((lane & 3) << 1);
        #pragma unroll
        for (int half = 0; half < 2; half++) {
            const int row = q0 + wid * 16 + (lane >> 2) + half * 8;
            const float inv = half ? inv1 : inv0;
            const float y0 = O[j][half * 2 + 0] * inv;
            const float y1 = O[j][half * 2 + 1] * inv;
            const size_t idx = ((size_t)(n * SEQ) + row) * DM + col;
            *(uint32_t*)&Yf[idx] = pack_f16(y0, y1);
        }
    }
}

// ---------------------------------------------------------------------------
extern "C" void kernel_launch(void* const* d_in, const int* in_sizes, int n_in,
                              void* d_out, int out_size)
{
    const float* q  = (const float*)d_in[0];
    const float* k  = (const float*)d_in[1];
    const float* v  = (const float*)d_in[2];
    const float* Wq = (const float*)d_in[3];
    const float* bq = (const float*)d_in[4];
    const float* Wk = (const float*)d_in[5];
    const float* bk = (const float*)d_in[6];
    const float* Wv = (const float*)d_in[7];
    const float* bv = (const float*)d_in[8];
    const float* Wo = (const float*)d_in[9];
    const float* bo = (const float*)d_in[10];
    float* out = (float*)d_out;

    __half *qf, *kh, *kl, *vh, *vl, *yf;
    cudaGetSymbolAddress((void**)&qf, g_qf);
    cudaGetSymbolAddress((void**)&kh, g_kh);
    cudaGetSymbolAddress((void**)&kl, g_kl);
    cudaGetSymbolAddress((void**)&vh, g_vh);
    cudaGetSymbolAddress((void**)&vl, g_vl);
    cudaGetSymbolAddress((void**)&yf, g_yf);

    const size_t XN = (size_t)ROWS * DM;
    const size_t WN = (size_t)DM * DM;

    { const dim3 gi((unsigned)(XN/4/256), 1, 3);
      split_in<<<gi, 256>>>((const float4*)q, (const float4*)k, (const float4*)v); }
    { const dim3 gw((unsigned)(WN/4/256), 1, 4);
      split_w<<<gw, 256>>>((const float4*)Wq, (const float4*)Wk,
                           (const float4*)Wv, (const float4*)Wo); }

    const int g16smem = 2 * G16_STAGE;   // 61440
    cudaFuncSetAttribute((const void*)gemm_qkv16,
                         cudaFuncAttributeMaxDynamicSharedMemorySize, g16smem);
    cudaFuncSetAttribute((const void*)gemm_out16,
                         cudaFuncAttributeMaxDynamicSharedMemorySize, g16smem);
    const dim3 gq(DM/128, ROWS/128, 3);
    gemm_qkv16<<<gq, 256, g16smem>>>(bq, bk, bv);

    const int asmem = QONE + 2 * ASTAGE;   // 92160
    cudaFuncSetAttribute((const void*)attn_mma,
                         cudaFuncAttributeMaxDynamicSharedMemorySize, asmem);
    const dim3 ga(SEQ/128, NH*NB);  // (16, 32)
    attn_mma<<<ga, 256, asmem>>>(qf, kh, kl, vh, vl, yf);

    const dim3 gg(DM/128, ROWS/128);
    gemm_out16<<<gg, 256, g16smem>>>(bo, out);
}

// round 14
// speedup vs baseline: 5.4633x; 1.1763x over previous
#include <cuda_runtime.h>
#include <cuda_bf16.h>
#include <cuda_fp16.h>
#include <cstdint>

#define NB   2
#define SEQ  2048
#define DM   1024
#define NH   16
#define HD   64
#define ROWS (NB*SEQ)          // 4096
// softmax scale 1/sqrt(64) folded into Q projection together with log2(e):
#define QSCALE 0.18033688011112042f   // 0.125 * log2(e)

// ---------------------------------------------------------------------------
// Scratch (allocation-free: __device__ globals)
// ---------------------------------------------------------------------------
#define PROJN ((size_t)NH*NB*SEQ*HD)     // 4M elems
__device__ __align__(256) __half g_qf[PROJN];                       // fp16 Q (single)
__device__ __align__(256) __half g_kf[PROJN];                       // fp16 K (single)
__device__ __align__(256) __half g_vh[PROJN], g_vl[PROJN];          // fp16 V hi/lo
__device__ __align__(256) __half g_xf[3][(size_t)ROWS*DM];          // fp16 inputs
__device__ __align__(256) __half g_wfh[4][(size_t)DM*DM];           // fp16 W hi (q,k,v,o)
__device__ __align__(256) __half g_wfl[4][(size_t)DM*DM];           // fp16 W lo (q,k,v,o)
__device__ __align__(256) __half g_yf[(size_t)ROWS*DM];             // fp16 Y (single)

// ---------------------------------------------------------------------------
// PTX helpers (baseline sm_80+ features: mma.sync / ldmatrix / cp.async)
// ---------------------------------------------------------------------------
__device__ __forceinline__ uint32_t smem_u32(const void* p) {
    uint32_t a;
    asm("{ .reg .u64 t; cvta.to.shared.u64 t, %1; cvt.u32.u64 %0, t; }"
        : "=r"(a) : "l"(p));
    return a;
}

#define CP_ASYNC16(dst, src) \
    asm volatile("cp.async.cg.shared.global [%0], [%1], 16;" :: "r"(dst), "l"(src))
#define CP_COMMIT() asm volatile("cp.async.commit_group;" ::: "memory")
#define CP_WAIT0()  asm volatile("cp.async.wait_group 0;" ::: "memory")

__device__ __forceinline__ void ldm_x4(uint32_t* r, uint32_t addr) {
    asm volatile("ldmatrix.sync.aligned.m8n8.x4.shared.b16 {%0,%1,%2,%3}, [%4];"
                 : "=r"(r[0]), "=r"(r[1]), "=r"(r[2]), "=r"(r[3]) : "r"(addr));
}
__device__ __forceinline__ void ldm_x4_t(uint32_t* r, uint32_t addr) {
    asm volatile("ldmatrix.sync.aligned.m8n8.x4.trans.shared.b16 {%0,%1,%2,%3}, [%4];"
                 : "=r"(r[0]), "=r"(r[1]), "=r"(r[2]), "=r"(r[3]) : "r"(addr));
}

__device__ __forceinline__ void mma_f16(float* d, const uint32_t* a, const uint32_t* b) {
    asm volatile(
        "mma.sync.aligned.m16n8k16.row.col.f32.f16.f16.f32 "
        "{%0,%1,%2,%3}, {%4,%5,%6,%7}, {%8,%9}, {%0,%1,%2,%3};"
        : "+f"(d[0]), "+f"(d[1]), "+f"(d[2]), "+f"(d[3])
        : "r"(a[0]), "r"(a[1]), "r"(a[2]), "r"(a[3]), "r"(b[0]), "r"(b[1]));
}

// fast exp2 / rcp via MUFU
__device__ __forceinline__ float ex2(float x) {
    float r; asm("ex2.approx.f32 %0, %1;" : "=f"(r) : "f"(x)); return r;
}
__device__ __forceinline__ float frcp(float x) {
    float r; asm("rcp.approx.f32 %0, %1;" : "=f"(r) : "f"(x)); return r;
}

// fp32 pair -> packed f16x2 (a in low half)
__device__ __forceinline__ uint32_t pack_f16(float a, float b) {
    uint32_t r; asm("cvt.rn.f16x2.f32 %0, %1, %2;" : "=r"(r) : "f"(b), "f"(a));
    return r;
}
// fp32 pair -> f16x2 hi + f16x2 lo
__device__ __forceinline__ void split2h(float a, float b, uint32_t& hi, uint32_t& lo) {
    hi = pack_f16(a, b);
    __half2 h = *(__half2*)&hi;
    const float la = a - __half2float(h.x);
    const float lb = b - __half2float(h.y);
    lo = pack_f16(la, lb);
}

// ---------------------------------------------------------------------------
// input split: fp32 -> fp16 single (z selects q/k/v)
// ---------------------------------------------------------------------------
__global__ void __launch_bounds__(256) split_in(
    const float4* __restrict__ q, const float4* __restrict__ k,
    const float4* __restrict__ v)
{
    const int z = blockIdx.z;
    const size_t XN4 = (size_t)ROWS * DM / 4;
    const float4* src = (z == 0) ? q : (z == 1) ? k : v;
    uint32_t* fp = (uint32_t*)(g_xf[z]);
    const size_t i = blockIdx.x * 256 + threadIdx.x;
    if (i >= XN4) return;
    float4 vv = src[i];
    fp[2*i]   = pack_f16(vv.x, vv.y);
    fp[2*i+1] = pack_f16(vv.z, vv.w);
}

// weight split: all four weights -> fp16 hi/lo
__global__ void __launch_bounds__(256) split_w(
    const float4* __restrict__ wq, const float4* __restrict__ wk,
    const float4* __restrict__ wv, const float4* __restrict__ wo)
{
    const int z = blockIdx.z;
    const size_t WN4 = (size_t)DM * DM / 4;
    const float4* src = (z == 0) ? wq : (z == 1) ? wk : (z == 2) ? wv : wo;
    uint32_t* hp = (uint32_t*)(g_wfh[z]);
    uint32_t* lp = (uint32_t*)(g_wfl[z]);
    const size_t i = blockIdx.x * 256 + threadIdx.x;
    if (i >= WN4) return;
    float4 vv = src[i];
    uint32_t h0, l0, h1, l1;
    split2h(vv.x, vv.y, h0, l0);
    split2h(vv.z, vv.w, h1, l1);
    hp[2*i] = h0; hp[2*i+1] = h1;
    lp[2*i] = l0; lp[2*i+1] = l1;
}

// ---------------------------------------------------------------------------
// fp16 2-term GEMM: C = A_f16 * (Wh + Wl)^T + bias.
// CTA 128x128, BK=64 (16 stages), 8 warps. Stage = A, Bh, Bl (3 arrays).
// MODE 0: fp32 C row-major; MODE 3: fp16 hi/lo scatter (V);
// MODE 4: fp16 single scatter (Q, K).
// ---------------------------------------------------------------------------
#define GSTRIDE 72                            // 64 + 8 pad (fp16 elems)
#define ARR_BYTES (128 * GSTRIDE * 2)         // 18432 B per 128x64 array
#define NSTAGE (DM / 64)                      // 16
#define G16_STAGE (3 * ARR_BYTES)             // 55296 B

template<int MODE>
__device__ __forceinline__ void gemm16_body(
    const __half* __restrict__ A, const __half* __restrict__ Bh,
    const __half* __restrict__ Bl, const float* __restrict__ bias,
    float* __restrict__ C, void* __restrict__ Ch, void* __restrict__ Cl,
    float oscale)
{
    extern __shared__ __align__(128) char smraw[];
    const uint32_t smem0 = smem_u32(smraw);

    const int tid = threadIdx.x;
    const int lane = tid & 31;
    const int wid = tid >> 5;
    const int wm = wid >> 2;
    const int wn = wid & 3;

    const int m0 = blockIdx.y << 7;
    const int n0 = blockIdx.x << 7;

    const __half* gsrc[3] = {
        A + (size_t)m0 * DM, Bh + (size_t)n0 * DM, Bl + (size_t)n0 * DM
    };

    auto load_stage = [&](int s) {
        const int kk = s * 64;
        const uint32_t sb = smem0 + (s & 1) * G16_STAGE;
        #pragma unroll
        for (int a = 0; a < 3; a++) {
            const __half* g = gsrc[a];
            const uint32_t ab = sb + a * ARR_BYTES;
            #pragma unroll
            for (int c = 0; c < 4; c++) {
                const int ch = tid + c * 256;          // 0..1023
                const int row = ch >> 3, c16 = ch & 7; // 128 rows x 8 chunks
                CP_ASYNC16(ab + row * (GSTRIDE*2) + c16 * 16,
                           g + (size_t)row * DM + kk + c16 * 8);
            }
        }
    };

    float acc[4][4][4];
    #pragma unroll
    for (int i = 0; i < 4; i++)
        #pragma unroll
        for (int j = 0; j < 4; j++)
            #pragma unroll
            for (int e = 0; e < 4; e++) acc[i][j][e] = 0.f;

    const int a_r = lane & 15, a_c = (lane >> 4) << 3;
    const int b_r = (lane & 7) + (((lane >> 3) & 2) << 2);
    const int b_c = ((lane >> 3) & 1) << 3;

    load_stage(0);
    CP_COMMIT();

    for (int s = 0; s < NSTAGE; s++) {
        CP_WAIT0();
        __syncthreads();
        if (s + 1 < NSTAGE) { load_stage(s + 1); CP_COMMIT(); }

        const uint32_t sb = smem0 + (s & 1) * G16_STAGE;
        const uint32_t sA  = sb;
        const uint32_t sBh = sb + ARR_BYTES;
        const uint32_t sBl = sb + 2 * ARR_BYTES;

        #pragma unroll
        for (int k16 = 0; k16 < 4; k16++) {
            const int kc = k16 * 16;
            uint32_t bh[2][4], bl[2][4];
            #pragma unroll
            for (int np = 0; np < 2; np++) {
                const uint32_t off =
                    ((wn * 32 + np * 16 + b_r) * GSTRIDE + kc + b_c) * 2;
                ldm_x4(bh[np], sBh + off);
                ldm_x4(bl[np], sBl + off);
            }
            #pragma unroll
            for (int mt = 0; mt < 4; mt++) {
                uint32_t af[4];
                const uint32_t off =
                    ((wm * 64 + mt * 16 + a_r) * GSTRIDE + kc + a_c) * 2;
                ldm_x4(af, sA + off);
                #pragma unroll
                for (int nt = 0; nt < 4; nt++)
                    mma_f16(acc[mt][nt], af, &bh[nt >> 1][(nt & 1) * 2]);
                #pragma unroll
                for (int nt = 0; nt < 4; nt++)
                    mma_f16(acc[mt][nt], af, &bl[nt >> 1][(nt & 1) * 2]);
            }
        }
    }

    #pragma unroll
    for (int mt = 0; mt < 4; mt++) {
        #pragma unroll
        for (int nt = 0; nt < 4; nt++) {
            const int col = n0 + wn * 32 + nt * 8 + ((lane & 3) << 1);
            const float b0 = bias[col], b1 = bias[col + 1];
            #pragma unroll
            for (int half = 0; half < 2; half++) {
                const int row = m0 + wm * 64 + mt * 16 + (lane >> 2) + half * 8;
                const float vx = (acc[mt][nt][half * 2 + 0] + b0) * oscale;
                const float vy = (acc[mt][nt][half * 2 + 1] + b1) * oscale;
                if (MODE == 0) {
                    float2 vo; vo.x = vx; vo.y = vy;
                    *(float2*)&C[(size_t)row * DM + col] = vo;
                } else {
                    const int h = col >> 6, d = col & 63;
                    const int nb = row >> 11, kq = row & 2047;
                    const size_t idx = (((size_t)(h * NB + nb)) * SEQ + kq) * HD + d;
                    if (MODE == 3) {
                        uint32_t hi, lo;
                        split2h(vx, vy, hi, lo);
                        *(uint32_t*)&((__half*)Ch)[idx] = hi;
                        *(uint32_t*)&((__half*)Cl)[idx] = lo;
                    } else {           // MODE 4: single fp16
                        *(uint32_t*)&((__half*)Ch)[idx] = pack_f16(vx, vy);
                    }
                }
            }
        }
    }
}

__global__ void __launch_bounds__(256, 2) gemm_qkv16(
    const float* __restrict__ bq, const float* __restrict__ bk,
    const float* __restrict__ bv)
{
    const int z = blockIdx.z;
    if (z == 0) {
        gemm16_body<4>(g_xf[0], g_wfh[0], g_wfl[0], bq, nullptr, g_qf, nullptr, QSCALE);
    } else if (z == 1) {
        gemm16_body<4>(g_xf[1], g_wfh[1], g_wfl[1], bk, nullptr, g_kf, nullptr, 1.f);
    } else {
        gemm16_body<3>(g_xf[2], g_wfh[2], g_wfl[2], bv, nullptr, g_vh, g_vl, 1.f);
    }
}

__global__ void __launch_bounds__(256, 2) gemm_out16(
    const float* __restrict__ bo, float* __restrict__ C)
{
    gemm16_body<0>(g_yf, g_wfh[3], g_wfl[3], bo, C, nullptr, nullptr, 1.f);
}

// ---------------------------------------------------------------------------
// FA2-style HMMA attention, 2 CTAs/SM, all-fp16 MMA.
// S:  1-term fp16 (Qf*Kf) — K-lo dropped; symmetric to round-11 Q-lo drop,
//     measured contribution ~2e-4 each; predicted total rel_err ~5.2e-4.
// PV: 2-term fp16 (P*Vh + P*Vl) — V-lo stays (propagates unattenuated).
// smem: [Qf 18432][stage0 27648][stage1 27648] = 73728 B.
// ---------------------------------------------------------------------------
#define ASTRIDE 72
#define AARR    (64 * ASTRIDE * 2)          // 9216 B
#define ASTAGE  (3 * AARR)                  // 27648 B (Kf, Vh, Vl)
#define QONE    (128 * ASTRIDE * 2)         // 18432 B

__global__ void __launch_bounds__(256, 2) attn_mma(
    const __half* __restrict__ Qf_, const __half* __restrict__ Kf_,
    const __half* __restrict__ Vh_, const __half* __restrict__ Vl_,
    __half* __restrict__ Yf)
{
    extern __shared__ __align__(128) char smraw[];
    const uint32_t s0 = smem_u32(smraw);
    const uint32_t stg = s0 + QONE;

    const int tid = threadIdx.x;
    const int lane = tid & 31;
    const int wid = tid >> 5;
    const int hn = blockIdx.y;
    const int h = hn >> 1, n = hn & 1;
    const int q0 = blockIdx.x << 7;
    const size_t hoff = (size_t)hn * SEQ * HD;

    const int a_r = lane & 15, a_c = (lane >> 4) << 3;
    const int b_r = (lane & 7) + (((lane >> 3) & 2) << 2);
    const int b_c = ((lane >> 3) & 1) << 3;

    {
        const __half* Qg = Qf_ + hoff + (size_t)q0 * HD;
        #pragma unroll
        for (int c = 0; c < 4; c++) {
            const int ch = tid + c * 256;
            const int row = ch >> 3, c16 = ch & 7;
            CP_ASYNC16(s0 + row * 144 + c16 * 16, Qg + row * 64 + c16 * 8);
        }
        CP_COMMIT();
    }

    const char* gs0 = (const char*)(Kf_ + hoff);
    const char* gs1 = (const char*)(Vh_ + hoff);
    const char* gs2 = (const char*)(Vl_ + hoff);

    auto load_stage = [&](int s) {
        const int kv0 = s << 6;
        const uint32_t sb = stg + (s & 1) * ASTAGE;
        const char* gs[3] = { gs0, gs1, gs2 };
        #pragma unroll
        for (int a = 0; a < 3; a++) {
            #pragma unroll
            for (int c = 0; c < 2; c++) {
                const int ch = tid + c * 256;        // 0..511
                const int row = ch >> 3, c16 = ch & 7;
                CP_ASYNC16(sb + a * AARR + row * 144 + c16 * 16,
                           gs[a] + (size_t)(kv0 + row) * 128 + c16 * 16);
            }
        }
    };

    load_stage(0); CP_COMMIT();

    CP_WAIT0();
    __syncthreads();
    uint32_t qf[4][4];
    const uint32_t qbase = ((wid * 16 + a_r) * ASTRIDE + a_c) * 2;
    #pragma unroll
    for (int t4 = 0; t4 < 4; t4++)
        ldm_x4(qf[t4], s0 + qbase + t4 * 32);

    float m0r = -1e30f, m1r = -1e30f, l0 = 0.f, l1 = 0.f;
    float O[8][4];
    #pragma unroll
    for (int j = 0; j < 8; j++)
        #pragma unroll
        for (int e = 0; e < 4; e++) O[j][e] = 0.f;

    for (int t = 0; t < SEQ / 64; t++) {
        if (t > 0) { CP_WAIT0(); __syncthreads(); }
        if (t + 1 < SEQ / 64) { load_stage(t + 1); CP_COMMIT(); }

        const uint32_t sb = stg + (t & 1) * ASTAGE;

        // ---- S = Q K^T (fp16 1-term) ----
        float S[8][4];
        #pragma unroll
        for (int j = 0; j < 8; j++)
            #pragma unroll
            for (int e = 0; e < 4; e++) S[j][e] = 0.f;

        #pragma unroll
        for (int t4 = 0; t4 < 4; t4++) {
            #pragma unroll
            for (int jp = 0; jp < 4; jp++) {
                uint32_t kf[4];
                const uint32_t off = ((16 * jp + b_r) * ASTRIDE + 16 * t4 + b_c) * 2;
                ldm_x4(kf, sb + off);
                mma_f16(S[2*jp],   qf[t4], &kf[0]);
                mma_f16(S[2*jp+1], qf[t4], &kf[2]);
            }
        }

        // ---- online softmax (scale pre-folded; bare exp2) ----
        float corr0, corr1;
        {
            float tm = S[0][0];
            #pragma unroll
            for (int j = 0; j < 8; j++) tm = fmaxf(tm, fmaxf(S[j][0], S[j][1]));
            tm = fmaxf(tm, __shfl_xor_sync(0xffffffffu, tm, 1));
            tm = fmaxf(tm, __shfl_xor_sync(0xffffffffu, tm, 2));
            const float mnew = fmaxf(m0r, tm);
            corr0 = ex2(m0r - mnew);
            float rs = 0.f;
            #pragma unroll
            for (int j = 0; j < 8; j++) {
                S[j][0] = ex2(S[j][0] - mnew);
                S[j][1] = ex2(S[j][1] - mnew);
                rs += S[j][0] + S[j][1];
            }
            rs += __shfl_xor_sync(0xffffffffu, rs, 1);
            rs += __shfl_xor_sync(0xffffffffu, rs, 2);
            l0 = l0 * corr0 + rs;
            m0r = mnew;
        }
        {
            float tm = S[0][2];
            #pragma unroll
            for (int j = 0; j < 8; j++) tm = fmaxf(tm, fmaxf(S[j][2], S[j][3]));
            tm = fmaxf(tm, __shfl_xor_sync(0xffffffffu, tm, 1));
            tm = fmaxf(tm, __shfl_xor_sync(0xffffffffu, tm, 2));
            const float mnew = fmaxf(m1r, tm);
            corr1 = ex2(m1r - mnew);
            float rs = 0.f;
            #pragma unroll
            for (int j = 0; j < 8; j++) {
                S[j][2] = ex2(S[j][2] - mnew);
                S[j][3] = ex2(S[j][3] - mnew);
                rs += S[j][2] + S[j][3];
            }
            rs += __shfl_xor_sync(0xffffffffu, rs, 1);
            rs += __shfl_xor_sync(0xffffffffu, rs, 2);
            l1 = l1 * corr1 + rs;
            m1r = mnew;
        }

        // ---- pack P to fp16 A-fragments ----
        uint32_t pa[4][4];
        #pragma unroll
        for (int t4 = 0; t4 < 4; t4++) {
            pa[t4][0] = pack_f16(S[2*t4][0],   S[2*t4][1]);
            pa[t4][1] = pack_f16(S[2*t4][2],   S[2*t4][3]);
            pa[t4][2] = pack_f16(S[2*t4+1][0], S[2*t4+1][1]);
            pa[t4][3] = pack_f16(S[2*t4+1][2], S[2*t4+1][3]);
        }

        // ---- rescale O ----
        #pragma unroll
        for (int j = 0; j < 8; j++) {
            O[j][0] *= corr0; O[j][1] *= corr0;
            O[j][2] *= corr1; O[j][3] *= corr1;
        }

        // ---- O += P V (fp16 2-term: P*Vh + P*Vl) ----
        #pragma unroll
        for (int t4 = 0; t4 < 4; t4++) {
            #pragma unroll
            for (int jp = 0; jp < 4; jp++) {
                uint32_t vh[4], vl[4];
                const uint32_t off =
                    ((16 * t4 + (lane & 15)) * ASTRIDE + 16 * jp + a_c) * 2;
                ldm_x4_t(vh, sb + AARR + off);
                ldm_x4_t(vl, sb + 2 * AARR + off);
                mma_f16(O[2*jp],   pa[t4], &vh[0]);
                mma_f16(O[2*jp+1], pa[t4], &vh[2]);
                mma_f16(O[2*jp],   pa[t4], &vl[0]);
                mma_f16(O[2*jp+1], pa[t4], &vl[2]);
            }
        }
    }

    // ---- epilogue: scale by 1/l, write single fp16 in [N, K, H*D] layout ----
    const float inv0 = frcp(l0), inv1 = frcp(l1);
    #pragma unroll
    for (int j = 0; j < 8; j++) {
        const int col = h * 64 + 8 * j + ((lane & 3) << 1);
        #pragma unroll
        for (int half = 0; half < 2; half++) {
            const int row = q0 + wid * 16 + (lane >> 2) + half * 8;
            const float inv = half ? inv1 : inv0;
            const float y0 = O[j][half * 2 + 0] * inv;
            const float y1 = O[j][half * 2 + 1] * inv;
            const size_t idx = ((size_t)(n * SEQ) + row) * DM + col;
            *(uint32_t*)&Yf[idx] = pack_f16(y0, y1);
        }
    }
}

// ---------------------------------------------------------------------------
extern "C" void kernel_launch(void* const* d_in, const int* in_sizes, int n_in,
                              void* d_out, int out_size)
{
    const float* q  = (const float*)d_in[0];
    const float* k  = (const float*)d_in[1];
    const float* v  = (const float*)d_in[2];
    const float* Wq = (const float*)d_in[3];
    const float* bq = (const float*)d_in[4];
    const float* Wk = (const float*)d_in[5];
    const float* bk = (const float*)d_in[6];
    const float* Wv = (const float*)d_in[7];
    const float* bv = (const float*)d_in[8];
    const float* Wo = (const float*)d_in[9];
    const float* bo = (const float*)d_in[10];
    float* out = (float*)d_out;

    __half *qf, *kf, *vh, *vl, *yf;
    cudaGetSymbolAddress((void**)&qf, g_qf);
    cudaGetSymbolAddress((void**)&kf, g_kf);
    cudaGetSymbolAddress((void**)&vh, g_vh);
    cudaGetSymbolAddress((void**)&vl, g_vl);
    cudaGetSymbolAddress((void**)&yf, g_yf);

    const size_t XN = (size_t)ROWS * DM;
    const size_t WN = (size_t)DM * DM;

    { const dim3 gi((unsigned)(XN/4/256), 1, 3);
      split_in<<<gi, 256>>>((const float4*)q, (const float4*)k, (const float4*)v); }
    { const dim3 gw((unsigned)(WN/4/256), 1, 4);
      split_w<<<gw, 256>>>((const float4*)Wq, (const float4*)Wk,
                           (const float4*)Wv, (const float4*)Wo); }

    const int g16smem = 2 * G16_STAGE;   // 110592
    cudaFuncSetAttribute((const void*)gemm_qkv16,
                         cudaFuncAttributeMaxDynamicSharedMemorySize, g16smem);
    cudaFuncSetAttribute((const void*)gemm_out16,
                         cudaFuncAttributeMaxDynamicSharedMemorySize, g16smem);
    const dim3 gq(DM/128, ROWS/128, 3);
    gemm_qkv16<<<gq, 256, g16smem>>>(bq, bk, bv);

    const int asmem = QONE + 2 * ASTAGE;   // 73728
    cudaFuncSetAttribute((const void*)attn_mma,
                         cudaFuncAttributeMaxDynamicSharedMemorySize, asmem);
    const dim3 ga(SEQ/128, NH*NB);  // (16, 32)
    attn_mma<<<ga, 256, asmem>>>(qf, kf, vh, vl, yf);

    const dim3 gg(DM/128, ROWS/128);
    gemm_out16<<<gg, 256, g16smem>>>(bo, out);
}

// round 15
// speedup vs baseline: 5.9198x; 1.0836x over previous
#include <cuda_runtime.h>
#include <cuda_bf16.h>
#include <cuda_fp16.h>
#include <cstdint>

#define NB   2
#define SEQ  2048
#define DM   1024
#define NH   16
#define HD   64
#define ROWS (NB*SEQ)          // 4096
// softmax scale 1/sqrt(64) folded into Q projection together with log2(e):
#define QSCALE 0.18033688011112042f   // 0.125 * log2(e)

// ---------------------------------------------------------------------------
// Scratch (allocation-free: __device__ globals)
// ---------------------------------------------------------------------------
#define PROJN ((size_t)NH*NB*SEQ*HD)     // 4M elems
__device__ __align__(256) __half g_qf[PROJN];                       // fp16 Q
__device__ __align__(256) __half g_kf[PROJN];                       // fp16 K
__device__ __align__(256) __half g_vf[PROJN];                       // fp16 V
__device__ __align__(256) __half g_xf[3][(size_t)ROWS*DM];          // fp16 inputs
__device__ __align__(256) __half g_wfh[4][(size_t)DM*DM];           // fp16 W hi
__device__ __align__(256) __half g_wfl[4][(size_t)DM*DM];           // fp16 W lo
__device__ __align__(256) __half g_yf[(size_t)ROWS*DM];             // fp16 Y

// ---------------------------------------------------------------------------
// PTX helpers (baseline sm_80+ features: mma.sync / ldmatrix / cp.async)
// ---------------------------------------------------------------------------
__device__ __forceinline__ uint32_t smem_u32(const void* p) {
    uint32_t a;
    asm("{ .reg .u64 t; cvta.to.shared.u64 t, %1; cvt.u32.u64 %0, t; }"
        : "=r"(a) : "l"(p));
    return a;
}

#define CP_ASYNC16(dst, src) \
    asm volatile("cp.async.cg.shared.global [%0], [%1], 16;" :: "r"(dst), "l"(src))
#define CP_COMMIT() asm volatile("cp.async.commit_group;" ::: "memory")
#define CP_WAIT0()  asm volatile("cp.async.wait_group 0;" ::: "memory")
#define CP_WAIT1()  asm volatile("cp.async.wait_group 1;" ::: "memory")
#define CP_WAIT2()  asm volatile("cp.async.wait_group 2;" ::: "memory")

__device__ __forceinline__ void ldm_x4(uint32_t* r, uint32_t addr) {
    asm volatile("ldmatrix.sync.aligned.m8n8.x4.shared.b16 {%0,%1,%2,%3}, [%4];"
                 : "=r"(r[0]), "=r"(r[1]), "=r"(r[2]), "=r"(r[3]) : "r"(addr));
}
__device__ __forceinline__ void ldm_x4_t(uint32_t* r, uint32_t addr) {
    asm volatile("ldmatrix.sync.aligned.m8n8.x4.trans.shared.b16 {%0,%1,%2,%3}, [%4];"
                 : "=r"(r[0]), "=r"(r[1]), "=r"(r[2]), "=r"(r[3]) : "r"(addr));
}

__device__ __forceinline__ void mma_f16(float* d, const uint32_t* a, const uint32_t* b) {
    asm volatile(
        "mma.sync.aligned.m16n8k16.row.col.f32.f16.f16.f32 "
        "{%0,%1,%2,%3}, {%4,%5,%6,%7}, {%8,%9}, {%0,%1,%2,%3};"
        : "+f"(d[0]), "+f"(d[1]), "+f"(d[2]), "+f"(d[3])
        : "r"(a[0]), "r"(a[1]), "r"(a[2]), "r"(a[3]), "r"(b[0]), "r"(b[1]));
}

__device__ __forceinline__ float ex2(float x) {
    float r; asm("ex2.approx.f32 %0, %1;" : "=f"(r) : "f"(x)); return r;
}
__device__ __forceinline__ float frcp(float x) {
    float r; asm("rcp.approx.f32 %0, %1;" : "=f"(r) : "f"(x)); return r;
}

__device__ __forceinline__ uint32_t pack_f16(float a, float b) {
    uint32_t r; asm("cvt.rn.f16x2.f32 %0, %1, %2;" : "=r"(r) : "f"(b), "f"(a));
    return r;
}
__device__ __forceinline__ void split2h(float a, float b, uint32_t& hi, uint32_t& lo) {
    hi = pack_f16(a, b);
    __half2 h = *(__half2*)&hi;
    const float la = a - __half2float(h.x);
    const float lb = b - __half2float(h.y);
    lo = pack_f16(la, lb);
}

// ---------------------------------------------------------------------------
// input split: fp32 -> fp16 single (z selects q/k/v)
// ---------------------------------------------------------------------------
__global__ void __launch_bounds__(256) split_in(
    const float4* __restrict__ q, const float4* __restrict__ k,
    const float4* __restrict__ v)
{
    const int z = blockIdx.z;
    const size_t XN4 = (size_t)ROWS * DM / 4;
    const float4* src = (z == 0) ? q : (z == 1) ? k : v;
    uint32_t* fp = (uint32_t*)(g_xf[z]);
    const size_t i = blockIdx.x * 256 + threadIdx.x;
    if (i >= XN4) return;
    float4 vv = src[i];
    fp[2*i]   = pack_f16(vv.x, vv.y);
    fp[2*i+1] = pack_f16(vv.z, vv.w);
}

// weight split: all four weights -> fp16 hi/lo
__global__ void __launch_bounds__(256) split_w(
    const float4* __restrict__ wq, const float4* __restrict__ wk,
    const float4* __restrict__ wv, const float4* __restrict__ wo)
{
    const int z = blockIdx.z;
    const size_t WN4 = (size_t)DM * DM / 4;
    const float4* src = (z == 0) ? wq : (z == 1) ? wk : (z == 2) ? wv : wo;
    uint32_t* hp = (uint32_t*)(g_wfh[z]);
    uint32_t* lp = (uint32_t*)(g_wfl[z]);
    const size_t i = blockIdx.x * 256 + threadIdx.x;
    if (i >= WN4) return;
    float4 vv = src[i];
    uint32_t h0, l0, h1, l1;
    split2h(vv.x, vv.y, h0, l0);
    split2h(vv.z, vv.w, h1, l1);
    hp[2*i] = h0; hp[2*i+1] = h1;
    lp[2*i] = l0; lp[2*i+1] = l1;
}

// ---------------------------------------------------------------------------
// fp16 2-term GEMM: C = A_f16 * (Wh + Wl)^T + bias.
// CTA 128x128, BK=64 (16 stages), 8 warps, double-buffered, 2 CTAs/SM.
// MODE 0: fp32 C row-major; MODE 4: fp16 single QKV scatter.
// ---------------------------------------------------------------------------
#define GSTRIDE 72                            // 64 + 8 pad (fp16 elems)
#define ARR_BYTES (128 * GSTRIDE * 2)         // 18432 B per 128x64 array
#define NSTAGE (DM / 64)                      // 16
#define G16_STAGE (3 * ARR_BYTES)             // 55296 B

template<int MODE>
__device__ __forceinline__ void gemm16_body(
    const __half* __restrict__ A, const __half* __restrict__ Bh,
    const __half* __restrict__ Bl, const float* __restrict__ bias,
    float* __restrict__ C, void* __restrict__ Ch, float oscale)
{
    extern __shared__ __align__(128) char smraw[];
    const uint32_t smem0 = smem_u32(smraw);

    const int tid = threadIdx.x;
    const int lane = tid & 31;
    const int wid = tid >> 5;
    const int wm = wid >> 2;
    const int wn = wid & 3;

    const int m0 = blockIdx.y << 7;
    const int n0 = blockIdx.x << 7;

    const __half* gsrc[3] = {
        A + (size_t)m0 * DM, Bh + (size_t)n0 * DM, Bl + (size_t)n0 * DM
    };

    auto load_stage = [&](int s) {
        const int kk = s * 64;
        const uint32_t sb = smem0 + (s & 1) * G16_STAGE;
        #pragma unroll
        for (int a = 0; a < 3; a++) {
            const __half* g = gsrc[a];
            const uint32_t ab = sb + a * ARR_BYTES;
            #pragma unroll
            for (int c = 0; c < 4; c++) {
                const int ch = tid + c * 256;
                const int row = ch >> 3, c16 = ch & 7;
                CP_ASYNC16(ab + row * (GSTRIDE*2) + c16 * 16,
                           g + (size_t)row * DM + kk + c16 * 8);
            }
        }
    };

    float acc[4][4][4];
    #pragma unroll
    for (int i = 0; i < 4; i++)
        #pragma unroll
        for (int j = 0; j < 4; j++)
            #pragma unroll
            for (int e = 0; e < 4; e++) acc[i][j][e] = 0.f;

    const int a_r = lane & 15, a_c = (lane >> 4) << 3;
    const int b_r = (lane & 7) + (((lane >> 3) & 2) << 2);
    const int b_c = ((lane >> 3) & 1) << 3;

    load_stage(0);
    CP_COMMIT();

    for (int s = 0; s < NSTAGE; s++) {
        CP_WAIT0();
        __syncthreads();
        if (s + 1 < NSTAGE) { load_stage(s + 1); CP_COMMIT(); }

        const uint32_t sb = smem0 + (s & 1) * G16_STAGE;
        const uint32_t sA  = sb;
        const uint32_t sBh = sb + ARR_BYTES;
        const uint32_t sBl = sb + 2 * ARR_BYTES;

        #pragma unroll
        for (int k16 = 0; k16 < 4; k16++) {
            const int kc = k16 * 16;
            uint32_t bh[2][4], bl[2][4];
            #pragma unroll
            for (int np = 0; np < 2; np++) {
                const uint32_t off =
                    ((wn * 32 + np * 16 + b_r) * GSTRIDE + kc + b_c) * 2;
                ldm_x4(bh[np], sBh + off);
                ldm_x4(bl[np], sBl + off);
            }
            #pragma unroll
            for (int mt = 0; mt < 4; mt++) {
                uint32_t af[4];
                const uint32_t off =
                    ((wm * 64 + mt * 16 + a_r) * GSTRIDE + kc + a_c) * 2;
                ldm_x4(af, sA + off);
                #pragma unroll
                for (int nt = 0; nt < 4; nt++)
                    mma_f16(acc[mt][nt], af, &bh[nt >> 1][(nt & 1) * 2]);
                #pragma unroll
                for (int nt = 0; nt < 4; nt++)
                    mma_f16(acc[mt][nt], af, &bl[nt >> 1][(nt & 1) * 2]);
            }
        }
    }

    #pragma unroll
    for (int mt = 0; mt < 4; mt++) {
        #pragma unroll
        for (int nt = 0; nt < 4; nt++) {
            const int col = n0 + wn * 32 + nt * 8 + ((lane & 3) << 1);
            const float b0 = bias[col], b1 = bias[col + 1];
            #pragma unroll
            for (int half = 0; half < 2; half++) {
                const int row = m0 + wm * 64 + mt * 16 + (lane >> 2) + half * 8;
                const float vx = (acc[mt][nt][half * 2 + 0] + b0) * oscale;
                const float vy = (acc[mt][nt][half * 2 + 1] + b1) * oscale;
                if (MODE == 0) {
                    float2 vo; vo.x = vx; vo.y = vy;
                    *(float2*)&C[(size_t)row * DM + col] = vo;
                } else {
                    const int h = col >> 6, d = col & 63;
                    const int nb = row >> 11, kq = row & 2047;
                    const size_t idx = (((size_t)(h * NB + nb)) * SEQ + kq) * HD + d;
                    *(uint32_t*)&((__half*)Ch)[idx] = pack_f16(vx, vy);
                }
            }
        }
    }
}

__global__ void __launch_bounds__(256, 2) gemm_qkv16(
    const float* __restrict__ bq, const float* __restrict__ bk,
    const float* __restrict__ bv)
{
    const int z = blockIdx.z;
    if (z == 0) {
        gemm16_body<4>(g_xf[0], g_wfh[0], g_wfl[0], bq, nullptr, g_qf, QSCALE);
    } else if (z == 1) {
        gemm16_body<4>(g_xf[1], g_wfh[1], g_wfl[1], bk, nullptr, g_kf, 1.f);
    } else {
        gemm16_body<4>(g_xf[2], g_wfh[2], g_wfl[2], bv, nullptr, g_vf, 1.f);
    }
}

__global__ void __launch_bounds__(256, 2) gemm_out16(
    const float* __restrict__ bo, float* __restrict__ C)
{
    gemm16_body<0>(g_yf, g_wfh[3], g_wfl[3], bo, C, nullptr, 1.f);
}

// ---------------------------------------------------------------------------
// FA2-style HMMA attention, 2 CTAs/SM, all-fp16, software-pipelined.
// S: 1-term (Qf*Kf).  PV: 1-term (P*Vf) — V-lo dropped, anchored ~1.76e-4.
// Tile order: S(t) -> PV(t-1) -> softmax(t) -> pack(t).  4 KV buffers,
// prefetch depth 2, ONE wait_group(1)+sync per tile; clamped dummy loads
// keep the pending-group count uniform.
// smem: [Qf 18432][4 x (K 9216 | V 9216)] = 92160 B.
// ---------------------------------------------------------------------------
#define ASTRIDE 72
#define AARR    (64 * ASTRIDE * 2)          // 9216 B
#define ASTAGE  (2 * AARR)                  // 18432 B (K + V)
#define QONE    (128 * ASTRIDE * 2)         // 18432 B

__global__ void __launch_bounds__(256, 2) attn_mma(
    const __half* __restrict__ Qf_, const __half* __restrict__ Kf_,
    const __half* __restrict__ Vf_, __half* __restrict__ Yf)
{
    extern __shared__ __align__(128) char smraw[];
    const uint32_t s0 = smem_u32(smraw);
    const uint32_t stg = s0 + QONE;

    const int tid = threadIdx.x;
    const int lane = tid & 31;
    const int wid = tid >> 5;
    const int hn = blockIdx.y;
    const int h = hn >> 1, n = hn & 1;
    const int q0 = blockIdx.x << 7;
    const size_t hoff = (size_t)hn * SEQ * HD;

    const int a_r = lane & 15, a_c = (lane >> 4) << 3;
    const int b_r = (lane & 7) + (((lane >> 3) & 2) << 2);
    const int b_c = ((lane >> 3) & 1) << 3;

    // ---- prologue: Q (group), stage0 (group), stage1 (group) ----
    {
        const __half* Qg = Qf_ + hoff + (size_t)q0 * HD;
        #pragma unroll
        for (int c = 0; c < 4; c++) {
            const int ch = tid + c * 256;
            const int row = ch >> 3, c16 = ch & 7;
            CP_ASYNC16(s0 + row * 144 + c16 * 16, Qg + row * 64 + c16 * 8);
        }
        CP_COMMIT();
    }

    const char* gsK = (const char*)(Kf_ + hoff);
    const char* gsV = (const char*)(Vf_ + hoff);

    auto load_stage = [&](int buf, int src) {
        const int kv0 = src << 6;
        const uint32_t sb = stg + buf * ASTAGE;
        const char* gs[2] = { gsK, gsV };
        #pragma unroll
        for (int a = 0; a < 2; a++) {
            #pragma unroll
            for (int c = 0; c < 2; c++) {
                const int ch = tid + c * 256;        // 0..511
                const int row = ch >> 3, c16 = ch & 7;
                CP_ASYNC16(sb + a * AARR + row * 144 + c16 * 16,
                           gs[a] + (size_t)(kv0 + row) * 128 + c16 * 16);
            }
        }
    };

    load_stage(0, 0); CP_COMMIT();
    load_stage(1, 1); CP_COMMIT();

    CP_WAIT2();            // Q landed (stages 0,1 may be pending)
    __syncthreads();
    uint32_t qf[4][4];
    const uint32_t qbase = ((wid * 16 + a_r) * ASTRIDE + a_c) * 2;
    #pragma unroll
    for (int t4 = 0; t4 < 4; t4++)
        ldm_x4(qf[t4], s0 + qbase + t4 * 32);

    float m0r = -1e30f, m1r = -1e30f, l0 = 0.f, l1 = 0.f;
    float O[8][4];
    #pragma unroll
    for (int j = 0; j < 8; j++)
        #pragma unroll
        for (int e = 0; e < 4; e++) O[j][e] = 0.f;
    uint32_t pa[4][4];     // P fragments of the PREVIOUS tile

    for (int t = 0; t < SEQ / 64; t++) {
        CP_WAIT1();                        // stage t complete
        __syncthreads();                   // buffer (t+2)&3 free to overwrite
        {   // prefetch stage t+2 (clamped dummy near the end)
            const int src = (t + 2 < SEQ / 64) ? t + 2 : SEQ / 64 - 1;
            load_stage((t + 2) & 3, src);
            CP_COMMIT();
        }

        const uint32_t sb = stg + (t & 3) * ASTAGE;

        // ---- S = Q K^T (fp16 1-term) ----
        float S[8][4];
        #pragma unroll
        for (int j = 0; j < 8; j++)
            #pragma unroll
            for (int e = 0; e < 4; e++) S[j][e] = 0.f;

        #pragma unroll
        for (int t4 = 0; t4 < 4; t4++) {
            #pragma unroll
            for (int jp = 0; jp < 4; jp++) {
                uint32_t kf[4];
                const uint32_t off = ((16 * jp + b_r) * ASTRIDE + 16 * t4 + b_c) * 2;
                ldm_x4(kf, sb + off);
                mma_f16(S[2*jp],   qf[t4], &kf[0]);
                mma_f16(S[2*jp+1], qf[t4], &kf[2]);
            }
        }

        // ---- PV of PREVIOUS tile (V had >=2 tiles to land) ----
        if (t > 0) {
            const uint32_t sbv = stg + ((t - 1) & 3) * ASTAGE + AARR;
            #pragma unroll
            for (int t4 = 0; t4 < 4; t4++) {
                #pragma unroll
                for (int jp = 0; jp < 4; jp++) {
                    uint32_t vf[4];
                    const uint32_t off =
                        ((16 * t4 + (lane & 15)) * ASTRIDE + 16 * jp + a_c) * 2;
                    ldm_x4_t(vf, sbv + off);
                    mma_f16(O[2*jp],   pa[t4], &vf[0]);
                    mma_f16(O[2*jp+1], pa[t4], &vf[2]);
                }
            }
        }

        // ---- online softmax(t) ----
        float corr0, corr1;
        {
            float tm = S[0][0];
            #pragma unroll
            for (int j = 0; j < 8; j++) tm = fmaxf(tm, fmaxf(S[j][0], S[j][1]));
            tm = fmaxf(tm, __shfl_xor_sync(0xffffffffu, tm, 1));
            tm = fmaxf(tm, __shfl_xor_sync(0xffffffffu, tm, 2));
            const float mnew = fmaxf(m0r, tm);
            corr0 = ex2(m0r - mnew);
            float rs = 0.f;
            #pragma unroll
            for (int j = 0; j < 8; j++) {
                S[j][0] = ex2(S[j][0] - mnew);
                S[j][1] = ex2(S[j][1] - mnew);
                rs += S[j][0] + S[j][1];
            }
            rs += __shfl_xor_sync(0xffffffffu, rs, 1);
            rs += __shfl_xor_sync(0xffffffffu, rs, 2);
            l0 = l0 * corr0 + rs;
            m0r = mnew;
        }
        {
            float tm = S[0][2];
            #pragma unroll
            for (int j = 0; j < 8; j++) tm = fmaxf(tm, fmaxf(S[j][2], S[j][3]));
            tm = fmaxf(tm, __shfl_xor_sync(0xffffffffu, tm, 1));
            tm = fmaxf(tm, __shfl_xor_sync(0xffffffffu, tm, 2));
            const float mnew = fmaxf(m1r, tm);
            corr1 = ex2(m1r - mnew);
            float rs = 0.f;
            #pragma unroll
            for (int j = 0; j < 8; j++) {
                S[j][2] = ex2(S[j][2] - mnew);
                S[j][3] = ex2(S[j][3] - mnew);
                rs += S[j][2] + S[j][3];
            }
            rs += __shfl_xor_sync(0xffffffffu, rs, 1);
            rs += __shfl_xor_sync(0xffffffffu, rs, 2);
            l1 = l1 * corr1 + rs;
            m1r = mnew;
        }

        // ---- rescale O, pack P(t) for next tile's PV ----
        #pragma unroll
        for (int j = 0; j < 8; j++) {
            O[j][0] *= corr0; O[j][1] *= corr0;
            O[j][2] *= corr1; O[j][3] *= corr1;
        }
        #pragma unroll
        for (int t4 = 0; t4 < 4; t4++) {
            pa[t4][0] = pack_f16(S[2*t4][0],   S[2*t4][1]);
            pa[t4][1] = pack_f16(S[2*t4][2],   S[2*t4][3]);
            pa[t4][2] = pack_f16(S[2*t4+1][0], S[2*t4+1][1]);
            pa[t4][3] = pack_f16(S[2*t4+1][2], S[2*t4+1][3]);
        }
    }

    // ---- drain: PV of the final tile ----
    {
        const uint32_t sbv = stg + ((SEQ / 64 - 1) & 3) * ASTAGE + AARR;
        #pragma unroll
        for (int t4 = 0; t4 < 4; t4++) {
            #pragma unroll
            for (int jp = 0; jp < 4; jp++) {
                uint32_t vf[4];
                const uint32_t off =
                    ((16 * t4 + (lane & 15)) * ASTRIDE + 16 * jp + a_c) * 2;
                ldm_x4_t(vf, sbv + off);
                mma_f16(O[2*jp],   pa[t4], &vf[0]);
                mma_f16(O[2*jp+1], pa[t4], &vf[2]);
            }
        }
    }

    // ---- epilogue: scale by 1/l, write single fp16 in [N, K, H*D] layout ----
    const float inv0 = frcp(l0), inv1 = frcp(l1);
    #pragma unroll
    for (int j = 0; j < 8; j++) {
        const int col = h * 64 + 8 * j + ((lane & 3) << 1);
        #pragma unroll
        for (int half = 0; half < 2; half++) {
            const int row = q0 + wid * 16 + (lane >> 2) + half * 8;
            const float inv = half ? inv1 : inv0;
            const float y0 = O[j][half * 2 + 0] * inv;
            const float y1 = O[j][half * 2 + 1] * inv;
            const size_t idx = ((size_t)(n * SEQ) + row) * DM + col;
            *(uint32_t*)&Yf[idx] = pack_f16(y0, y1);
        }
    }
}

// ---------------------------------------------------------------------------
extern "C" void kernel_launch(void* const* d_in, const int* in_sizes, int n_in,
                              void* d_out, int out_size)
{
    const float* q  = (const float*)d_in[0];
    const float* k  = (const float*)d_in[1];
    const float* v  = (const float*)d_in[2];
    const float* Wq = (const float*)d_in[3];
    const float* bq = (const float*)d_in[4];
    const float* Wk = (const float*)d_in[5];
    const float* bk = (const float*)d_in[6];
    const float* Wv = (const float*)d_in[7];
    const float* bv = (const float*)d_in[8];
    const float* Wo = (const float*)d_in[9];
    const float* bo = (const float*)d_in[10];
    float* out = (float*)d_out;

    __half *qf, *kf, *vf, *yf;
    cudaGetSymbolAddress((void**)&qf, g_qf);
    cudaGetSymbolAddress((void**)&kf, g_kf);
    cudaGetSymbolAddress((void**)&vf, g_vf);
    cudaGetSymbolAddress((void**)&yf, g_yf);

    const size_t XN = (size_t)ROWS * DM;
    const size_t WN = (size_t)DM * DM;

    { const dim3 gi((unsigned)(XN/4/256), 1, 3);
      split_in<<<gi, 256>>>((const float4*)q, (const float4*)k, (const float4*)v); }
    { const dim3 gw((unsigned)(WN/4/256), 1, 4);
      split_w<<<gw, 256>>>((const float4*)Wq, (const float4*)Wk,
                           (const float4*)Wv, (const float4*)Wo); }

    const int g16smem = 2 * G16_STAGE;   // 110592
    cudaFuncSetAttribute((const void*)gemm_qkv16,
                         cudaFuncAttributeMaxDynamicSharedMemorySize, g16smem);
    cudaFuncSetAttribute((const void*)gemm_out16,
                         cudaFuncAttributeMaxDynamicSharedMemorySize, g16smem);
    const dim3 gq(DM/128, ROWS/128, 3);
    gemm_qkv16<<<gq, 256, g16smem>>>(bq, bk, bv);

    const int asmem = QONE + 4 * ASTAGE;   // 92160
    cudaFuncSetAttribute((const void*)attn_mma,
                         cudaFuncAttributeMaxDynamicSharedMemorySize, asmem);
    const dim3 ga(SEQ/128, NH*NB);  // (16, 32)
    attn_mma<<<ga, 256, asmem>>>(qf, kf, vf, yf);

    const dim3 gg(DM/128, ROWS/128);
    gemm_out16<<<gg, 256, g16smem>>>(bo, out);
}